// round 2
// baseline (speedup 1.0000x reference)
#include <cuda_runtime.h>
#include <math.h>
#include <stdint.h>

#define N0  65536     // total nodes
#define E0  524288    // total edges
#define NB  32        // graphs
#define FHC 256       // feature width (H*C)

// ---------------- static device scratch (no allocations allowed) ----------------
__device__ float g_h0[(size_t)N0 * FHC];   // lin0 output          64MB
__device__ float g_h1[(size_t)N0 * FHC];   // GAT hidden (h @ W)   64MB
__device__ float g_ho[(size_t)N0 * FHC];   // GAT output           64MB
__device__ float g_hp[(size_t)(N0 / 2) * FHC];   // pooled feats 0  32MB
__device__ float g_hp2[(size_t)(N0 / 4) * FHC];  // pooled feats 1  16MB
__device__ float g_as[N0 * 4], g_ad[N0 * 4], g_mx[N0 * 4], g_dn[N0 * 4];
__device__ float g_sc[N0];
__device__ float g_th[N0 / 2];
__device__ float g_gt[N0 / 2];
__device__ int g_s0[E0], g_d0[E0], g_s1[E0], g_d1[E0];
__device__ unsigned char g_v1[E0];
__device__ int g_deg[N0 + 1], g_off[N0 + 1], g_cur[N0], g_csr[E0];
__device__ int g_pm[N0 / 2], g_nid[N0];
__device__ int g_is64;

static inline int divup(int a, int b) { return (a + b - 1) / b; }

__device__ __forceinline__ float lrelu(float z) { return z > 0.f ? z : 0.2f * z; }

__device__ __forceinline__ void atomicMaxF(float* a, float v) {
    if (v >= 0.f) atomicMax((int*)a, __float_as_int(v));
    else          atomicMin((unsigned int*)a, __float_as_uint(v));
}

// ---------------- kernels ----------------

// Detect whether the edge buffer is int64 or int32 (JAX x64 is usually
// disabled, so "int64" edge_index is often really int32). For little-endian
// int64 node ids < 2^31, every odd 32-bit word is 0; for int32 node ids the
// odd words are random ids (all-zero probability ~ (1/2048)^32 ~ 0).
__global__ void k_detect(const int* __restrict__ w) {
    int nz = 0;
    for (int i = 1; i < 128; i += 2) nz |= (w[i] != 0);
    g_is64 = nz ? 0 : 1;
}

__global__ void k_edges(const void* __restrict__ ei, int* __restrict__ s,
                        int* __restrict__ d, int E) {
    int i = blockIdx.x * blockDim.x + threadIdx.x;
    if (i >= E) return;
    if (g_is64) {
        const long long* p = (const long long*)ei;
        s[i] = (int)p[i];
        d[i] = (int)p[E + i];
    } else {
        const int* p = (const int*)ei;
        s[i] = p[i];
        d[i] = p[E + i];
    }
}

// C[M,N] = act(A[M,K] @ B[K,N] + bias). M % 64 == 0, N % 64 == 0. K arbitrary.
__global__ void k_gemm(const float* __restrict__ A, const float* __restrict__ Bm,
                       const float* __restrict__ bias, float* __restrict__ Cm,
                       int M, int K, int N, int act) {
    __shared__ float As[16][68];  // transposed, padded (row = 272B, 16B aligned)
    __shared__ float Bs[16][64];
    int tx = threadIdx.x & 15, ty = threadIdx.x >> 4;
    int row0 = blockIdx.y * 64, col0 = blockIdx.x * 64;
    float acc[4][4] = {};
    for (int k0 = 0; k0 < K; k0 += 16) {
        for (int i = threadIdx.x; i < 64 * 16; i += 256) {
            int r = i >> 4, c = i & 15;
            float v = 0.f;
            if (k0 + c < K) v = A[(size_t)(row0 + r) * K + k0 + c];
            As[c][r] = v;
        }
        for (int i = threadIdx.x; i < 16 * 64; i += 256) {
            int r = i >> 6, c = i & 63;
            float v = 0.f;
            if (k0 + r < K) v = Bm[(size_t)(k0 + r) * N + col0 + c];
            Bs[r][c] = v;
        }
        __syncthreads();
#pragma unroll
        for (int kk = 0; kk < 16; kk++) {
            float4 a4 = *(const float4*)&As[kk][ty * 4];
            float4 b4 = *(const float4*)&Bs[kk][tx * 4];
            float av[4] = {a4.x, a4.y, a4.z, a4.w};
            float bv[4] = {b4.x, b4.y, b4.z, b4.w};
#pragma unroll
            for (int i = 0; i < 4; i++)
#pragma unroll
                for (int j = 0; j < 4; j++)
                    acc[i][j] = fmaf(av[i], bv[j], acc[i][j]);
        }
        __syncthreads();
    }
#pragma unroll
    for (int i = 0; i < 4; i++) {
        int r = row0 + ty * 4 + i;
#pragma unroll
        for (int j = 0; j < 4; j++) {
            int c = col0 + tx * 4 + j;
            float v = acc[i][j];
            if (bias) v += bias[c];
            if (act) v = fmaxf(v, 0.f);
            Cm[(size_t)r * N + c] = v;
        }
    }
}

// per (node, head): a_s = <h1[n,h,:], asrc[h,:]>, a_d = <h1[n,h,:], adst[h,:]>
__global__ void k_attn(const float* __restrict__ h, const float* __restrict__ aS,
                       const float* __restrict__ aD, float* __restrict__ as_,
                       float* __restrict__ ad_, int n) {
    int idx = blockIdx.x * blockDim.x + threadIdx.x;
    if (idx >= n * 4) return;
    int node = idx >> 2, hh = idx & 3;
    const float* hv = h + (size_t)node * FHC + hh * 64;
    const float* ws = aS + hh * 64;
    const float* wd = aD + hh * 64;
    float s = 0.f, d = 0.f;
#pragma unroll 8
    for (int c = 0; c < 64; c++) {
        float v = hv[c];
        s = fmaf(v, ws[c], s);
        d = fmaf(v, wd[c], d);
    }
    as_[idx] = s; ad_[idx] = d;
}

__global__ void k_mxinit(const float* __restrict__ as_, const float* __restrict__ ad_,
                         float* __restrict__ mx, int n) {
    int idx = blockIdx.x * blockDim.x + threadIdx.x;
    if (idx < n * 4) mx[idx] = lrelu(as_[idx] + ad_[idx]);  // self-loop logit
}

__global__ void k_emax(const int* __restrict__ s, const int* __restrict__ d,
                       const unsigned char* __restrict__ val,
                       const float* __restrict__ as_, const float* __restrict__ ad_,
                       float* __restrict__ mx, int E) {
    int e = blockIdx.x * blockDim.x + threadIdx.x;
    if (e >= E) return;
    if (val && !val[e]) return;
    int ss = s[e], dd = d[e];
#pragma unroll
    for (int h = 0; h < 4; h++) {
        float l = lrelu(as_[ss * 4 + h] + ad_[dd * 4 + h]);
        atomicMaxF(&mx[dd * 4 + h], l);
    }
}

__global__ void k_dninit(const float* __restrict__ as_, const float* __restrict__ ad_,
                         const float* __restrict__ mx, float* __restrict__ dn, int n) {
    int idx = blockIdx.x * blockDim.x + threadIdx.x;
    if (idx < n * 4) dn[idx] = expf(lrelu(as_[idx] + ad_[idx]) - mx[idx]);
}

__global__ void k_eden(const int* __restrict__ s, const int* __restrict__ d,
                       const unsigned char* __restrict__ val,
                       const float* __restrict__ as_, const float* __restrict__ ad_,
                       const float* __restrict__ mx, float* __restrict__ dn, int E) {
    int e = blockIdx.x * blockDim.x + threadIdx.x;
    if (e >= E) return;
    if (val && !val[e]) return;
    int ss = s[e], dd = d[e];
#pragma unroll
    for (int h = 0; h < 4; h++) {
        float l = lrelu(as_[ss * 4 + h] + ad_[dd * 4 + h]);
        atomicAdd(&dn[dd * 4 + h], expf(l - mx[dd * 4 + h]));
    }
}

__global__ void k_fill(int* __restrict__ p, int v, int n) {
    int i = blockIdx.x * blockDim.x + threadIdx.x;
    if (i < n) p[i] = v;
}

__global__ void k_copy(const int* __restrict__ a, int* __restrict__ b, int n) {
    int i = blockIdx.x * blockDim.x + threadIdx.x;
    if (i < n) b[i] = a[i];
}

__global__ void k_edeg(const int* __restrict__ d, const unsigned char* __restrict__ val,
                       int* __restrict__ deg, int E) {
    int e = blockIdx.x * blockDim.x + threadIdx.x;
    if (e >= E) return;
    if (val && !val[e]) return;
    atomicAdd(&deg[d[e]], 1);
}

// single-block chunked exclusive scan; out has n+1 entries (out[n] = total)
__global__ void __launch_bounds__(1024) k_scan(const int* __restrict__ in,
                                               int* __restrict__ out, int n) {
    __shared__ int sm[1024];
    __shared__ int carry;
    int t = threadIdx.x;
    if (t == 0) carry = 0;
    __syncthreads();
    for (int base = 0; base < n; base += 1024) {
        int i = base + t;
        int v = (i < n) ? in[i] : 0;
        sm[t] = v;
        __syncthreads();
        for (int o = 1; o < 1024; o <<= 1) {
            int u = (t >= o) ? sm[t - o] : 0;
            __syncthreads();
            sm[t] += u;
            __syncthreads();
        }
        if (i < n) out[i] = carry + sm[t] - v;
        __syncthreads();
        if (t == 1023) carry += sm[1023];
        __syncthreads();
    }
    if (t == 0) out[n] = carry;
}

__global__ void k_escatter(const int* __restrict__ s, const int* __restrict__ d,
                           const unsigned char* __restrict__ val, int* __restrict__ cur,
                           int* __restrict__ csr, int E) {
    int e = blockIdx.x * blockDim.x + threadIdx.x;
    if (e >= E) return;
    if (val && !val[e]) return;
    int p = atomicAdd(&cur[d[e]], 1);
    csr[p] = s[e];
}

// one warp per dst node; lane owns 8 contiguous channels -> head = lane/8
__global__ void k_gather(const float* __restrict__ h1, const int* __restrict__ off,
                         const int* __restrict__ csr,
                         const float* __restrict__ as_, const float* __restrict__ ad_,
                         const float* __restrict__ mx, const float* __restrict__ dn,
                         const float* __restrict__ bias, float* __restrict__ out, int n) {
    int wp = (blockIdx.x * blockDim.x + threadIdx.x) >> 5;
    if (wp >= n) return;
    int lane = threadIdx.x & 31;
    int head = lane >> 3;
    int d = wp;
    float adh = ad_[d * 4 + head];
    float mxh = mx[d * 4 + head];
    float inv = 1.f / (dn[d * 4 + head] + 1e-16f);
    float acc[8] = {0, 0, 0, 0, 0, 0, 0, 0};
    // self loop
    {
        float l = lrelu(as_[d * 4 + head] + adh);
        float cw = expf(l - mxh) * inv;
        const float4* p = (const float4*)(h1 + (size_t)d * FHC + lane * 8);
        float4 x0 = p[0], x1 = p[1];
        acc[0] += cw * x0.x; acc[1] += cw * x0.y; acc[2] += cw * x0.z; acc[3] += cw * x0.w;
        acc[4] += cw * x1.x; acc[5] += cw * x1.y; acc[6] += cw * x1.z; acc[7] += cw * x1.w;
    }
    int e1 = off[d + 1];
    for (int e = off[d]; e < e1; e++) {
        int s = csr[e];
        float l = lrelu(as_[s * 4 + head] + adh);
        float cw = expf(l - mxh) * inv;
        const float4* p = (const float4*)(h1 + (size_t)s * FHC + lane * 8);
        float4 x0 = p[0], x1 = p[1];
        acc[0] += cw * x0.x; acc[1] += cw * x0.y; acc[2] += cw * x0.z; acc[3] += cw * x0.w;
        acc[4] += cw * x1.x; acc[5] += cw * x1.y; acc[6] += cw * x1.z; acc[7] += cw * x1.w;
    }
    int cb = lane * 8;
    float4 o0, o1;
    float v;
    v = acc[0] + bias[cb + 0]; o0.x = v > 0.f ? v : expm1f(v);
    v = acc[1] + bias[cb + 1]; o0.y = v > 0.f ? v : expm1f(v);
    v = acc[2] + bias[cb + 2]; o0.z = v > 0.f ? v : expm1f(v);
    v = acc[3] + bias[cb + 3]; o0.w = v > 0.f ? v : expm1f(v);
    v = acc[4] + bias[cb + 4]; o1.x = v > 0.f ? v : expm1f(v);
    v = acc[5] + bias[cb + 5]; o1.y = v > 0.f ? v : expm1f(v);
    v = acc[6] + bias[cb + 6]; o1.z = v > 0.f ? v : expm1f(v);
    v = acc[7] + bias[cb + 7]; o1.w = v > 0.f ? v : expm1f(v);
    float4* po = (float4*)(out + (size_t)d * FHC + cb);
    po[0] = o0; po[1] = o1;
}

// one warp per node: normalized score = <h, w> / (||w|| + eps)
__global__ void k_score(const float* __restrict__ h, const float* __restrict__ w,
                        float* __restrict__ sc, int m) {
    int wp = (blockIdx.x * blockDim.x + threadIdx.x) >> 5;
    if (wp >= m) return;
    int lane = threadIdx.x & 31;
    const float* r = h + (size_t)wp * FHC;
    float s = 0.f, n2 = 0.f;
    for (int c = lane; c < FHC; c += 32) {
        float ww = w[c];
        s = fmaf(r[c], ww, s);
        n2 = fmaf(ww, ww, n2);
    }
    for (int o = 16; o; o >>= 1) {
        s += __shfl_xor_sync(0xffffffffu, s, o);
        n2 += __shfl_xor_sync(0xffffffffu, n2, o);
    }
    if (!lane) sc[wp] = s / (sqrtf(n2) + 1e-16f);
}

// exact top-k per graph via tie-broken rank counting; compacts in node order
// (final output is invariant to within-graph node order).
__global__ void __launch_bounds__(1024) k_topk(const float* __restrict__ score, int n_in,
                                               int k, int* __restrict__ perm,
                                               float* __restrict__ tanhv,
                                               int* __restrict__ newid) {
    __shared__ float sv[2048];
    __shared__ int sc[1024];
    int b = blockIdx.x, t = threadIdx.x;
    const float* s = score + b * n_in;
    for (int i = t; i < n_in; i += 1024) sv[i] = s[i];
    __syncthreads();
    int per = n_in >> 10;  // 1 or 2
    int cnt[2] = {0, 0};
    float mine[2] = {0.f, 0.f};
    int mi[2] = {0, 0};
    for (int q = 0; q < 2; q++)
        if (q < per) { mi[q] = t * per + q; mine[q] = sv[mi[q]]; }
    for (int j = 0; j < n_in; j++) {
        float x = sv[j];
        for (int q = 0; q < 2; q++)
            if (q < per)
                cnt[q] += (x > mine[q]) || (x == mine[q] && j < mi[q]);
    }
    int keep[2] = {0, 0};
    int local = 0;
    for (int q = 0; q < 2; q++)
        if (q < per) { keep[q] = (cnt[q] < k); local += keep[q]; }
    sc[t] = local;
    __syncthreads();
    for (int o = 1; o < 1024; o <<= 1) {
        int u = (t >= o) ? sc[t - o] : 0;
        __syncthreads();
        sc[t] += u;
        __syncthreads();
    }
    int pos = sc[t] - local;
    for (int q = 0; q < 2; q++) {
        if (q >= per) break;
        int oldl = mi[q];
        int old = b * n_in + oldl;
        if (keep[q]) {
            int np = b * k + pos;
            perm[np] = old;
            tanhv[np] = tanhf(mine[q]);
            newid[old] = np;
            pos++;
        } else {
            newid[old] = -1;
        }
    }
}

__global__ void k_poolfeat(const float* __restrict__ h, const int* __restrict__ pm,
                           const float* __restrict__ th, float* __restrict__ hp, int m) {
    int i = blockIdx.x * blockDim.x + threadIdx.x;
    if (i < m * FHC) {
        int nd = i >> 8, c = i & 255;
        hp[i] = h[(size_t)pm[nd] * FHC + c] * th[nd];
    }
}

__global__ void k_remap(const int* __restrict__ si, const int* __restrict__ di,
                        const int* __restrict__ nid, int* __restrict__ so,
                        int* __restrict__ dq, unsigned char* __restrict__ vo, int E) {
    int e = blockIdx.x * blockDim.x + threadIdx.x;
    if (e >= E) return;
    int ns = nid[si[e]], nd = nid[di[e]];
    bool v = (ns >= 0) && (nd >= 0);
    so[e] = v ? ns : 0;
    dq[e] = v ? nd : 0;
    vo[e] = v ? 1 : 0;
}

__global__ void k_gate(const float* __restrict__ hp, const float* __restrict__ gw,
                       const float* __restrict__ gb, float* __restrict__ gt, int m) {
    int wp = (blockIdx.x * blockDim.x + threadIdx.x) >> 5;
    if (wp >= m) return;
    int lane = threadIdx.x & 31;
    const float* r = hp + (size_t)wp * FHC;
    float s = 0.f;
    for (int c = lane; c < FHC; c += 32) s = fmaf(r[c], gw[c], s);
    for (int o = 16; o; o >>= 1) s += __shfl_xor_sync(0xffffffffu, s, o);
    if (!lane) gt[wp] = s + gb[0];
}

// block per graph, thread per output feature; npg <= 1024
__global__ void k_attpool(const float* __restrict__ hp, const float* __restrict__ gate,
                          float* __restrict__ out, int npg, int acc) {
    __shared__ float red[256];
    __shared__ float w[1024];
    int b = blockIdx.x, t = threadIdx.x;
    const float* g = gate + b * npg;
    float mxv = -1e30f;
    for (int i = t; i < npg; i += 256) mxv = fmaxf(mxv, g[i]);
    red[t] = mxv;
    __syncthreads();
    for (int o = 128; o; o >>= 1) { if (t < o) red[t] = fmaxf(red[t], red[t + o]); __syncthreads(); }
    float m = red[0];
    __syncthreads();
    float sum = 0.f;
    for (int i = t; i < npg; i += 256) {
        float e = expf(g[i] - m);
        w[i] = e;
        sum += e;
    }
    red[t] = sum;
    __syncthreads();
    for (int o = 128; o; o >>= 1) { if (t < o) red[t] += red[t + o]; __syncthreads(); }
    float inv = 1.f / red[0];
    __syncthreads();
    float a = 0.f;
    const float* hb = hp + (size_t)b * npg * FHC;
    for (int i = 0; i < npg; i++) a = fmaf(w[i], hb[(size_t)i * FHC + t], a);
    a *= inv;
    float* po = out + b * FHC + t;
    if (acc) *po += a; else *po = a;
}

// ---------------- host side ----------------

extern "C" void kernel_launch(void* const* d_in, const int* in_sizes, int n_in,
                              void* d_out, int out_size) {
    const float* x        = (const float*)d_in[0];
    const void*  ei       = d_in[1];
    const float* lin0_w   = (const float*)d_in[2];
    const float* lin0_b   = (const float*)d_in[3];
    const float* gat0_W   = (const float*)d_in[4];
    const float* gat0_as  = (const float*)d_in[5];
    const float* gat0_ad  = (const float*)d_in[6];
    const float* gat0_b   = (const float*)d_in[7];
    const float* pool0_w  = (const float*)d_in[8];
    const float* gat1_W   = (const float*)d_in[9];
    const float* gat1_as  = (const float*)d_in[10];
    const float* gat1_ad  = (const float*)d_in[11];
    const float* gat1_b   = (const float*)d_in[12];
    const float* pool1_w  = (const float*)d_in[13];
    const float* gate_w   = (const float*)d_in[14];
    const float* gate_b   = (const float*)d_in[15];
    float* out = (float*)d_out;

    float *h0, *h1, *ho, *hp, *hp2, *as_, *ad_, *mx_, *dn_, *sc, *th, *gt;
    int *s0, *d0, *s1, *d1, *deg, *off, *cur, *csr, *pm, *nid;
    unsigned char* v1;
    cudaGetSymbolAddress((void**)&h0, g_h0);
    cudaGetSymbolAddress((void**)&h1, g_h1);
    cudaGetSymbolAddress((void**)&ho, g_ho);
    cudaGetSymbolAddress((void**)&hp, g_hp);
    cudaGetSymbolAddress((void**)&hp2, g_hp2);
    cudaGetSymbolAddress((void**)&as_, g_as);
    cudaGetSymbolAddress((void**)&ad_, g_ad);
    cudaGetSymbolAddress((void**)&mx_, g_mx);
    cudaGetSymbolAddress((void**)&dn_, g_dn);
    cudaGetSymbolAddress((void**)&sc, g_sc);
    cudaGetSymbolAddress((void**)&th, g_th);
    cudaGetSymbolAddress((void**)&gt, g_gt);
    cudaGetSymbolAddress((void**)&s0, g_s0);
    cudaGetSymbolAddress((void**)&d0, g_d0);
    cudaGetSymbolAddress((void**)&s1, g_s1);
    cudaGetSymbolAddress((void**)&d1, g_d1);
    cudaGetSymbolAddress((void**)&deg, g_deg);
    cudaGetSymbolAddress((void**)&off, g_off);
    cudaGetSymbolAddress((void**)&cur, g_cur);
    cudaGetSymbolAddress((void**)&csr, g_csr);
    cudaGetSymbolAddress((void**)&pm, g_pm);
    cudaGetSymbolAddress((void**)&nid, g_nid);
    cudaGetSymbolAddress((void**)&v1, g_v1);

    const int EB = divup(E0, 256);

    // GAT stage: hidden GEMM -> attention coeffs -> segment softmax -> CSR gather
    auto gat = [&](const float* fin, int n, const int* src, const int* dst,
                   const unsigned char* val, const float* W, const float* aS,
                   const float* aD, const float* bias, float* fout) {
        k_gemm<<<dim3(4, n / 64), 256>>>(fin, W, nullptr, h1, n, 256, 256, 0);
        k_attn<<<divup(n * 4, 256), 256>>>(h1, aS, aD, as_, ad_, n);
        k_mxinit<<<divup(n * 4, 256), 256>>>(as_, ad_, mx_, n);
        k_emax<<<EB, 256>>>(src, dst, val, as_, ad_, mx_, E0);
        k_dninit<<<divup(n * 4, 256), 256>>>(as_, ad_, mx_, dn_, n);
        k_eden<<<EB, 256>>>(src, dst, val, as_, ad_, mx_, dn_, E0);
        k_fill<<<divup(n + 1, 256), 256>>>(deg, 0, n + 1);
        k_edeg<<<EB, 256>>>(dst, val, deg, E0);
        k_scan<<<1, 1024>>>(deg, off, n);
        k_copy<<<divup(n, 256), 256>>>(off, cur, n);
        k_escatter<<<EB, 256>>>(src, dst, val, cur, csr, E0);
        k_gather<<<divup(n, 8), 256>>>(h1, off, csr, as_, ad_, mx_, dn_, bias, fout, n);
    };

    // edge dtype detection + int32 decode
    k_detect<<<1, 1>>>((const int*)ei);
    k_edges<<<EB, 256>>>(ei, s0, d0, E0);

    // lin0: h0 = relu(x @ W + b)
    k_gemm<<<dim3(4, N0 / 64), 256>>>(x, lin0_w, lin0_b, h0, N0, 129, 256, 1);

    // GAT0 (all edges valid) -> ho (elu + bias fused in gather)
    gat(h0, N0, s0, d0, nullptr, gat0_W, gat0_as, gat0_ad, gat0_b, ho);

    // TopK pool 0: 2048 -> 1024 per graph
    k_score<<<divup(N0, 8), 256>>>(ho, pool0_w, sc, N0);
    k_topk<<<NB, 1024>>>(sc, 2048, 1024, pm, th, nid);
    k_poolfeat<<<divup((N0 / 2) * FHC, 256), 256>>>(ho, pm, th, hp, N0 / 2);
    k_remap<<<EB, 256>>>(s0, d0, nid, s1, d1, v1, E0);

    // AttPool 0 -> out (overwrite)
    k_gate<<<divup(N0 / 2, 8), 256>>>(hp, gate_w, gate_b, gt, N0 / 2);
    k_attpool<<<NB, 256>>>(hp, gt, out, 1024, 0);

    // GAT1 on pooled graph
    gat(hp, N0 / 2, s1, d1, v1, gat1_W, gat1_as, gat1_ad, gat1_b, ho);

    // TopK pool 1: 1024 -> 512 per graph
    k_score<<<divup(N0 / 2, 8), 256>>>(ho, pool1_w, sc, N0 / 2);
    k_topk<<<NB, 1024>>>(sc, 1024, 512, pm, th, nid);
    k_poolfeat<<<divup((N0 / 4) * FHC, 256), 256>>>(ho, pm, th, hp2, N0 / 4);

    // AttPool 1 -> out (accumulate)
    k_gate<<<divup(N0 / 4, 8), 256>>>(hp2, gate_w, gate_b, gt, N0 / 4);
    k_attpool<<<NB, 256>>>(hp2, gt, out, 512, 1);
}

// round 3
// speedup vs baseline: 1.2881x; 1.2881x over previous
#include <cuda_runtime.h>
#include <math.h>
#include <stdint.h>

#define N0  65536     // total nodes
#define E0  524288    // total edges
#define NB  32        // graphs
#define FHC 256       // feature width (H*C)

// ---------------- static device scratch (no allocations allowed) ----------------
__device__ float g_h0[(size_t)N0 * FHC];   // lin0 output          64MB
__device__ float g_h1[(size_t)N0 * FHC];   // GAT hidden (h @ W)   64MB
__device__ float g_ho[(size_t)N0 * FHC];   // GAT output           64MB
__device__ float g_hp[(size_t)(N0 / 2) * FHC];   // pooled feats 0  32MB
__device__ float g_hp2[(size_t)(N0 / 4) * FHC];  // pooled feats 1  16MB
__device__ float g_as[N0 * 4], g_ad[N0 * 4];
__device__ float g_sc[N0];
__device__ float g_th[N0 / 2];
__device__ float g_gt[N0 / 2];
__device__ int g_s0[E0], g_d0[E0], g_s1[E0], g_d1[E0];
__device__ unsigned char g_v1[E0];
__device__ int g_deg[N0], g_off[N0 + 1], g_cur[N0], g_csr[E0];
__device__ int g_bs[64];
__device__ int g_pm[N0 / 2], g_nid[N0];
__device__ int g_is64;

static inline int divup(int a, int b) { return (a + b - 1) / b; }

__device__ __forceinline__ float lrelu(float z) { return z > 0.f ? z : 0.2f * z; }

// ---------------- kernels ----------------

// Detect int64 vs int32 edge buffer (JAX x64 usually off -> really int32).
__global__ void k_detect(const int* __restrict__ w) {
    int nz = 0;
    for (int i = 1; i < 128; i += 2) nz |= (w[i] != 0);
    g_is64 = nz ? 0 : 1;
}

__global__ void k_edges(const void* __restrict__ ei, int* __restrict__ s,
                        int* __restrict__ d, int E) {
    int i = blockIdx.x * blockDim.x + threadIdx.x;
    if (i >= E) return;
    if (g_is64) {
        const long long* p = (const long long*)ei;
        s[i] = (int)p[i];
        d[i] = (int)p[E + i];
    } else {
        const int* p = (const int*)ei;
        s[i] = p[i];
        d[i] = p[E + i];
    }
}

// C[M,N] = act(A[M,K] @ B[K,N] + bias). M%128==0, N%128==0, K arbitrary.
// 128x128 block tile, BK=16, 256 threads, 8x8 register tile per thread.
__global__ void __launch_bounds__(256, 2)
k_gemm(const float* __restrict__ A, const float* __restrict__ Bm,
       const float* __restrict__ bias, float* __restrict__ Cm,
       int M, int K, int N, int act) {
    __shared__ float As[16][132];  // transposed A tile; pitch 132 keeps 16B align
    __shared__ float Bs[16][128];
    int t = threadIdx.x;
    int tx = t & 15, ty = t >> 4;
    int row0 = blockIdx.y * 128, col0 = blockIdx.x * 128;
    float acc[8][8] = {};
    for (int k0 = 0; k0 < K; k0 += 16) {
        // A tile: 128x16 scalars, coalesced along K
#pragma unroll
        for (int it = 0; it < 8; it++) {
            int lin = t + 256 * it;
            int r = lin >> 4, c = lin & 15;
            float v = 0.f;
            if (k0 + c < K) v = A[(size_t)(row0 + r) * K + k0 + c];
            As[c][r] = v;
        }
        // B tile: 16x128 via float4, coalesced along N
#pragma unroll
        for (int it = 0; it < 2; it++) {
            int lin = t + 256 * it;       // 512 float4 slots
            int kk = lin >> 5, c4 = lin & 31;
            float4 v = {0.f, 0.f, 0.f, 0.f};
            if (k0 + kk < K)
                v = *(const float4*)&Bm[(size_t)(k0 + kk) * N + col0 + c4 * 4];
            *(float4*)&Bs[kk][c4 * 4] = v;
        }
        __syncthreads();
#pragma unroll
        for (int kk = 0; kk < 16; kk++) {
            float4 a0 = *(const float4*)&As[kk][ty * 8];
            float4 a1 = *(const float4*)&As[kk][ty * 8 + 4];
            float4 b0 = *(const float4*)&Bs[kk][tx * 8];
            float4 b1 = *(const float4*)&Bs[kk][tx * 8 + 4];
            float av[8] = {a0.x, a0.y, a0.z, a0.w, a1.x, a1.y, a1.z, a1.w};
            float bv[8] = {b0.x, b0.y, b0.z, b0.w, b1.x, b1.y, b1.z, b1.w};
#pragma unroll
            for (int i = 0; i < 8; i++)
#pragma unroll
                for (int j = 0; j < 8; j++)
                    acc[i][j] = fmaf(av[i], bv[j], acc[i][j]);
        }
        __syncthreads();
    }
#pragma unroll
    for (int i = 0; i < 8; i++) {
        int r = row0 + ty * 8 + i;
        float* crow = Cm + (size_t)r * N + col0 + tx * 8;
        float4 o0, o1;
        float vv[8];
#pragma unroll
        for (int j = 0; j < 8; j++) {
            float v = acc[i][j];
            if (bias) v += bias[col0 + tx * 8 + j];
            if (act) v = fmaxf(v, 0.f);
            vv[j] = v;
        }
        o0.x = vv[0]; o0.y = vv[1]; o0.z = vv[2]; o0.w = vv[3];
        o1.x = vv[4]; o1.y = vv[5]; o1.z = vv[6]; o1.w = vv[7];
        *(float4*)crow = o0;
        *(float4*)(crow + 4) = o1;
    }
}

// per (node, head): a_s = <h1[n,h,:], asrc[h,:]>, a_d = <h1[n,h,:], adst[h,:]>
__global__ void k_attn(const float* __restrict__ h, const float* __restrict__ aS,
                       const float* __restrict__ aD, float* __restrict__ as_,
                       float* __restrict__ ad_, int n) {
    int idx = blockIdx.x * blockDim.x + threadIdx.x;
    if (idx >= n * 4) return;
    int node = idx >> 2, hh = idx & 3;
    const float* hv = h + (size_t)node * FHC + hh * 64;
    const float* ws = aS + hh * 64;
    const float* wd = aD + hh * 64;
    float s = 0.f, d = 0.f;
#pragma unroll 8
    for (int c = 0; c < 64; c++) {
        float v = hv[c];
        s = fmaf(v, ws[c], s);
        d = fmaf(v, wd[c], d);
    }
    as_[idx] = s; ad_[idx] = d;
}

__global__ void k_fill(int* __restrict__ p, int v, int n) {
    int i = blockIdx.x * blockDim.x + threadIdx.x;
    if (i < n) p[i] = v;
}

__global__ void k_edeg(const int* __restrict__ d, const unsigned char* __restrict__ val,
                       int* __restrict__ deg, int E) {
    int e = blockIdx.x * blockDim.x + threadIdx.x;
    if (e >= E) return;
    if (val && !val[e]) return;
    atomicAdd(&deg[d[e]], 1);
}

// multi-block exclusive scan, stage 1: per-1024 chunk scan + block sums
__global__ void __launch_bounds__(1024) k_scan1(const int* __restrict__ in,
                                                int* __restrict__ out,
                                                int* __restrict__ bsum, int n) {
    __shared__ int sm[1024];
    int t = threadIdx.x;
    int i = blockIdx.x * 1024 + t;
    int v = (i < n) ? in[i] : 0;
    sm[t] = v;
    __syncthreads();
    for (int o = 1; o < 1024; o <<= 1) {
        int u = (t >= o) ? sm[t - o] : 0;
        __syncthreads();
        sm[t] += u;
        __syncthreads();
    }
    if (i < n) out[i] = sm[t] - v;
    if (t == 1023) bsum[blockIdx.x] = sm[1023];
}

// stage 2: serial exclusive scan of <=64 block sums (1 thread), total -> off[n]
__global__ void k_scan2(int* __restrict__ bsum, int nb, int* __restrict__ off, int n) {
    int total = 0;
    for (int i = 0; i < nb; i++) { int v = bsum[i]; bsum[i] = total; total += v; }
    off[n] = total;
}

// stage 3: add block offsets; also produce the scatter cursor copy
__global__ void __launch_bounds__(1024) k_scan3(int* __restrict__ off,
                                                const int* __restrict__ bsum,
                                                int* __restrict__ cur, int n) {
    int i = blockIdx.x * 1024 + threadIdx.x;
    if (i < n) {
        int v = off[i] + bsum[blockIdx.x];
        off[i] = v;
        cur[i] = v;
    }
}

__global__ void k_escatter(const int* __restrict__ s, const int* __restrict__ d,
                           const unsigned char* __restrict__ val, int* __restrict__ cur,
                           int* __restrict__ csr, int E) {
    int e = blockIdx.x * blockDim.x + threadIdx.x;
    if (e >= E) return;
    if (val && !val[e]) return;
    int p = atomicAdd(&cur[d[e]], 1);
    csr[p] = s[e];
}

// Fused GAT aggregation: one warp per dst node, online (rescaling) softmax over
// {self} U neighbors, feature accumulate, bias + ELU epilogue.
// lane owns 8 contiguous channels -> head = lane/8.
__global__ void k_gather(const float* __restrict__ h1, const int* __restrict__ off,
                         const int* __restrict__ csr,
                         const float* __restrict__ as_, const float* __restrict__ ad_,
                         const float* __restrict__ bias, float* __restrict__ out, int n) {
    int wp = (blockIdx.x * blockDim.x + threadIdx.x) >> 5;
    if (wp >= n) return;
    int lane = threadIdx.x & 31;
    int head = lane >> 3;
    int d = wp;
    float adh = ad_[d * 4 + head];
    // init with self loop (weight exp(0) relative to mx = self logit)
    float mx = lrelu(as_[d * 4 + head] + adh);
    float den = 1.f;
    float acc[8];
    {
        const float4* p = (const float4*)(h1 + (size_t)d * FHC + lane * 8);
        float4 x0 = p[0], x1 = p[1];
        acc[0] = x0.x; acc[1] = x0.y; acc[2] = x0.z; acc[3] = x0.w;
        acc[4] = x1.x; acc[5] = x1.y; acc[6] = x1.z; acc[7] = x1.w;
    }
    int e1 = off[d + 1];
    for (int e = off[d]; e < e1; e++) {
        int s = csr[e];
        float l = lrelu(as_[s * 4 + head] + adh);
        float nm = fmaxf(mx, l);
        float scl = expf(mx - nm);   // 1 when no new max
        float w = expf(l - nm);
        den = den * scl + w;
        mx = nm;
        const float4* p = (const float4*)(h1 + (size_t)s * FHC + lane * 8);
        float4 x0 = p[0], x1 = p[1];
        acc[0] = acc[0] * scl + w * x0.x;
        acc[1] = acc[1] * scl + w * x0.y;
        acc[2] = acc[2] * scl + w * x0.z;
        acc[3] = acc[3] * scl + w * x0.w;
        acc[4] = acc[4] * scl + w * x1.x;
        acc[5] = acc[5] * scl + w * x1.y;
        acc[6] = acc[6] * scl + w * x1.z;
        acc[7] = acc[7] * scl + w * x1.w;
    }
    float inv = 1.f / (den + 1e-16f);
    int cb = lane * 8;
    float4 o0, o1;
    float v;
    v = acc[0] * inv + bias[cb + 0]; o0.x = v > 0.f ? v : expm1f(v);
    v = acc[1] * inv + bias[cb + 1]; o0.y = v > 0.f ? v : expm1f(v);
    v = acc[2] * inv + bias[cb + 2]; o0.z = v > 0.f ? v : expm1f(v);
    v = acc[3] * inv + bias[cb + 3]; o0.w = v > 0.f ? v : expm1f(v);
    v = acc[4] * inv + bias[cb + 4]; o1.x = v > 0.f ? v : expm1f(v);
    v = acc[5] * inv + bias[cb + 5]; o1.y = v > 0.f ? v : expm1f(v);
    v = acc[6] * inv + bias[cb + 6]; o1.z = v > 0.f ? v : expm1f(v);
    v = acc[7] * inv + bias[cb + 7]; o1.w = v > 0.f ? v : expm1f(v);
    float4* po = (float4*)(out + (size_t)d * FHC + cb);
    po[0] = o0; po[1] = o1;
}

// one warp per node: normalized score = <h, w> / (||w|| + eps)
__global__ void k_score(const float* __restrict__ h, const float* __restrict__ w,
                        float* __restrict__ sc, int m) {
    int wp = (blockIdx.x * blockDim.x + threadIdx.x) >> 5;
    if (wp >= m) return;
    int lane = threadIdx.x & 31;
    const float* r = h + (size_t)wp * FHC;
    float s = 0.f, n2 = 0.f;
    for (int c = lane; c < FHC; c += 32) {
        float ww = w[c];
        s = fmaf(r[c], ww, s);
        n2 = fmaf(ww, ww, n2);
    }
    for (int o = 16; o; o >>= 1) {
        s += __shfl_xor_sync(0xffffffffu, s, o);
        n2 += __shfl_xor_sync(0xffffffffu, n2, o);
    }
    if (!lane) sc[wp] = s / (sqrtf(n2) + 1e-16f);
}

// exact top-k per graph via tie-broken rank counting; compacts in node order
// (final output is invariant to within-graph node order).
__global__ void __launch_bounds__(1024) k_topk(const float* __restrict__ score, int n_in,
                                               int k, int* __restrict__ perm,
                                               float* __restrict__ tanhv,
                                               int* __restrict__ newid) {
    __shared__ float sv[2048];
    __shared__ int sc[1024];
    int b = blockIdx.x, t = threadIdx.x;
    const float* s = score + b * n_in;
    for (int i = t; i < n_in; i += 1024) sv[i] = s[i];
    __syncthreads();
    int per = n_in >> 10;  // 1 or 2
    int cnt[2] = {0, 0};
    float mine[2] = {0.f, 0.f};
    int mi[2] = {0, 0};
    for (int q = 0; q < 2; q++)
        if (q < per) { mi[q] = t * per + q; mine[q] = sv[mi[q]]; }
    for (int j = 0; j < n_in; j++) {
        float x = sv[j];
        for (int q = 0; q < 2; q++)
            if (q < per)
                cnt[q] += (x > mine[q]) || (x == mine[q] && j < mi[q]);
    }
    int keep[2] = {0, 0};
    int local = 0;
    for (int q = 0; q < 2; q++)
        if (q < per) { keep[q] = (cnt[q] < k); local += keep[q]; }
    sc[t] = local;
    __syncthreads();
    for (int o = 1; o < 1024; o <<= 1) {
        int u = (t >= o) ? sc[t - o] : 0;
        __syncthreads();
        sc[t] += u;
        __syncthreads();
    }
    int pos = sc[t] - local;
    for (int q = 0; q < 2; q++) {
        if (q >= per) break;
        int oldl = mi[q];
        int old = b * n_in + oldl;
        if (keep[q]) {
            int np = b * k + pos;
            perm[np] = old;
            tanhv[np] = tanhf(mine[q]);
            newid[old] = np;
            pos++;
        } else {
            newid[old] = -1;
        }
    }
}

__global__ void k_poolfeat(const float* __restrict__ h, const int* __restrict__ pm,
                           const float* __restrict__ th, float* __restrict__ hp, int m) {
    int i = blockIdx.x * blockDim.x + threadIdx.x;
    if (i < m * FHC) {
        int nd = i >> 8, c = i & 255;
        hp[i] = h[(size_t)pm[nd] * FHC + c] * th[nd];
    }
}

__global__ void k_remap(const int* __restrict__ si, const int* __restrict__ di,
                        const int* __restrict__ nid, int* __restrict__ so,
                        int* __restrict__ dq, unsigned char* __restrict__ vo, int E) {
    int e = blockIdx.x * blockDim.x + threadIdx.x;
    if (e >= E) return;
    int ns = nid[si[e]], nd = nid[di[e]];
    bool v = (ns >= 0) && (nd >= 0);
    so[e] = v ? ns : 0;
    dq[e] = v ? nd : 0;
    vo[e] = v ? 1 : 0;
}

__global__ void k_gate(const float* __restrict__ hp, const float* __restrict__ gw,
                       const float* __restrict__ gb, float* __restrict__ gt, int m) {
    int wp = (blockIdx.x * blockDim.x + threadIdx.x) >> 5;
    if (wp >= m) return;
    int lane = threadIdx.x & 31;
    const float* r = hp + (size_t)wp * FHC;
    float s = 0.f;
    for (int c = lane; c < FHC; c += 32) s = fmaf(r[c], gw[c], s);
    for (int o = 16; o; o >>= 1) s += __shfl_xor_sync(0xffffffffu, s, o);
    if (!lane) gt[wp] = s + gb[0];
}

// block per graph, thread per output feature; npg <= 1024
__global__ void k_attpool(const float* __restrict__ hp, const float* __restrict__ gate,
                          float* __restrict__ out, int npg, int acc) {
    __shared__ float red[256];
    __shared__ float w[1024];
    int b = blockIdx.x, t = threadIdx.x;
    const float* g = gate + b * npg;
    float mxv = -1e30f;
    for (int i = t; i < npg; i += 256) mxv = fmaxf(mxv, g[i]);
    red[t] = mxv;
    __syncthreads();
    for (int o = 128; o; o >>= 1) { if (t < o) red[t] = fmaxf(red[t], red[t + o]); __syncthreads(); }
    float m = red[0];
    __syncthreads();
    float sum = 0.f;
    for (int i = t; i < npg; i += 256) {
        float e = expf(g[i] - m);
        w[i] = e;
        sum += e;
    }
    red[t] = sum;
    __syncthreads();
    for (int o = 128; o; o >>= 1) { if (t < o) red[t] += red[t + o]; __syncthreads(); }
    float inv = 1.f / red[0];
    __syncthreads();
    float a = 0.f;
    const float* hb = hp + (size_t)b * npg * FHC;
    for (int i = 0; i < npg; i++) a = fmaf(w[i], hb[(size_t)i * FHC + t], a);
    a *= inv;
    float* po = out + b * FHC + t;
    if (acc) *po += a; else *po = a;
}

// ---------------- host side ----------------

extern "C" void kernel_launch(void* const* d_in, const int* in_sizes, int n_in,
                              void* d_out, int out_size) {
    const float* x        = (const float*)d_in[0];
    const void*  ei       = d_in[1];
    const float* lin0_w   = (const float*)d_in[2];
    const float* lin0_b   = (const float*)d_in[3];
    const float* gat0_W   = (const float*)d_in[4];
    const float* gat0_as  = (const float*)d_in[5];
    const float* gat0_ad  = (const float*)d_in[6];
    const float* gat0_b   = (const float*)d_in[7];
    const float* pool0_w  = (const float*)d_in[8];
    const float* gat1_W   = (const float*)d_in[9];
    const float* gat1_as  = (const float*)d_in[10];
    const float* gat1_ad  = (const float*)d_in[11];
    const float* gat1_b   = (const float*)d_in[12];
    const float* pool1_w  = (const float*)d_in[13];
    const float* gate_w   = (const float*)d_in[14];
    const float* gate_b   = (const float*)d_in[15];
    float* out = (float*)d_out;

    float *h0, *h1, *ho, *hp, *hp2, *as_, *ad_, *sc, *th, *gt;
    int *s0, *d0, *s1, *d1, *deg, *off, *cur, *csr, *pm, *nid, *bs;
    unsigned char* v1;
    cudaGetSymbolAddress((void**)&h0, g_h0);
    cudaGetSymbolAddress((void**)&h1, g_h1);
    cudaGetSymbolAddress((void**)&ho, g_ho);
    cudaGetSymbolAddress((void**)&hp, g_hp);
    cudaGetSymbolAddress((void**)&hp2, g_hp2);
    cudaGetSymbolAddress((void**)&as_, g_as);
    cudaGetSymbolAddress((void**)&ad_, g_ad);
    cudaGetSymbolAddress((void**)&sc, g_sc);
    cudaGetSymbolAddress((void**)&th, g_th);
    cudaGetSymbolAddress((void**)&gt, g_gt);
    cudaGetSymbolAddress((void**)&s0, g_s0);
    cudaGetSymbolAddress((void**)&d0, g_d0);
    cudaGetSymbolAddress((void**)&s1, g_s1);
    cudaGetSymbolAddress((void**)&d1, g_d1);
    cudaGetSymbolAddress((void**)&deg, g_deg);
    cudaGetSymbolAddress((void**)&off, g_off);
    cudaGetSymbolAddress((void**)&cur, g_cur);
    cudaGetSymbolAddress((void**)&csr, g_csr);
    cudaGetSymbolAddress((void**)&pm, g_pm);
    cudaGetSymbolAddress((void**)&nid, g_nid);
    cudaGetSymbolAddress((void**)&bs, g_bs);
    cudaGetSymbolAddress((void**)&v1, g_v1);

    const int EB = divup(E0, 256);

    // GAT stage: hidden GEMM -> attention coeffs -> CSR build -> fused softmax gather
    auto gat = [&](const float* fin, int n, const int* src, const int* dst,
                   const unsigned char* val, const float* W, const float* aS,
                   const float* aD, const float* bias, float* fout) {
        k_gemm<<<dim3(2, n / 128), 256>>>(fin, W, nullptr, h1, n, 256, 256, 0);
        k_attn<<<divup(n * 4, 256), 256>>>(h1, aS, aD, as_, ad_, n);
        k_fill<<<divup(n, 256), 256>>>(deg, 0, n);
        k_edeg<<<EB, 256>>>(dst, val, deg, E0);
        k_scan1<<<n / 1024, 1024>>>(deg, off, bs, n);
        k_scan2<<<1, 1>>>(bs, n / 1024, off, n);
        k_scan3<<<n / 1024, 1024>>>(off, bs, cur, n);
        k_escatter<<<EB, 256>>>(src, dst, val, cur, csr, E0);
        k_gather<<<divup(n, 8), 256>>>(h1, off, csr, as_, ad_, bias, fout, n);
    };

    // edge dtype detection + int32 decode
    k_detect<<<1, 1>>>((const int*)ei);
    k_edges<<<EB, 256>>>(ei, s0, d0, E0);

    // lin0: h0 = relu(x @ W + b)
    k_gemm<<<dim3(2, N0 / 128), 256>>>(x, lin0_w, lin0_b, h0, N0, 129, 256, 1);

    // GAT0 (all edges valid) -> ho (elu + bias fused in gather)
    gat(h0, N0, s0, d0, nullptr, gat0_W, gat0_as, gat0_ad, gat0_b, ho);

    // TopK pool 0: 2048 -> 1024 per graph
    k_score<<<divup(N0, 8), 256>>>(ho, pool0_w, sc, N0);
    k_topk<<<NB, 1024>>>(sc, 2048, 1024, pm, th, nid);
    k_poolfeat<<<divup((N0 / 2) * FHC, 256), 256>>>(ho, pm, th, hp, N0 / 2);
    k_remap<<<EB, 256>>>(s0, d0, nid, s1, d1, v1, E0);

    // AttPool 0 -> out (overwrite)
    k_gate<<<divup(N0 / 2, 8), 256>>>(hp, gate_w, gate_b, gt, N0 / 2);
    k_attpool<<<NB, 256>>>(hp, gt, out, 1024, 0);

    // GAT1 on pooled graph
    gat(hp, N0 / 2, s1, d1, v1, gat1_W, gat1_as, gat1_ad, gat1_b, ho);

    // TopK pool 1: 1024 -> 512 per graph
    k_score<<<divup(N0 / 2, 8), 256>>>(ho, pool1_w, sc, N0 / 2);
    k_topk<<<NB, 1024>>>(sc, 1024, 512, pm, th, nid);
    k_poolfeat<<<divup((N0 / 4) * FHC, 256), 256>>>(ho, pm, th, hp2, N0 / 4);

    // AttPool 1 -> out (accumulate)
    k_gate<<<divup(N0 / 4, 8), 256>>>(hp2, gate_w, gate_b, gt, N0 / 4);
    k_attpool<<<NB, 256>>>(hp2, gt, out, 512, 1);
}

// round 4
// speedup vs baseline: 1.4861x; 1.1537x over previous
#include <cuda_runtime.h>
#include <math.h>
#include <stdint.h>

#define N0  65536     // total nodes
#define E0  524288    // total edges
#define NB  32        // graphs
#define FHC 256       // feature width (H*C)

// ---------------- static device scratch (no allocations allowed) ----------------
__device__ float g_h0[(size_t)N0 * FHC];
__device__ float g_h1[(size_t)N0 * FHC];
__device__ float g_ho[(size_t)N0 * FHC];
__device__ float g_hp[(size_t)(N0 / 2) * FHC];
__device__ float g_hp2[(size_t)(N0 / 4) * FHC];
__device__ float g_as[N0 * 4], g_ad[N0 * 4];
__device__ float g_sc[N0];
__device__ float g_th[N0 / 2];
__device__ float g_gt[N0 / 2];
__device__ float g_gmi[NB * 2];
__device__ int g_s0[E0], g_d0[E0], g_s1[E0], g_d1[E0];
__device__ unsigned char g_v1[E0];
__device__ int g_deg[N0], g_off[N0 + 1], g_cur[N0], g_csr[E0];
__device__ int g_bs[64];
__device__ int g_pm[N0 / 2], g_nid[N0];
__device__ int g_is64;

static inline int divup(int a, int b) { return (a + b - 1) / b; }

__device__ __forceinline__ float lrelu(float z) { return z > 0.f ? z : 0.2f * z; }

// ---------------- tf32 helpers ----------------
__device__ __forceinline__ void tf32split(float x, float& hi, float& lo) {
    uint32_t uh;
    asm("cvt.rna.tf32.f32 %0, %1;" : "=r"(uh) : "f"(x));
    hi = __uint_as_float(uh);
    float r = x - hi;
    uint32_t ul;
    asm("cvt.rna.tf32.f32 %0, %1;" : "=r"(ul) : "f"(r));
    lo = __uint_as_float(ul);
}

#define MMA_TF32(d, a, b0, b1)                                                   \
    asm volatile(                                                                \
        "mma.sync.aligned.m16n8k8.row.col.f32.tf32.tf32.f32 "                    \
        "{%0,%1,%2,%3},{%4,%5,%6,%7},{%8,%9},{%0,%1,%2,%3};"                     \
        : "+f"(d[0]), "+f"(d[1]), "+f"(d[2]), "+f"(d[3])                         \
        : "r"(a[0]), "r"(a[1]), "r"(a[2]), "r"(a[3]), "r"(b0), "r"(b1))

// ---------------- kernels ----------------

// Detect int64 vs int32 edge buffer (JAX x64 usually off -> really int32).
__global__ void k_detect(const int* __restrict__ w) {
    int nz = 0;
    for (int i = 1; i < 128; i += 2) nz |= (w[i] != 0);
    g_is64 = nz ? 0 : 1;
}

__global__ void k_edges(const void* __restrict__ ei, int* __restrict__ s,
                        int* __restrict__ d, int E) {
    int i = blockIdx.x * blockDim.x + threadIdx.x;
    if (i >= E) return;
    if (g_is64) {
        const long long* p = (const long long*)ei;
        s[i] = (int)p[i];
        d[i] = (int)p[E + i];
    } else {
        const int* p = (const int*)ei;
        s[i] = p[i];
        d[i] = p[E + i];
    }
}

// Tensor-core GEMM: C[M,N] = act(A @ B + bias), 3xTF32 (fp32-accurate).
// Block tile 128x256, BK=32, 512 threads (16 warps, warp tile 32x64).
#define ASP 132          // As pitch (floats), 132%32=4 -> conflict-free frags
#define BSP 260          // Bs pitch
#define SMEM_GEMM ((2 * 32 * ASP + 2 * 32 * BSP) * 4)
__global__ void __launch_bounds__(512, 1)
k_gemm_tc(const float* __restrict__ A, const float* __restrict__ Bm,
          const float* __restrict__ bias, float* __restrict__ Cm,
          int M, int K, int N, int act) {
    extern __shared__ float smg[];
    float* As_h = smg;
    float* As_l = As_h + 32 * ASP;
    float* Bs_h = As_l + 32 * ASP;
    float* Bs_l = Bs_h + 32 * BSP;
    int t = threadIdx.x;
    int lane = t & 31, w = t >> 5;
    int g = lane >> 2, tig = lane & 3;
    int wm = w & 3, wn = w >> 2;
    int row0 = blockIdx.y * 128, col0 = blockIdx.x * 256;
    float acc[2][8][4];
#pragma unroll
    for (int i = 0; i < 2; i++)
#pragma unroll
        for (int j = 0; j < 8; j++)
#pragma unroll
            for (int q = 0; q < 4; q++) acc[i][j][q] = 0.f;

    for (int k0 = 0; k0 < K; k0 += 32) {
        // A tile 128x32 -> transposed smem [k][m], hi/lo split
#pragma unroll
        for (int it = 0; it < 2; it++) {
            int lin = t + 512 * it;
            int r = lin >> 3, c4 = (lin & 7) * 4;
            const float* ap = A + (size_t)(row0 + r) * K + k0 + c4;
            float v[4];
#pragma unroll
            for (int j = 0; j < 4; j++)
                v[j] = (k0 + c4 + j < K) ? ap[j] : 0.f;
#pragma unroll
            for (int j = 0; j < 4; j++) {
                float hi, lo;
                tf32split(v[j], hi, lo);
                As_h[(c4 + j) * ASP + r] = hi;
                As_l[(c4 + j) * ASP + r] = lo;
            }
        }
        // B tile 32x256 -> smem [k][n], hi/lo split, float4 stores
#pragma unroll
        for (int it = 0; it < 4; it++) {
            int lin = t + 512 * it;
            int kk = lin >> 6, c4 = (lin & 63) * 4;
            float v[4] = {0.f, 0.f, 0.f, 0.f};
            if (k0 + kk < K)
                *(float4*)v = *(const float4*)&Bm[(size_t)(k0 + kk) * N + col0 + c4];
            float h4[4], l4[4];
#pragma unroll
            for (int j = 0; j < 4; j++) tf32split(v[j], h4[j], l4[j]);
            *(float4*)&Bs_h[kk * BSP + c4] = *(float4*)h4;
            *(float4*)&Bs_l[kk * BSP + c4] = *(float4*)l4;
        }
        __syncthreads();
#pragma unroll
        for (int ks = 0; ks < 4; ks++) {
            int k8 = ks * 8;
            int r0 = (k8 + tig) * ASP, r1 = (k8 + tig + 4) * ASP;
            uint32_t ah[2][4], al[2][4];
#pragma unroll
            for (int mt = 0; mt < 2; mt++) {
                int bm = wm * 32 + mt * 16 + g;
                ah[mt][0] = __float_as_uint(As_h[r0 + bm]);
                ah[mt][1] = __float_as_uint(As_h[r0 + bm + 8]);
                ah[mt][2] = __float_as_uint(As_h[r1 + bm]);
                ah[mt][3] = __float_as_uint(As_h[r1 + bm + 8]);
                al[mt][0] = __float_as_uint(As_l[r0 + bm]);
                al[mt][1] = __float_as_uint(As_l[r0 + bm + 8]);
                al[mt][2] = __float_as_uint(As_l[r1 + bm]);
                al[mt][3] = __float_as_uint(As_l[r1 + bm + 8]);
            }
            int q0 = (k8 + tig) * BSP, q1 = (k8 + tig + 4) * BSP;
#pragma unroll
            for (int nt = 0; nt < 8; nt++) {
                int bn = wn * 64 + nt * 8 + g;
                uint32_t b0h = __float_as_uint(Bs_h[q0 + bn]);
                uint32_t b1h = __float_as_uint(Bs_h[q1 + bn]);
                uint32_t b0l = __float_as_uint(Bs_l[q0 + bn]);
                uint32_t b1l = __float_as_uint(Bs_l[q1 + bn]);
#pragma unroll
                for (int mt = 0; mt < 2; mt++) {
                    MMA_TF32(acc[mt][nt], ah[mt], b0h, b1h);
                    MMA_TF32(acc[mt][nt], ah[mt], b0l, b1l);
                    MMA_TF32(acc[mt][nt], al[mt], b0h, b1h);
                }
            }
        }
        __syncthreads();
    }
    // epilogue: c0,c1 -> (row g, col tig*2, tig*2+1); c2,c3 -> row g+8
#pragma unroll
    for (int mt = 0; mt < 2; mt++) {
        int r = row0 + wm * 32 + mt * 16 + g;
#pragma unroll
        for (int nt = 0; nt < 8; nt++) {
            int cc = col0 + wn * 64 + nt * 8 + tig * 2;
            float b0 = bias ? bias[cc] : 0.f, b1 = bias ? bias[cc + 1] : 0.f;
            float v0 = acc[mt][nt][0] + b0, v1 = acc[mt][nt][1] + b1;
            float v2 = acc[mt][nt][2] + b0, v3 = acc[mt][nt][3] + b1;
            if (act) {
                v0 = fmaxf(v0, 0.f); v1 = fmaxf(v1, 0.f);
                v2 = fmaxf(v2, 0.f); v3 = fmaxf(v3, 0.f);
            }
            float2 p0 = {v0, v1}, p1 = {v2, v3};
            *(float2*)&Cm[(size_t)r * N + cc] = p0;
            *(float2*)&Cm[(size_t)(r + 8) * N + cc] = p1;
        }
    }
}

// per (node, head): a_s = <h1[n,h,:], asrc[h,:]>, a_d = <h1[n,h,:], adst[h,:]>
__global__ void k_attn(const float* __restrict__ h, const float* __restrict__ aS,
                       const float* __restrict__ aD, float* __restrict__ as_,
                       float* __restrict__ ad_, int n) {
    int idx = blockIdx.x * blockDim.x + threadIdx.x;
    if (idx >= n * 4) return;
    int node = idx >> 2, hh = idx & 3;
    const float4* hv = (const float4*)(h + (size_t)node * FHC + hh * 64);
    const float4* ws = (const float4*)(aS + hh * 64);
    const float4* wd = (const float4*)(aD + hh * 64);
    float s = 0.f, d = 0.f;
#pragma unroll
    for (int c = 0; c < 16; c++) {
        float4 v = hv[c], a = ws[c], b = wd[c];
        s = fmaf(v.x, a.x, s); s = fmaf(v.y, a.y, s);
        s = fmaf(v.z, a.z, s); s = fmaf(v.w, a.w, s);
        d = fmaf(v.x, b.x, d); d = fmaf(v.y, b.y, d);
        d = fmaf(v.z, b.z, d); d = fmaf(v.w, b.w, d);
    }
    as_[idx] = s; ad_[idx] = d;
}

__global__ void k_fill(int* __restrict__ p, int v, int n) {
    int i = blockIdx.x * blockDim.x + threadIdx.x;
    if (i < n) p[i] = v;
}

__global__ void k_zerof(float* __restrict__ p, int n) {
    int i = blockIdx.x * blockDim.x + threadIdx.x;
    if (i < n) p[i] = 0.f;
}

__global__ void k_edeg(const int* __restrict__ d, const unsigned char* __restrict__ val,
                       int* __restrict__ deg, int E) {
    int e = blockIdx.x * blockDim.x + threadIdx.x;
    if (e >= E) return;
    if (val && !val[e]) return;
    atomicAdd(&deg[d[e]], 1);
}

__global__ void __launch_bounds__(1024) k_scan1(const int* __restrict__ in,
                                                int* __restrict__ out,
                                                int* __restrict__ bsum, int n) {
    __shared__ int sm[1024];
    int t = threadIdx.x;
    int i = blockIdx.x * 1024 + t;
    int v = (i < n) ? in[i] : 0;
    sm[t] = v;
    __syncthreads();
    for (int o = 1; o < 1024; o <<= 1) {
        int u = (t >= o) ? sm[t - o] : 0;
        __syncthreads();
        sm[t] += u;
        __syncthreads();
    }
    if (i < n) out[i] = sm[t] - v;
    if (t == 1023) bsum[blockIdx.x] = sm[1023];
}

__global__ void k_scan2(int* __restrict__ bsum, int nb, int* __restrict__ off, int n) {
    int total = 0;
    for (int i = 0; i < nb; i++) { int v = bsum[i]; bsum[i] = total; total += v; }
    off[n] = total;
}

__global__ void __launch_bounds__(1024) k_scan3(int* __restrict__ off,
                                                const int* __restrict__ bsum,
                                                int* __restrict__ cur, int n) {
    int i = blockIdx.x * 1024 + threadIdx.x;
    if (i < n) {
        int v = off[i] + bsum[blockIdx.x];
        off[i] = v;
        cur[i] = v;
    }
}

__global__ void k_escatter(const int* __restrict__ s, const int* __restrict__ d,
                           const unsigned char* __restrict__ val, int* __restrict__ cur,
                           int* __restrict__ csr, int E) {
    int e = blockIdx.x * blockDim.x + threadIdx.x;
    if (e >= E) return;
    if (val && !val[e]) return;
    int p = atomicAdd(&cur[d[e]], 1);
    csr[p] = s[e];
}

// Fused GAT aggregation: one warp per dst node, online softmax + feature
// accumulate + bias/ELU epilogue. lane owns 8 channels; head = lane/8.
__global__ void k_gather(const float* __restrict__ h1, const int* __restrict__ off,
                         const int* __restrict__ csr,
                         const float* __restrict__ as_, const float* __restrict__ ad_,
                         const float* __restrict__ bias, float* __restrict__ out, int n) {
    int wp = (blockIdx.x * blockDim.x + threadIdx.x) >> 5;
    if (wp >= n) return;
    int lane = threadIdx.x & 31;
    int head = lane >> 3;
    int d = wp;
    float adh = ad_[d * 4 + head];
    float mx = lrelu(as_[d * 4 + head] + adh);
    float den = 1.f;
    float acc[8];
    {
        const float4* p = (const float4*)(h1 + (size_t)d * FHC + lane * 8);
        float4 x0 = p[0], x1 = p[1];
        acc[0] = x0.x; acc[1] = x0.y; acc[2] = x0.z; acc[3] = x0.w;
        acc[4] = x1.x; acc[5] = x1.y; acc[6] = x1.z; acc[7] = x1.w;
    }
    int e1 = off[d + 1];
    for (int e = off[d]; e < e1; e++) {
        int s = csr[e];
        float l = lrelu(as_[s * 4 + head] + adh);
        float nm = fmaxf(mx, l);
        float scl = expf(mx - nm);
        float w = expf(l - nm);
        den = den * scl + w;
        mx = nm;
        const float4* p = (const float4*)(h1 + (size_t)s * FHC + lane * 8);
        float4 x0 = p[0], x1 = p[1];
        acc[0] = acc[0] * scl + w * x0.x;
        acc[1] = acc[1] * scl + w * x0.y;
        acc[2] = acc[2] * scl + w * x0.z;
        acc[3] = acc[3] * scl + w * x0.w;
        acc[4] = acc[4] * scl + w * x1.x;
        acc[5] = acc[5] * scl + w * x1.y;
        acc[6] = acc[6] * scl + w * x1.z;
        acc[7] = acc[7] * scl + w * x1.w;
    }
    float inv = 1.f / (den + 1e-16f);
    int cb = lane * 8;
    float4 o0, o1;
    float v;
    v = acc[0] * inv + bias[cb + 0]; o0.x = v > 0.f ? v : expm1f(v);
    v = acc[1] * inv + bias[cb + 1]; o0.y = v > 0.f ? v : expm1f(v);
    v = acc[2] * inv + bias[cb + 2]; o0.z = v > 0.f ? v : expm1f(v);
    v = acc[3] * inv + bias[cb + 3]; o0.w = v > 0.f ? v : expm1f(v);
    v = acc[4] * inv + bias[cb + 4]; o1.x = v > 0.f ? v : expm1f(v);
    v = acc[5] * inv + bias[cb + 5]; o1.y = v > 0.f ? v : expm1f(v);
    v = acc[6] * inv + bias[cb + 6]; o1.z = v > 0.f ? v : expm1f(v);
    v = acc[7] * inv + bias[cb + 7]; o1.w = v > 0.f ? v : expm1f(v);
    float4* po = (float4*)(out + (size_t)d * FHC + cb);
    po[0] = o0; po[1] = o1;
}

// one warp per node: normalized score = <h, w> / (||w|| + eps)
__global__ void k_score(const float* __restrict__ h, const float* __restrict__ w,
                        float* __restrict__ sc, int m) {
    int wp = (blockIdx.x * blockDim.x + threadIdx.x) >> 5;
    if (wp >= m) return;
    int lane = threadIdx.x & 31;
    const float* r = h + (size_t)wp * FHC;
    float s = 0.f, n2 = 0.f;
    for (int c = lane; c < FHC; c += 32) {
        float ww = w[c];
        s = fmaf(r[c], ww, s);
        n2 = fmaf(ww, ww, n2);
    }
    for (int o = 16; o; o >>= 1) {
        s += __shfl_xor_sync(0xffffffffu, s, o);
        n2 += __shfl_xor_sync(0xffffffffu, n2, o);
    }
    if (!lane) sc[wp] = s / (sqrtf(n2) + 1e-16f);
}

// exact top-k per graph via tie-broken rank counting (order-invariant compact)
__global__ void __launch_bounds__(1024) k_topk(const float* __restrict__ score, int n_in,
                                               int k, int* __restrict__ perm,
                                               float* __restrict__ tanhv,
                                               int* __restrict__ newid) {
    __shared__ float sv[2048];
    __shared__ int sc[1024];
    int b = blockIdx.x, t = threadIdx.x;
    const float* s = score + b * n_in;
    for (int i = t; i < n_in; i += 1024) sv[i] = s[i];
    __syncthreads();
    int per = n_in >> 10;  // 1 or 2
    int cnt[2] = {0, 0};
    float mine[2] = {0.f, 0.f};
    int mi[2] = {0, 0};
    for (int q = 0; q < 2; q++)
        if (q < per) { mi[q] = t * per + q; mine[q] = sv[mi[q]]; }
    for (int j = 0; j < n_in; j++) {
        float x = sv[j];
        for (int q = 0; q < 2; q++)
            if (q < per)
                cnt[q] += (x > mine[q]) || (x == mine[q] && j < mi[q]);
    }
    int keep[2] = {0, 0};
    int local = 0;
    for (int q = 0; q < 2; q++)
        if (q < per) { keep[q] = (cnt[q] < k); local += keep[q]; }
    sc[t] = local;
    __syncthreads();
    for (int o = 1; o < 1024; o <<= 1) {
        int u = (t >= o) ? sc[t - o] : 0;
        __syncthreads();
        sc[t] += u;
        __syncthreads();
    }
    int pos = sc[t] - local;
    for (int q = 0; q < 2; q++) {
        if (q >= per) break;
        int oldl = mi[q];
        int old = b * n_in + oldl;
        if (keep[q]) {
            int np = b * k + pos;
            perm[np] = old;
            tanhv[np] = tanhf(mine[q]);
            newid[old] = np;
            pos++;
        } else {
            newid[old] = -1;
        }
    }
}

__global__ void k_poolfeat(const float* __restrict__ h, const int* __restrict__ pm,
                           const float* __restrict__ th, float* __restrict__ hp, int m) {
    int i = blockIdx.x * blockDim.x + threadIdx.x;
    if (i < m * FHC) {
        int nd = i >> 8, c = i & 255;
        hp[i] = h[(size_t)pm[nd] * FHC + c] * th[nd];
    }
}

__global__ void k_remap(const int* __restrict__ si, const int* __restrict__ di,
                        const int* __restrict__ nid, int* __restrict__ so,
                        int* __restrict__ dq, unsigned char* __restrict__ vo, int E) {
    int e = blockIdx.x * blockDim.x + threadIdx.x;
    if (e >= E) return;
    int ns = nid[si[e]], nd = nid[di[e]];
    bool v = (ns >= 0) && (nd >= 0);
    so[e] = v ? ns : 0;
    dq[e] = v ? nd : 0;
    vo[e] = v ? 1 : 0;
}

__global__ void k_gate(const float* __restrict__ hp, const float* __restrict__ gw,
                       const float* __restrict__ gb, float* __restrict__ gt, int m) {
    int wp = (blockIdx.x * blockDim.x + threadIdx.x) >> 5;
    if (wp >= m) return;
    int lane = threadIdx.x & 31;
    const float* r = hp + (size_t)wp * FHC;
    float s = 0.f;
    for (int c = lane; c < FHC; c += 32) s = fmaf(r[c], gw[c], s);
    for (int o = 16; o; o >>= 1) s += __shfl_xor_sync(0xffffffffu, s, o);
    if (!lane) gt[wp] = s + gb[0];
}

// per-graph gate softmax stats: one warp per graph -> (max, 1/sum)
__global__ void __launch_bounds__(1024) k_gmax(const float* __restrict__ gt,
                                               float* __restrict__ gmi, int npg) {
    int w = threadIdx.x >> 5, lane = threadIdx.x & 31;
    const float* g = gt + w * npg;
    float mx = -1e30f;
    for (int i = lane; i < npg; i += 32) mx = fmaxf(mx, g[i]);
    for (int o = 16; o; o >>= 1) mx = fmaxf(mx, __shfl_xor_sync(0xffffffffu, mx, o));
    float s = 0.f;
    for (int i = lane; i < npg; i += 32) s += expf(g[i] - mx);
    for (int o = 16; o; o >>= 1) s += __shfl_xor_sync(0xffffffffu, s, o);
    if (!lane) { gmi[w * 2] = mx; gmi[w * 2 + 1] = 1.f / s; }
}

// weighted partial sums: grid (8, NB), accumulate into out via atomics
__global__ void k_attpool2(const float* __restrict__ hp, const float* __restrict__ gt,
                           const float* __restrict__ gmi, float* __restrict__ out,
                           int npg) {
    int b = blockIdx.y, t = threadIdx.x;
    int chunk = npg >> 3;
    int i0 = blockIdx.x * chunk;
    float mx = gmi[b * 2], inv = gmi[b * 2 + 1];
    const float* g = gt + b * npg + i0;
    const float* hb = hp + ((size_t)b * npg + i0) * FHC;
    float a = 0.f;
    for (int i = 0; i < chunk; i++)
        a = fmaf(expf(g[i] - mx), hb[(size_t)i * FHC + t], a);
    atomicAdd(&out[b * FHC + t], a * inv);
}

// ---------------- host side ----------------

extern "C" void kernel_launch(void* const* d_in, const int* in_sizes, int n_in,
                              void* d_out, int out_size) {
    const float* x        = (const float*)d_in[0];
    const void*  ei       = d_in[1];
    const float* lin0_w   = (const float*)d_in[2];
    const float* lin0_b   = (const float*)d_in[3];
    const float* gat0_W   = (const float*)d_in[4];
    const float* gat0_as  = (const float*)d_in[5];
    const float* gat0_ad  = (const float*)d_in[6];
    const float* gat0_b   = (const float*)d_in[7];
    const float* pool0_w  = (const float*)d_in[8];
    const float* gat1_W   = (const float*)d_in[9];
    const float* gat1_as  = (const float*)d_in[10];
    const float* gat1_ad  = (const float*)d_in[11];
    const float* gat1_b   = (const float*)d_in[12];
    const float* pool1_w  = (const float*)d_in[13];
    const float* gate_w   = (const float*)d_in[14];
    const float* gate_b   = (const float*)d_in[15];
    float* out = (float*)d_out;

    float *h0, *h1, *ho, *hp, *hp2, *as_, *ad_, *sc, *th, *gt, *gmi;
    int *s0, *d0, *s1, *d1, *deg, *off, *cur, *csr, *pm, *nid, *bs;
    unsigned char* v1;
    cudaGetSymbolAddress((void**)&h0, g_h0);
    cudaGetSymbolAddress((void**)&h1, g_h1);
    cudaGetSymbolAddress((void**)&ho, g_ho);
    cudaGetSymbolAddress((void**)&hp, g_hp);
    cudaGetSymbolAddress((void**)&hp2, g_hp2);
    cudaGetSymbolAddress((void**)&as_, g_as);
    cudaGetSymbolAddress((void**)&ad_, g_ad);
    cudaGetSymbolAddress((void**)&sc, g_sc);
    cudaGetSymbolAddress((void**)&th, g_th);
    cudaGetSymbolAddress((void**)&gt, g_gt);
    cudaGetSymbolAddress((void**)&gmi, g_gmi);
    cudaGetSymbolAddress((void**)&s0, g_s0);
    cudaGetSymbolAddress((void**)&d0, g_d0);
    cudaGetSymbolAddress((void**)&s1, g_s1);
    cudaGetSymbolAddress((void**)&d1, g_d1);
    cudaGetSymbolAddress((void**)&deg, g_deg);
    cudaGetSymbolAddress((void**)&off, g_off);
    cudaGetSymbolAddress((void**)&cur, g_cur);
    cudaGetSymbolAddress((void**)&csr, g_csr);
    cudaGetSymbolAddress((void**)&pm, g_pm);
    cudaGetSymbolAddress((void**)&nid, g_nid);
    cudaGetSymbolAddress((void**)&bs, g_bs);
    cudaGetSymbolAddress((void**)&v1, g_v1);

    cudaFuncSetAttribute(k_gemm_tc, cudaFuncAttributeMaxDynamicSharedMemorySize,
                         SMEM_GEMM);

    const int EB = divup(E0, 256);

    auto gat = [&](const float* fin, int n, const int* src, const int* dst,
                   const unsigned char* val, const float* W, const float* aS,
                   const float* aD, const float* bias, float* fout) {
        k_gemm_tc<<<dim3(1, n / 128), 512, SMEM_GEMM>>>(fin, W, nullptr, h1, n, 256, 256, 0);
        k_attn<<<divup(n * 4, 256), 256>>>(h1, aS, aD, as_, ad_, n);
        k_fill<<<divup(n, 256), 256>>>(deg, 0, n);
        k_edeg<<<EB, 256>>>(dst, val, deg, E0);
        k_scan1<<<n / 1024, 1024>>>(deg, off, bs, n);
        k_scan2<<<1, 1>>>(bs, n / 1024, off, n);
        k_scan3<<<n / 1024, 1024>>>(off, bs, cur, n);
        k_escatter<<<EB, 256>>>(src, dst, val, cur, csr, E0);
        k_gather<<<divup(n, 8), 256>>>(h1, off, csr, as_, ad_, bias, fout, n);
    };

    // edge dtype detection + int32 decode
    k_detect<<<1, 1>>>((const int*)ei);
    k_edges<<<EB, 256>>>(ei, s0, d0, E0);

    // zero final output (both attpool stages accumulate atomically)
    k_zerof<<<divup(NB * FHC, 256), 256>>>(out, NB * FHC);

    // lin0: h0 = relu(x @ W + b)
    k_gemm_tc<<<dim3(1, N0 / 128), 512, SMEM_GEMM>>>(x, lin0_w, lin0_b, h0, N0, 129, 256, 1);

    // GAT0 -> ho
    gat(h0, N0, s0, d0, nullptr, gat0_W, gat0_as, gat0_ad, gat0_b, ho);

    // TopK pool 0: 2048 -> 1024 per graph
    k_score<<<divup(N0, 8), 256>>>(ho, pool0_w, sc, N0);
    k_topk<<<NB, 1024>>>(sc, 2048, 1024, pm, th, nid);
    k_poolfeat<<<divup((N0 / 2) * FHC, 256), 256>>>(ho, pm, th, hp, N0 / 2);
    k_remap<<<EB, 256>>>(s0, d0, nid, s1, d1, v1, E0);

    // AttPool 0 -> out (+=)
    k_gate<<<divup(N0 / 2, 8), 256>>>(hp, gate_w, gate_b, gt, N0 / 2);
    k_gmax<<<1, 1024>>>(gt, gmi, 1024);
    k_attpool2<<<dim3(8, NB), 256>>>(hp, gt, gmi, out, 1024);

    // GAT1 on pooled graph
    gat(hp, N0 / 2, s1, d1, v1, gat1_W, gat1_as, gat1_ad, gat1_b, ho);

    // TopK pool 1: 1024 -> 512 per graph
    k_score<<<divup(N0 / 2, 8), 256>>>(ho, pool1_w, sc, N0 / 2);
    k_topk<<<NB, 1024>>>(sc, 1024, 512, pm, th, nid);
    k_poolfeat<<<divup((N0 / 4) * FHC, 256), 256>>>(ho, pm, th, hp2, N0 / 4);

    // AttPool 1 -> out (+=)
    k_gate<<<divup(N0 / 4, 8), 256>>>(hp2, gate_w, gate_b, gt, N0 / 4);
    k_gmax<<<1, 1024>>>(gt, gmi, 512);
    k_attpool2<<<dim3(8, NB), 256>>>(hp2, gt, gmi, out, 512);
}

// round 5
// speedup vs baseline: 1.6486x; 1.1094x over previous
#include <cuda_runtime.h>
#include <math.h>
#include <stdint.h>

#define N0  65536     // total nodes
#define E0  524288    // total edges
#define NB  32        // graphs
#define FHC 256       // feature width (H*C)
#define KP  160       // padded K for lin0

// ---------------- static device scratch ----------------
__device__ float g_xp[(size_t)N0 * KP];
__device__ float g_wp[KP * FHC];
__device__ float g_h0[(size_t)N0 * FHC];
__device__ float g_h1[(size_t)N0 * FHC];
__device__ float g_ho[(size_t)N0 * FHC];
__device__ float g_hp[(size_t)(N0 / 2) * FHC];
__device__ float g_hp2[(size_t)(N0 / 4) * FHC];
__device__ float g_as[N0 * 4], g_ad[N0 * 4];
__device__ float g_sc[N0];
__device__ float g_th[N0 / 2];
__device__ float g_gt[N0 / 2];
__device__ float g_gmi[NB * 2];
__device__ int g_s0[E0], g_d0[E0], g_s1[E0], g_d1[E0];
__device__ unsigned char g_v1[E0];
__device__ int g_deg[N0], g_off[N0 + 1], g_cur[N0], g_csr[E0];
__device__ int g_bs[64];
__device__ int g_pm[N0 / 2], g_nid[N0];
__device__ int g_is64;

static inline int divup(int a, int b) { return (a + b - 1) / b; }

__device__ __forceinline__ float lrelu(float z) { return z > 0.f ? z : 0.2f * z; }

// ---------------- tf32 helpers ----------------
__device__ __forceinline__ void tf32split(float x, uint32_t& hi, uint32_t& lo) {
    asm("cvt.rna.tf32.f32 %0, %1;" : "=r"(hi) : "f"(x));
    float r = x - __uint_as_float(hi);
    asm("cvt.rna.tf32.f32 %0, %1;" : "=r"(lo) : "f"(r));
}

#define MMA_TF32(d, a, b0, b1)                                                   \
    asm volatile(                                                                \
        "mma.sync.aligned.m16n8k8.row.col.f32.tf32.tf32.f32 "                    \
        "{%0,%1,%2,%3},{%4,%5,%6,%7},{%8,%9},{%0,%1,%2,%3};"                     \
        : "+f"(d[0]), "+f"(d[1]), "+f"(d[2]), "+f"(d[3])                         \
        : "r"(a[0]), "r"(a[1]), "r"(a[2]), "r"(a[3]), "r"(b0), "r"(b1))

__device__ __forceinline__ void cpa16(uint32_t dst, const void* src) {
    asm volatile("cp.async.cg.shared.global [%0], [%1], 16;" :: "r"(dst), "l"(src));
}

// ---------------- kernels ----------------

__global__ void k_detect(const int* __restrict__ w) {
    int nz = 0;
    for (int i = 1; i < 128; i += 2) nz |= (w[i] != 0);
    g_is64 = nz ? 0 : 1;
}

__global__ void k_edges(const void* __restrict__ ei, int* __restrict__ s,
                        int* __restrict__ d, int E) {
    int i = blockIdx.x * blockDim.x + threadIdx.x;
    if (i >= E) return;
    if (g_is64) {
        const long long* p = (const long long*)ei;
        s[i] = (int)p[i];
        d[i] = (int)p[E + i];
    } else {
        const int* p = (const int*)ei;
        s[i] = p[i];
        d[i] = p[E + i];
    }
}

__global__ void k_padx(const float* __restrict__ x, float* __restrict__ xp) {
    int i = blockIdx.x * blockDim.x + threadIdx.x;
    if (i >= N0 * KP) return;
    int n = i / KP, k = i - n * KP;
    xp[i] = (k < 129) ? x[(size_t)n * 129 + k] : 0.f;
}

__global__ void k_padw(const float* __restrict__ w, float* __restrict__ wp) {
    int i = blockIdx.x * blockDim.x + threadIdx.x;
    if (i >= KP * FHC) return;
    int k = i >> 8;
    wp[i] = (k < 129) ? w[i] : 0.f;
}

// Tensor-core GEMM, 3xTF32, double-buffered cp.async, raw-float smem.
// Block tile 128x256, BK=32, 512 threads; grid (1, M/128); K % 32 == 0.
// Optional fused attention epilogue (aS != null): per-head dot products
// a_s/a_d — warp wn's 64 columns are exactly head wn.
#define AP 36                         // As pitch (floats)
#define BP 260                        // Bs pitch
#define ABUF (128 * AP)               // 4608 floats
#define BBUF (32 * BP)                // 8320 floats
#define SBUF (ABUF + BBUF)            // per-stage floats
#define SMEM_GEMM (2 * SBUF * 4)      // 103424 bytes
__global__ void __launch_bounds__(512, 1)
k_gemm_tc(const float* __restrict__ A, const float* __restrict__ Bm,
          const float* __restrict__ bias, float* __restrict__ Cm,
          int M, int K, int N, int act,
          const float* __restrict__ aS, const float* __restrict__ aD,
          float* __restrict__ as_, float* __restrict__ ad_) {
    extern __shared__ float smg[];
    int t = threadIdx.x;
    int lane = t & 31, w = t >> 5;
    int g = lane >> 2, tig = lane & 3;
    int wm = w & 3, wn = w >> 2;
    int row0 = blockIdx.y * 128;
    int nk = K >> 5;

    float acc[2][8][4];
#pragma unroll
    for (int i = 0; i < 2; i++)
#pragma unroll
        for (int j = 0; j < 8; j++)
#pragma unroll
            for (int q = 0; q < 4; q++) acc[i][j][q] = 0.f;

    // tile copy: A 128x32 -> As[m][k], B 32x256 -> Bs[k][n]
    auto copy_tile = [&](int ti, int bf) {
        float* As = smg + bf * SBUF;
        float* Bs = As + ABUF;
#pragma unroll
        for (int it = 0; it < 2; it++) {
            int lin = t + 512 * it;
            int r = lin >> 3, c4 = (lin & 7) * 4;
            cpa16((uint32_t)__cvta_generic_to_shared(&As[r * AP + c4]),
                  &A[(size_t)(row0 + r) * K + ti * 32 + c4]);
        }
#pragma unroll
        for (int it = 0; it < 4; it++) {
            int lin = t + 512 * it;
            int kk = lin >> 6, c4 = (lin & 63) * 4;
            cpa16((uint32_t)__cvta_generic_to_shared(&Bs[kk * BP + c4]),
                  &Bm[(size_t)(ti * 32 + kk) * N + c4]);
        }
    };

    copy_tile(0, 0);
    asm volatile("cp.async.commit_group;");

    for (int ti = 0; ti < nk; ti++) {
        if (ti + 1 < nk) {
            copy_tile(ti + 1, (ti + 1) & 1);
            asm volatile("cp.async.commit_group;");
            asm volatile("cp.async.wait_group 1;");
        } else {
            asm volatile("cp.async.wait_group 0;");
        }
        __syncthreads();
        const float* As = smg + (ti & 1) * SBUF;
        const float* Bs = As + ABUF;
#pragma unroll
        for (int ks = 0; ks < 4; ks++) {
            int k8 = ks * 8;
            uint32_t ah[2][4], al[2][4];
#pragma unroll
            for (int mt = 0; mt < 2; mt++) {
                int bm = wm * 32 + mt * 16 + g;
                tf32split(As[bm * AP + k8 + tig],           ah[mt][0], al[mt][0]);
                tf32split(As[(bm + 8) * AP + k8 + tig],     ah[mt][1], al[mt][1]);
                tf32split(As[bm * AP + k8 + tig + 4],       ah[mt][2], al[mt][2]);
                tf32split(As[(bm + 8) * AP + k8 + tig + 4], ah[mt][3], al[mt][3]);
            }
#pragma unroll
            for (int nt = 0; nt < 8; nt++) {
                int bn = wn * 64 + nt * 8 + g;
                uint32_t b0h, b0l, b1h, b1l;
                tf32split(Bs[(k8 + tig) * BP + bn],     b0h, b0l);
                tf32split(Bs[(k8 + tig + 4) * BP + bn], b1h, b1l);
#pragma unroll
                for (int mt = 0; mt < 2; mt++) {
                    MMA_TF32(acc[mt][nt], ah[mt], b0h, b1h);
                    MMA_TF32(acc[mt][nt], ah[mt], b0l, b1l);
                    MMA_TF32(acc[mt][nt], al[mt], b0h, b1h);
                }
            }
        }
        __syncthreads();
    }

    // store C (+bias, +relu)
#pragma unroll
    for (int mt = 0; mt < 2; mt++) {
        int r = row0 + wm * 32 + mt * 16 + g;
#pragma unroll
        for (int nt = 0; nt < 8; nt++) {
            int cc = wn * 64 + nt * 8 + tig * 2;
            float b0 = bias ? bias[cc] : 0.f, b1 = bias ? bias[cc + 1] : 0.f;
            float v0 = acc[mt][nt][0] + b0, v1 = acc[mt][nt][1] + b1;
            float v2 = acc[mt][nt][2] + b0, v3 = acc[mt][nt][3] + b1;
            if (act) {
                v0 = fmaxf(v0, 0.f); v1 = fmaxf(v1, 0.f);
                v2 = fmaxf(v2, 0.f); v3 = fmaxf(v3, 0.f);
            }
            float2 p0 = {v0, v1}, p1 = {v2, v3};
            *(float2*)&Cm[(size_t)r * N + cc] = p0;
            *(float2*)&Cm[(size_t)(r + 8) * N + cc] = p1;
        }
    }

    // fused attention dot products (head = wn)
    if (aS) {
        const float* ws = aS + wn * 64;
        const float* wd = aD + wn * 64;
#pragma unroll
        for (int mt = 0; mt < 2; mt++) {
            float s0 = 0.f, d0 = 0.f, s1 = 0.f, d1 = 0.f;
#pragma unroll
            for (int nt = 0; nt < 8; nt++) {
                int c = nt * 8 + tig * 2;
                float w0 = ws[c], w1 = ws[c + 1];
                float u0 = wd[c], u1 = wd[c + 1];
                s0 = fmaf(acc[mt][nt][0], w0, fmaf(acc[mt][nt][1], w1, s0));
                d0 = fmaf(acc[mt][nt][0], u0, fmaf(acc[mt][nt][1], u1, d0));
                s1 = fmaf(acc[mt][nt][2], w0, fmaf(acc[mt][nt][3], w1, s1));
                d1 = fmaf(acc[mt][nt][2], u0, fmaf(acc[mt][nt][3], u1, d1));
            }
#pragma unroll
            for (int o = 1; o <= 2; o <<= 1) {
                s0 += __shfl_xor_sync(0xffffffffu, s0, o);
                d0 += __shfl_xor_sync(0xffffffffu, d0, o);
                s1 += __shfl_xor_sync(0xffffffffu, s1, o);
                d1 += __shfl_xor_sync(0xffffffffu, d1, o);
            }
            if (tig == 0) {
                int r = row0 + wm * 32 + mt * 16 + g;
                as_[r * 4 + wn] = s0; ad_[r * 4 + wn] = d0;
                as_[(r + 8) * 4 + wn] = s1; ad_[(r + 8) * 4 + wn] = d1;
            }
        }
    }
}

__global__ void k_fill(int* __restrict__ p, int v, int n) {
    int i = blockIdx.x * blockDim.x + threadIdx.x;
    if (i < n) p[i] = v;
}

__global__ void k_zerof(float* __restrict__ p, int n) {
    int i = blockIdx.x * blockDim.x + threadIdx.x;
    if (i < n) p[i] = 0.f;
}

__global__ void k_edeg(const int* __restrict__ d, const unsigned char* __restrict__ val,
                       int* __restrict__ deg, int E) {
    int e = blockIdx.x * blockDim.x + threadIdx.x;
    if (e >= E) return;
    if (val && !val[e]) return;
    atomicAdd(&deg[d[e]], 1);
}

__global__ void __launch_bounds__(1024) k_scan1(const int* __restrict__ in,
                                                int* __restrict__ out,
                                                int* __restrict__ bsum, int n) {
    __shared__ int sm[1024];
    int t = threadIdx.x;
    int i = blockIdx.x * 1024 + t;
    int v = (i < n) ? in[i] : 0;
    sm[t] = v;
    __syncthreads();
    for (int o = 1; o < 1024; o <<= 1) {
        int u = (t >= o) ? sm[t - o] : 0;
        __syncthreads();
        sm[t] += u;
        __syncthreads();
    }
    if (i < n) out[i] = sm[t] - v;
    if (t == 1023) bsum[blockIdx.x] = sm[1023];
}

__global__ void k_scan2(int* __restrict__ bsum, int nb, int* __restrict__ off, int n) {
    int total = 0;
    for (int i = 0; i < nb; i++) { int v = bsum[i]; bsum[i] = total; total += v; }
    off[n] = total;
}

__global__ void __launch_bounds__(1024) k_scan3(int* __restrict__ off,
                                                const int* __restrict__ bsum,
                                                int* __restrict__ cur, int n) {
    int i = blockIdx.x * 1024 + threadIdx.x;
    if (i < n) {
        int v = off[i] + bsum[blockIdx.x];
        off[i] = v;
        cur[i] = v;
    }
}

__global__ void k_escatter(const int* __restrict__ s, const int* __restrict__ d,
                           const unsigned char* __restrict__ val, int* __restrict__ cur,
                           int* __restrict__ csr, int E) {
    int e = blockIdx.x * blockDim.x + threadIdx.x;
    if (e >= E) return;
    if (val && !val[e]) return;
    int p = atomicAdd(&cur[d[e]], 1);
    csr[p] = s[e];
}

// Fused GAT aggregation + topk score: one warp per dst node, online softmax,
// bias/ELU epilogue, then score = <out_row, pw>/||pw||.
__global__ void k_gather(const float* __restrict__ h1, const int* __restrict__ off,
                         const int* __restrict__ csr,
                         const float* __restrict__ as_, const float* __restrict__ ad_,
                         const float* __restrict__ bias, const float* __restrict__ pw,
                         float* __restrict__ out, float* __restrict__ sc, int n) {
    int wp = (blockIdx.x * blockDim.x + threadIdx.x) >> 5;
    if (wp >= n) return;
    int lane = threadIdx.x & 31;
    int head = lane >> 3;
    int d = wp;
    float adh = ad_[d * 4 + head];
    float mx = lrelu(as_[d * 4 + head] + adh);
    float den = 1.f;
    float acc[8];
    {
        const float4* p = (const float4*)(h1 + (size_t)d * FHC + lane * 8);
        float4 x0 = p[0], x1 = p[1];
        acc[0] = x0.x; acc[1] = x0.y; acc[2] = x0.z; acc[3] = x0.w;
        acc[4] = x1.x; acc[5] = x1.y; acc[6] = x1.z; acc[7] = x1.w;
    }
    int e1 = off[d + 1];
    for (int e = off[d]; e < e1; e++) {
        int s = csr[e];
        float l = lrelu(as_[s * 4 + head] + adh);
        float nm = fmaxf(mx, l);
        float scl = expf(mx - nm);
        float w = expf(l - nm);
        den = den * scl + w;
        mx = nm;
        const float4* p = (const float4*)(h1 + (size_t)s * FHC + lane * 8);
        float4 x0 = p[0], x1 = p[1];
        acc[0] = acc[0] * scl + w * x0.x;
        acc[1] = acc[1] * scl + w * x0.y;
        acc[2] = acc[2] * scl + w * x0.z;
        acc[3] = acc[3] * scl + w * x0.w;
        acc[4] = acc[4] * scl + w * x1.x;
        acc[5] = acc[5] * scl + w * x1.y;
        acc[6] = acc[6] * scl + w * x1.z;
        acc[7] = acc[7] * scl + w * x1.w;
    }
    float inv = 1.f / (den + 1e-16f);
    int cb = lane * 8;
    float4 o0, o1;
    float v;
    v = acc[0] * inv + bias[cb + 0]; o0.x = v > 0.f ? v : expm1f(v);
    v = acc[1] * inv + bias[cb + 1]; o0.y = v > 0.f ? v : expm1f(v);
    v = acc[2] * inv + bias[cb + 2]; o0.z = v > 0.f ? v : expm1f(v);
    v = acc[3] * inv + bias[cb + 3]; o0.w = v > 0.f ? v : expm1f(v);
    v = acc[4] * inv + bias[cb + 4]; o1.x = v > 0.f ? v : expm1f(v);
    v = acc[5] * inv + bias[cb + 5]; o1.y = v > 0.f ? v : expm1f(v);
    v = acc[6] * inv + bias[cb + 6]; o1.z = v > 0.f ? v : expm1f(v);
    v = acc[7] * inv + bias[cb + 7]; o1.w = v > 0.f ? v : expm1f(v);
    float4* po = (float4*)(out + (size_t)d * FHC + cb);
    po[0] = o0; po[1] = o1;
    // fused pooling score
    const float4* pwp = (const float4*)(pw + cb);
    float4 w0 = pwp[0], w1 = pwp[1];
    float sp = o0.x * w0.x + o0.y * w0.y + o0.z * w0.z + o0.w * w0.w +
               o1.x * w1.x + o1.y * w1.y + o1.z * w1.z + o1.w * w1.w;
    float n2 = w0.x * w0.x + w0.y * w0.y + w0.z * w0.z + w0.w * w0.w +
               w1.x * w1.x + w1.y * w1.y + w1.z * w1.z + w1.w * w1.w;
#pragma unroll
    for (int o = 16; o; o >>= 1) {
        sp += __shfl_xor_sync(0xffffffffu, sp, o);
        n2 += __shfl_xor_sync(0xffffffffu, n2, o);
    }
    if (!lane) sc[d] = sp / (sqrtf(n2) + 1e-16f);
}

// exact top-k per graph via tie-broken rank counting (order-invariant compact)
__global__ void __launch_bounds__(1024) k_topk(const float* __restrict__ score, int n_in,
                                               int k, int* __restrict__ perm,
                                               float* __restrict__ tanhv,
                                               int* __restrict__ newid) {
    __shared__ float sv[2048];
    __shared__ int sc[1024];
    int b = blockIdx.x, t = threadIdx.x;
    const float* s = score + b * n_in;
    for (int i = t; i < n_in; i += 1024) sv[i] = s[i];
    __syncthreads();
    int per = n_in >> 10;  // 1 or 2
    int cnt[2] = {0, 0};
    float mine[2] = {0.f, 0.f};
    int mi[2] = {0, 0};
    for (int q = 0; q < 2; q++)
        if (q < per) { mi[q] = t * per + q; mine[q] = sv[mi[q]]; }
    for (int j = 0; j < n_in; j++) {
        float x = sv[j];
        for (int q = 0; q < 2; q++)
            if (q < per)
                cnt[q] += (x > mine[q]) || (x == mine[q] && j < mi[q]);
    }
    int keep[2] = {0, 0};
    int local = 0;
    for (int q = 0; q < 2; q++)
        if (q < per) { keep[q] = (cnt[q] < k); local += keep[q]; }
    sc[t] = local;
    __syncthreads();
    for (int o = 1; o < 1024; o <<= 1) {
        int u = (t >= o) ? sc[t - o] : 0;
        __syncthreads();
        sc[t] += u;
        __syncthreads();
    }
    int pos = sc[t] - local;
    for (int q = 0; q < 2; q++) {
        if (q >= per) break;
        int oldl = mi[q];
        int old = b * n_in + oldl;
        if (keep[q]) {
            int np = b * k + pos;
            perm[np] = old;
            tanhv[np] = tanhf(mine[q]);
            newid[old] = np;
            pos++;
        } else {
            newid[old] = -1;
        }
    }
}

// warp per pooled node: hp = h[perm]*tanh, fused gate = <hp_row, gate_w> + b
__global__ void k_poolfeat(const float* __restrict__ h, const int* __restrict__ pm,
                           const float* __restrict__ th, const float* __restrict__ gw,
                           const float* __restrict__ gb, float* __restrict__ hp,
                           float* __restrict__ gt, int m) {
    int wp = (blockIdx.x * blockDim.x + threadIdx.x) >> 5;
    if (wp >= m) return;
    int lane = threadIdx.x & 31;
    int srcn = pm[wp];
    float tv = th[wp];
    int cb = lane * 8;
    const float4* p = (const float4*)(h + (size_t)srcn * FHC + cb);
    float4 a = p[0], b = p[1];
    a.x *= tv; a.y *= tv; a.z *= tv; a.w *= tv;
    b.x *= tv; b.y *= tv; b.z *= tv; b.w *= tv;
    float4* po = (float4*)(hp + (size_t)wp * FHC + cb);
    po[0] = a; po[1] = b;
    const float4* g4 = (const float4*)(gw + cb);
    float4 w0 = g4[0], w1 = g4[1];
    float s = a.x * w0.x + a.y * w0.y + a.z * w0.z + a.w * w0.w +
              b.x * w1.x + b.y * w1.y + b.z * w1.z + b.w * w1.w;
#pragma unroll
    for (int o = 16; o; o >>= 1) s += __shfl_xor_sync(0xffffffffu, s, o);
    if (!lane) gt[wp] = s + gb[0];
}

__global__ void k_remap(const int* __restrict__ si, const int* __restrict__ di,
                        const int* __restrict__ nid, int* __restrict__ so,
                        int* __restrict__ dq, unsigned char* __restrict__ vo, int E) {
    int e = blockIdx.x * blockDim.x + threadIdx.x;
    if (e >= E) return;
    int ns = nid[si[e]], nd = nid[di[e]];
    bool v = (ns >= 0) && (nd >= 0);
    so[e] = v ? ns : 0;
    dq[e] = v ? nd : 0;
    vo[e] = v ? 1 : 0;
}

// per-graph gate softmax stats: one warp per graph -> (max, 1/sum)
__global__ void __launch_bounds__(1024) k_gmax(const float* __restrict__ gt,
                                               float* __restrict__ gmi, int npg) {
    int w = threadIdx.x >> 5, lane = threadIdx.x & 31;
    const float* g = gt + w * npg;
    float mx = -1e30f;
    for (int i = lane; i < npg; i += 32) mx = fmaxf(mx, g[i]);
    for (int o = 16; o; o >>= 1) mx = fmaxf(mx, __shfl_xor_sync(0xffffffffu, mx, o));
    float s = 0.f;
    for (int i = lane; i < npg; i += 32) s += expf(g[i] - mx);
    for (int o = 16; o; o >>= 1) s += __shfl_xor_sync(0xffffffffu, s, o);
    if (!lane) { gmi[w * 2] = mx; gmi[w * 2 + 1] = 1.f / s; }
}

// weighted partial sums: grid (8, NB), accumulate into out via atomics
__global__ void k_attpool2(const float* __restrict__ hp, const float* __restrict__ gt,
                           const float* __restrict__ gmi, float* __restrict__ out,
                           int npg) {
    int b = blockIdx.y, t = threadIdx.x;
    int chunk = npg >> 3;
    int i0 = blockIdx.x * chunk;
    float mx = gmi[b * 2], inv = gmi[b * 2 + 1];
    const float* g = gt + b * npg + i0;
    const float* hb = hp + ((size_t)b * npg + i0) * FHC;
    float a = 0.f;
    for (int i = 0; i < chunk; i++)
        a = fmaf(expf(g[i] - mx), hb[(size_t)i * FHC + t], a);
    atomicAdd(&out[b * FHC + t], a * inv);
}

// ---------------- host side ----------------

extern "C" void kernel_launch(void* const* d_in, const int* in_sizes, int n_in,
                              void* d_out, int out_size) {
    const float* x        = (const float*)d_in[0];
    const void*  ei       = d_in[1];
    const float* lin0_w   = (const float*)d_in[2];
    const float* lin0_b   = (const float*)d_in[3];
    const float* gat0_W   = (const float*)d_in[4];
    const float* gat0_as  = (const float*)d_in[5];
    const float* gat0_ad  = (const float*)d_in[6];
    const float* gat0_b   = (const float*)d_in[7];
    const float* pool0_w  = (const float*)d_in[8];
    const float* gat1_W   = (const float*)d_in[9];
    const float* gat1_as  = (const float*)d_in[10];
    const float* gat1_ad  = (const float*)d_in[11];
    const float* gat1_b   = (const float*)d_in[12];
    const float* pool1_w  = (const float*)d_in[13];
    const float* gate_w   = (const float*)d_in[14];
    const float* gate_b   = (const float*)d_in[15];
    float* out = (float*)d_out;

    float *xp, *wpad, *h0, *h1, *ho, *hp, *hp2, *as_, *ad_, *sc, *th, *gt, *gmi;
    int *s0, *d0, *s1, *d1, *deg, *off, *cur, *csr, *pm, *nid, *bs;
    unsigned char* v1;
    cudaGetSymbolAddress((void**)&xp, g_xp);
    cudaGetSymbolAddress((void**)&wpad, g_wp);
    cudaGetSymbolAddress((void**)&h0, g_h0);
    cudaGetSymbolAddress((void**)&h1, g_h1);
    cudaGetSymbolAddress((void**)&ho, g_ho);
    cudaGetSymbolAddress((void**)&hp, g_hp);
    cudaGetSymbolAddress((void**)&hp2, g_hp2);
    cudaGetSymbolAddress((void**)&as_, g_as);
    cudaGetSymbolAddress((void**)&ad_, g_ad);
    cudaGetSymbolAddress((void**)&sc, g_sc);
    cudaGetSymbolAddress((void**)&th, g_th);
    cudaGetSymbolAddress((void**)&gt, g_gt);
    cudaGetSymbolAddress((void**)&gmi, g_gmi);
    cudaGetSymbolAddress((void**)&s0, g_s0);
    cudaGetSymbolAddress((void**)&d0, g_d0);
    cudaGetSymbolAddress((void**)&s1, g_s1);
    cudaGetSymbolAddress((void**)&d1, g_d1);
    cudaGetSymbolAddress((void**)&deg, g_deg);
    cudaGetSymbolAddress((void**)&off, g_off);
    cudaGetSymbolAddress((void**)&cur, g_cur);
    cudaGetSymbolAddress((void**)&csr, g_csr);
    cudaGetSymbolAddress((void**)&pm, g_pm);
    cudaGetSymbolAddress((void**)&nid, g_nid);
    cudaGetSymbolAddress((void**)&bs, g_bs);
    cudaGetSymbolAddress((void**)&v1, g_v1);

    cudaFuncSetAttribute(k_gemm_tc, cudaFuncAttributeMaxDynamicSharedMemorySize,
                         SMEM_GEMM);

    const int EB = divup(E0, 256);

    auto gat = [&](const float* fin, int n, const int* src, const int* dst,
                   const unsigned char* val, const float* W, const float* aS,
                   const float* aD, const float* bias, const float* pw, float* fout) {
        k_gemm_tc<<<dim3(1, n / 128), 512, SMEM_GEMM>>>(fin, W, nullptr, h1, n, 256, 256, 0,
                                                        aS, aD, as_, ad_);
        k_fill<<<divup(n, 256), 256>>>(deg, 0, n);
        k_edeg<<<EB, 256>>>(dst, val, deg, E0);
        k_scan1<<<n / 1024, 1024>>>(deg, off, bs, n);
        k_scan2<<<1, 1>>>(bs, n / 1024, off, n);
        k_scan3<<<n / 1024, 1024>>>(off, bs, cur, n);
        k_escatter<<<EB, 256>>>(src, dst, val, cur, csr, E0);
        k_gather<<<divup(n, 8), 256>>>(h1, off, csr, as_, ad_, bias, pw, fout, sc, n);
    };

    // edge dtype detection + int32 decode; pad x and lin0_w to K=160
    k_detect<<<1, 1>>>((const int*)ei);
    k_edges<<<EB, 256>>>(ei, s0, d0, E0);
    k_padx<<<divup(N0 * KP, 256), 256>>>(x, xp);
    k_padw<<<divup(KP * FHC, 256), 256>>>(lin0_w, wpad);
    k_zerof<<<divup(NB * FHC, 256), 256>>>(out, NB * FHC);

    // lin0: h0 = relu(xp @ wp + b)
    k_gemm_tc<<<dim3(1, N0 / 128), 512, SMEM_GEMM>>>(xp, wpad, lin0_b, h0, N0, KP, 256, 1,
                                                     nullptr, nullptr, nullptr, nullptr);

    // GAT0 -> ho (+ pool0 scores)
    gat(h0, N0, s0, d0, nullptr, gat0_W, gat0_as, gat0_ad, gat0_b, pool0_w, ho);

    // TopK pool 0: 2048 -> 1024 per graph
    k_topk<<<NB, 1024>>>(sc, 2048, 1024, pm, th, nid);
    k_poolfeat<<<divup((N0 / 2) * 32, 256), 256>>>(ho, pm, th, gate_w, gate_b, hp, gt, N0 / 2);
    k_remap<<<EB, 256>>>(s0, d0, nid, s1, d1, v1, E0);

    // AttPool 0 -> out (+=)
    k_gmax<<<1, 1024>>>(gt, gmi, 1024);
    k_attpool2<<<dim3(8, NB), 256>>>(hp, gt, gmi, out, 1024);

    // GAT1 on pooled graph (+ pool1 scores)
    gat(hp, N0 / 2, s1, d1, v1, gat1_W, gat1_as, gat1_ad, gat1_b, pool1_w, ho);

    // TopK pool 1: 1024 -> 512 per graph
    k_topk<<<NB, 1024>>>(sc, 1024, 512, pm, th, nid);
    k_poolfeat<<<divup((N0 / 4) * 32, 256), 256>>>(ho, pm, th, gate_w, gate_b, hp2, gt, N0 / 4);

    // AttPool 1 -> out (+=)
    k_gmax<<<1, 1024>>>(gt, gmi, 512);
    k_attpool2<<<dim3(8, NB), 256>>>(hp2, gt, gmi, out, 512);
}

// round 6
// speedup vs baseline: 1.8026x; 1.0934x over previous
#include <cuda_runtime.h>
#include <math.h>
#include <stdint.h>

#define N0  65536     // total nodes
#define E0  524288    // total edges
#define NB  32        // graphs
#define FHC 256       // feature width (H*C)
#define KP  160       // padded K for lin0

// ---------------- static device scratch ----------------
__device__ float g_xp[(size_t)N0 * KP];
__device__ float g_wp[KP * FHC];
__device__ float g_h0[(size_t)N0 * FHC];
__device__ float g_h1[(size_t)N0 * FHC];
__device__ float g_ho[(size_t)N0 * FHC];
__device__ float g_hp[(size_t)(N0 / 2) * FHC];
__device__ float g_hp2[(size_t)(N0 / 4) * FHC];
__device__ float g_as[N0 * 4], g_ad[N0 * 4];
__device__ float g_sc[N0];
__device__ float g_th[N0 / 2];
__device__ float g_gt[N0 / 2];
__device__ float g_gmi[NB * 2];
__device__ int g_s0[E0], g_d0[E0], g_s1[E0], g_d1[E0];
__device__ unsigned char g_v1[E0];
__device__ int g_deg[N0], g_off[N0 + 1], g_cur[N0], g_csr[E0];
__device__ int g_bs[64];
__device__ int g_pm[N0 / 2], g_nid[N0];
__device__ int g_is64;

static inline int divup(int a, int b) { return (a + b - 1) / b; }

__device__ __forceinline__ float lrelu(float z) { return z > 0.f ? z : 0.2f * z; }

// ---------------- tf32 helpers ----------------
__device__ __forceinline__ void tf32split(float x, uint32_t& hi, uint32_t& lo) {
    asm("cvt.rna.tf32.f32 %0, %1;" : "=r"(hi) : "f"(x));
    float r = x - __uint_as_float(hi);
    asm("cvt.rna.tf32.f32 %0, %1;" : "=r"(lo) : "f"(r));
}

#define MMA_TF32(d, a, b0, b1)                                                   \
    asm volatile(                                                                \
        "mma.sync.aligned.m16n8k8.row.col.f32.tf32.tf32.f32 "                    \
        "{%0,%1,%2,%3},{%4,%5,%6,%7},{%8,%9},{%0,%1,%2,%3};"                     \
        : "+f"(d[0]), "+f"(d[1]), "+f"(d[2]), "+f"(d[3])                         \
        : "r"(a[0]), "r"(a[1]), "r"(a[2]), "r"(a[3]), "r"(b0), "r"(b1))

__device__ __forceinline__ void cpa16(uint32_t dst, const void* src) {
    asm volatile("cp.async.cg.shared.global [%0], [%1], 16;" :: "r"(dst), "l"(src));
}

// ---------------- kernels ----------------

__global__ void k_detect(const int* __restrict__ w) {
    int nz = 0;
    for (int i = 1; i < 128; i += 2) nz |= (w[i] != 0);
    g_is64 = nz ? 0 : 1;
}

// decode edges + count in-degrees (fused)
__global__ void k_edges_deg(const void* __restrict__ ei, int* __restrict__ s,
                            int* __restrict__ d, int* __restrict__ deg, int E) {
    int i = blockIdx.x * blockDim.x + threadIdx.x;
    if (i >= E) return;
    int sv, dv;
    if (g_is64) {
        const long long* p = (const long long*)ei;
        sv = (int)p[i];
        dv = (int)p[E + i];
    } else {
        const int* p = (const int*)ei;
        sv = p[i];
        dv = p[E + i];
    }
    s[i] = sv; d[i] = dv;
    atomicAdd(&deg[dv], 1);
}

__global__ void k_padx(const float* __restrict__ x, float* __restrict__ xp) {
    int i = blockIdx.x * blockDim.x + threadIdx.x;
    if (i >= N0 * KP) return;
    int n = i / KP, k = i - n * KP;
    xp[i] = (k < 129) ? x[(size_t)n * 129 + k] : 0.f;
}

__global__ void k_padw(const float* __restrict__ w, float* __restrict__ wp) {
    int i = blockIdx.x * blockDim.x + threadIdx.x;
    if (i >= KP * FHC) return;
    int k = i >> 8;
    wp[i] = (k < 129) ? w[i] : 0.f;
}

// Tensor-core GEMM, 3xTF32, double-buffered cp.async, raw-float smem.
// Block tile 128x256, BK=32, 512 threads; grid (1, M/128); K % 32 == 0.
// Optional fused attention epilogue (aS != null).
#define AP 36
#define BP 260
#define ABUF (128 * AP)
#define BBUF (32 * BP)
#define SBUF (ABUF + BBUF)
#define SMEM_GEMM (2 * SBUF * 4)
__global__ void __launch_bounds__(512, 1)
k_gemm_tc(const float* __restrict__ A, const float* __restrict__ Bm,
          const float* __restrict__ bias, float* __restrict__ Cm,
          int M, int K, int N, int act,
          const float* __restrict__ aS, const float* __restrict__ aD,
          float* __restrict__ as_, float* __restrict__ ad_) {
    extern __shared__ float smg[];
    int t = threadIdx.x;
    int lane = t & 31, w = t >> 5;
    int g = lane >> 2, tig = lane & 3;
    int wm = w & 3, wn = w >> 2;
    int row0 = blockIdx.y * 128;
    int nk = K >> 5;

    float acc[2][8][4];
#pragma unroll
    for (int i = 0; i < 2; i++)
#pragma unroll
        for (int j = 0; j < 8; j++)
#pragma unroll
            for (int q = 0; q < 4; q++) acc[i][j][q] = 0.f;

    auto copy_tile = [&](int ti, int bf) {
        float* As = smg + bf * SBUF;
        float* Bs = As + ABUF;
#pragma unroll
        for (int it = 0; it < 2; it++) {
            int lin = t + 512 * it;
            int r = lin >> 3, c4 = (lin & 7) * 4;
            cpa16((uint32_t)__cvta_generic_to_shared(&As[r * AP + c4]),
                  &A[(size_t)(row0 + r) * K + ti * 32 + c4]);
        }
#pragma unroll
        for (int it = 0; it < 4; it++) {
            int lin = t + 512 * it;
            int kk = lin >> 6, c4 = (lin & 63) * 4;
            cpa16((uint32_t)__cvta_generic_to_shared(&Bs[kk * BP + c4]),
                  &Bm[(size_t)(ti * 32 + kk) * N + c4]);
        }
    };

    copy_tile(0, 0);
    asm volatile("cp.async.commit_group;");

    for (int ti = 0; ti < nk; ti++) {
        if (ti + 1 < nk) {
            copy_tile(ti + 1, (ti + 1) & 1);
            asm volatile("cp.async.commit_group;");
            asm volatile("cp.async.wait_group 1;");
        } else {
            asm volatile("cp.async.wait_group 0;");
        }
        __syncthreads();
        const float* As = smg + (ti & 1) * SBUF;
        const float* Bs = As + ABUF;
#pragma unroll
        for (int ks = 0; ks < 4; ks++) {
            int k8 = ks * 8;
            uint32_t ah[2][4], al[2][4];
#pragma unroll
            for (int mt = 0; mt < 2; mt++) {
                int bm = wm * 32 + mt * 16 + g;
                tf32split(As[bm * AP + k8 + tig],           ah[mt][0], al[mt][0]);
                tf32split(As[(bm + 8) * AP + k8 + tig],     ah[mt][1], al[mt][1]);
                tf32split(As[bm * AP + k8 + tig + 4],       ah[mt][2], al[mt][2]);
                tf32split(As[(bm + 8) * AP + k8 + tig + 4], ah[mt][3], al[mt][3]);
            }
#pragma unroll
            for (int nt = 0; nt < 8; nt++) {
                int bn = wn * 64 + nt * 8 + g;
                uint32_t b0h, b0l, b1h, b1l;
                tf32split(Bs[(k8 + tig) * BP + bn],     b0h, b0l);
                tf32split(Bs[(k8 + tig + 4) * BP + bn], b1h, b1l);
#pragma unroll
                for (int mt = 0; mt < 2; mt++) {
                    MMA_TF32(acc[mt][nt], ah[mt], b0h, b1h);
                    MMA_TF32(acc[mt][nt], ah[mt], b0l, b1l);
                    MMA_TF32(acc[mt][nt], al[mt], b0h, b1h);
                }
            }
        }
        __syncthreads();
    }

#pragma unroll
    for (int mt = 0; mt < 2; mt++) {
        int r = row0 + wm * 32 + mt * 16 + g;
#pragma unroll
        for (int nt = 0; nt < 8; nt++) {
            int cc = wn * 64 + nt * 8 + tig * 2;
            float b0 = bias ? bias[cc] : 0.f, b1 = bias ? bias[cc + 1] : 0.f;
            float v0 = acc[mt][nt][0] + b0, v1 = acc[mt][nt][1] + b1;
            float v2 = acc[mt][nt][2] + b0, v3 = acc[mt][nt][3] + b1;
            if (act) {
                v0 = fmaxf(v0, 0.f); v1 = fmaxf(v1, 0.f);
                v2 = fmaxf(v2, 0.f); v3 = fmaxf(v3, 0.f);
            }
            float2 p0 = {v0, v1}, p1 = {v2, v3};
            *(float2*)&Cm[(size_t)r * N + cc] = p0;
            *(float2*)&Cm[(size_t)(r + 8) * N + cc] = p1;
        }
    }

    if (aS) {
        const float* ws = aS + wn * 64;
        const float* wd = aD + wn * 64;
#pragma unroll
        for (int mt = 0; mt < 2; mt++) {
            float s0 = 0.f, d0 = 0.f, s1 = 0.f, d1 = 0.f;
#pragma unroll
            for (int nt = 0; nt < 8; nt++) {
                int c = nt * 8 + tig * 2;
                float w0 = ws[c], w1 = ws[c + 1];
                float u0 = wd[c], u1 = wd[c + 1];
                s0 = fmaf(acc[mt][nt][0], w0, fmaf(acc[mt][nt][1], w1, s0));
                d0 = fmaf(acc[mt][nt][0], u0, fmaf(acc[mt][nt][1], u1, d0));
                s1 = fmaf(acc[mt][nt][2], w0, fmaf(acc[mt][nt][3], w1, s1));
                d1 = fmaf(acc[mt][nt][2], u0, fmaf(acc[mt][nt][3], u1, d1));
            }
#pragma unroll
            for (int o = 1; o <= 2; o <<= 1) {
                s0 += __shfl_xor_sync(0xffffffffu, s0, o);
                d0 += __shfl_xor_sync(0xffffffffu, d0, o);
                s1 += __shfl_xor_sync(0xffffffffu, s1, o);
                d1 += __shfl_xor_sync(0xffffffffu, d1, o);
            }
            if (tig == 0) {
                int r = row0 + wm * 32 + mt * 16 + g;
                as_[r * 4 + wn] = s0; ad_[r * 4 + wn] = d0;
                as_[(r + 8) * 4 + wn] = s1; ad_[(r + 8) * 4 + wn] = d1;
            }
        }
    }
}

__global__ void k_fill(int* __restrict__ p, int v, int n) {
    int i = blockIdx.x * blockDim.x + threadIdx.x;
    if (i < n) p[i] = v;
}

__global__ void k_zerof(float* __restrict__ p, int n) {
    int i = blockIdx.x * blockDim.x + threadIdx.x;
    if (i < n) p[i] = 0.f;
}

__global__ void __launch_bounds__(1024) k_scan1(const int* __restrict__ in,
                                                int* __restrict__ out,
                                                int* __restrict__ bsum, int n) {
    __shared__ int sm[1024];
    int t = threadIdx.x;
    int i = blockIdx.x * 1024 + t;
    int v = (i < n) ? in[i] : 0;
    sm[t] = v;
    __syncthreads();
    for (int o = 1; o < 1024; o <<= 1) {
        int u = (t >= o) ? sm[t - o] : 0;
        __syncthreads();
        sm[t] += u;
        __syncthreads();
    }
    if (i < n) out[i] = sm[t] - v;
    if (t == 1023) bsum[blockIdx.x] = sm[1023];
}

__global__ void k_scan2(int* __restrict__ bsum, int nb, int* __restrict__ off, int n) {
    int total = 0;
    for (int i = 0; i < nb; i++) { int v = bsum[i]; bsum[i] = total; total += v; }
    off[n] = total;
}

__global__ void __launch_bounds__(1024) k_scan3(int* __restrict__ off,
                                                const int* __restrict__ bsum,
                                                int* __restrict__ cur, int n) {
    int i = blockIdx.x * 1024 + threadIdx.x;
    if (i < n) {
        int v = off[i] + bsum[blockIdx.x];
        off[i] = v;
        cur[i] = v;
    }
}

__global__ void k_escatter(const int* __restrict__ s, const int* __restrict__ d,
                           const unsigned char* __restrict__ val, int* __restrict__ cur,
                           int* __restrict__ csr, int E) {
    int e = blockIdx.x * blockDim.x + threadIdx.x;
    if (e >= E) return;
    if (val && !val[e]) return;
    int p = atomicAdd(&cur[d[e]], 1);
    csr[p] = s[e];
}

// Fused GAT aggregation + topk score: warp per dst node, online softmax
// (2-way unrolled, pairwise exact merge), bias/ELU, fused pooling score.
__global__ void k_gather(const float* __restrict__ h1, const int* __restrict__ off,
                         const int* __restrict__ csr,
                         const float* __restrict__ as_, const float* __restrict__ ad_,
                         const float* __restrict__ bias, const float* __restrict__ pw,
                         float* __restrict__ out, float* __restrict__ sc, int n) {
    int wp = (blockIdx.x * blockDim.x + threadIdx.x) >> 5;
    if (wp >= n) return;
    int lane = threadIdx.x & 31;
    int head = lane >> 3;
    int d = wp;
    float adh = ad_[d * 4 + head];
    float mx = lrelu(as_[d * 4 + head] + adh);
    float den = 1.f;
    float acc[8];
    {
        const float4* p = (const float4*)(h1 + (size_t)d * FHC + lane * 8);
        float4 x0 = p[0], x1 = p[1];
        acc[0] = x0.x; acc[1] = x0.y; acc[2] = x0.z; acc[3] = x0.w;
        acc[4] = x1.x; acc[5] = x1.y; acc[6] = x1.z; acc[7] = x1.w;
    }
    int e = off[d], e1 = off[d + 1];
    for (; e + 1 < e1; e += 2) {
        int sa = csr[e], sb = csr[e + 1];
        float la = lrelu(as_[sa * 4 + head] + adh);
        float lb = lrelu(as_[sb * 4 + head] + adh);
        const float4* pa = (const float4*)(h1 + (size_t)sa * FHC + lane * 8);
        const float4* pb = (const float4*)(h1 + (size_t)sb * FHC + lane * 8);
        float4 a0 = pa[0], a1 = pa[1];
        float4 b0 = pb[0], b1 = pb[1];
        float nm = fmaxf(mx, fmaxf(la, lb));
        float scl = expf(mx - nm);
        float wa = expf(la - nm), wb = expf(lb - nm);
        den = den * scl + wa + wb;
        mx = nm;
        acc[0] = acc[0] * scl + wa * a0.x + wb * b0.x;
        acc[1] = acc[1] * scl + wa * a0.y + wb * b0.y;
        acc[2] = acc[2] * scl + wa * a0.z + wb * b0.z;
        acc[3] = acc[3] * scl + wa * a0.w + wb * b0.w;
        acc[4] = acc[4] * scl + wa * a1.x + wb * b1.x;
        acc[5] = acc[5] * scl + wa * a1.y + wb * b1.y;
        acc[6] = acc[6] * scl + wa * a1.z + wb * b1.z;
        acc[7] = acc[7] * scl + wa * a1.w + wb * b1.w;
    }
    if (e < e1) {
        int s = csr[e];
        float l = lrelu(as_[s * 4 + head] + adh);
        float nm = fmaxf(mx, l);
        float scl = expf(mx - nm);
        float w = expf(l - nm);
        den = den * scl + w;
        mx = nm;
        const float4* p = (const float4*)(h1 + (size_t)s * FHC + lane * 8);
        float4 x0 = p[0], x1 = p[1];
        acc[0] = acc[0] * scl + w * x0.x;
        acc[1] = acc[1] * scl + w * x0.y;
        acc[2] = acc[2] * scl + w * x0.z;
        acc[3] = acc[3] * scl + w * x0.w;
        acc[4] = acc[4] * scl + w * x1.x;
        acc[5] = acc[5] * scl + w * x1.y;
        acc[6] = acc[6] * scl + w * x1.z;
        acc[7] = acc[7] * scl + w * x1.w;
    }
    float inv = 1.f / (den + 1e-16f);
    int cb = lane * 8;
    float4 o0, o1;
    float v;
    v = acc[0] * inv + bias[cb + 0]; o0.x = v > 0.f ? v : expm1f(v);
    v = acc[1] * inv + bias[cb + 1]; o0.y = v > 0.f ? v : expm1f(v);
    v = acc[2] * inv + bias[cb + 2]; o0.z = v > 0.f ? v : expm1f(v);
    v = acc[3] * inv + bias[cb + 3]; o0.w = v > 0.f ? v : expm1f(v);
    v = acc[4] * inv + bias[cb + 4]; o1.x = v > 0.f ? v : expm1f(v);
    v = acc[5] * inv + bias[cb + 5]; o1.y = v > 0.f ? v : expm1f(v);
    v = acc[6] * inv + bias[cb + 6]; o1.z = v > 0.f ? v : expm1f(v);
    v = acc[7] * inv + bias[cb + 7]; o1.w = v > 0.f ? v : expm1f(v);
    float4* po = (float4*)(out + (size_t)d * FHC + cb);
    po[0] = o0; po[1] = o1;
    const float4* pwp = (const float4*)(pw + cb);
    float4 w0 = pwp[0], w1 = pwp[1];
    float sp = o0.x * w0.x + o0.y * w0.y + o0.z * w0.z + o0.w * w0.w +
               o1.x * w1.x + o1.y * w1.y + o1.z * w1.z + o1.w * w1.w;
    float n2 = w0.x * w0.x + w0.y * w0.y + w0.z * w0.z + w0.w * w0.w +
               w1.x * w1.x + w1.y * w1.y + w1.z * w1.z + w1.w * w1.w;
#pragma unroll
    for (int o = 16; o; o >>= 1) {
        sp += __shfl_xor_sync(0xffffffffu, sp, o);
        n2 += __shfl_xor_sync(0xffffffffu, n2, o);
    }
    if (!lane) sc[d] = sp / (sqrtf(n2) + 1e-16f);
}

// exact top-k per graph via tie-broken rank counting (order-invariant compact)
__global__ void __launch_bounds__(1024) k_topk(const float* __restrict__ score, int n_in,
                                               int k, int* __restrict__ perm,
                                               float* __restrict__ tanhv,
                                               int* __restrict__ newid) {
    __shared__ float sv[2048];
    __shared__ int sc[1024];
    int b = blockIdx.x, t = threadIdx.x;
    const float* s = score + b * n_in;
    for (int i = t; i < n_in; i += 1024) sv[i] = s[i];
    __syncthreads();
    int per = n_in >> 10;
    int cnt[2] = {0, 0};
    float mine[2] = {0.f, 0.f};
    int mi[2] = {0, 0};
    for (int q = 0; q < 2; q++)
        if (q < per) { mi[q] = t * per + q; mine[q] = sv[mi[q]]; }
    for (int j = 0; j < n_in; j++) {
        float x = sv[j];
        for (int q = 0; q < 2; q++)
            if (q < per)
                cnt[q] += (x > mine[q]) || (x == mine[q] && j < mi[q]);
    }
    int keep[2] = {0, 0};
    int local = 0;
    for (int q = 0; q < 2; q++)
        if (q < per) { keep[q] = (cnt[q] < k); local += keep[q]; }
    sc[t] = local;
    __syncthreads();
    for (int o = 1; o < 1024; o <<= 1) {
        int u = (t >= o) ? sc[t - o] : 0;
        __syncthreads();
        sc[t] += u;
        __syncthreads();
    }
    int pos = sc[t] - local;
    for (int q = 0; q < 2; q++) {
        if (q >= per) break;
        int oldl = mi[q];
        int old = b * n_in + oldl;
        if (keep[q]) {
            int np = b * k + pos;
            perm[np] = old;
            tanhv[np] = tanhf(mine[q]);
            newid[old] = np;
            pos++;
        } else {
            newid[old] = -1;
        }
    }
}

// warp per pooled node: hp = h[perm]*tanh, fused gate = <hp_row, gate_w> + b
__global__ void k_poolfeat(const float* __restrict__ h, const int* __restrict__ pm,
                           const float* __restrict__ th, const float* __restrict__ gw,
                           const float* __restrict__ gb, float* __restrict__ hp,
                           float* __restrict__ gt, int m) {
    int wp = (blockIdx.x * blockDim.x + threadIdx.x) >> 5;
    if (wp >= m) return;
    int lane = threadIdx.x & 31;
    int srcn = pm[wp];
    float tv = th[wp];
    int cb = lane * 8;
    const float4* p = (const float4*)(h + (size_t)srcn * FHC + cb);
    float4 a = p[0], b = p[1];
    a.x *= tv; a.y *= tv; a.z *= tv; a.w *= tv;
    b.x *= tv; b.y *= tv; b.z *= tv; b.w *= tv;
    float4* po = (float4*)(hp + (size_t)wp * FHC + cb);
    po[0] = a; po[1] = b;
    const float4* g4 = (const float4*)(gw + cb);
    float4 w0 = g4[0], w1 = g4[1];
    float s = a.x * w0.x + a.y * w0.y + a.z * w0.z + a.w * w0.w +
              b.x * w1.x + b.y * w1.y + b.z * w1.z + b.w * w1.w;
#pragma unroll
    for (int o = 16; o; o >>= 1) s += __shfl_xor_sync(0xffffffffu, s, o);
    if (!lane) gt[wp] = s + gb[0];
}

// remap edges to pooled ids + count pooled in-degrees (fused)
__global__ void k_remap_deg(const int* __restrict__ si, const int* __restrict__ di,
                            const int* __restrict__ nid, int* __restrict__ so,
                            int* __restrict__ dq, unsigned char* __restrict__ vo,
                            int* __restrict__ deg, int E) {
    int e = blockIdx.x * blockDim.x + threadIdx.x;
    if (e >= E) return;
    int ns = nid[si[e]], nd = nid[di[e]];
    bool v = (ns >= 0) && (nd >= 0);
    so[e] = v ? ns : 0;
    dq[e] = v ? nd : 0;
    vo[e] = v ? 1 : 0;
    if (v) atomicAdd(&deg[nd], 1);
}

// per-graph gate softmax stats: one warp per graph -> (max, 1/sum)
__global__ void __launch_bounds__(1024) k_gmax(const float* __restrict__ gt,
                                               float* __restrict__ gmi, int npg) {
    int w = threadIdx.x >> 5, lane = threadIdx.x & 31;
    const float* g = gt + w * npg;
    float mx = -1e30f;
    for (int i = lane; i < npg; i += 32) mx = fmaxf(mx, g[i]);
    for (int o = 16; o; o >>= 1) mx = fmaxf(mx, __shfl_xor_sync(0xffffffffu, mx, o));
    float s = 0.f;
    for (int i = lane; i < npg; i += 32) s += expf(g[i] - mx);
    for (int o = 16; o; o >>= 1) s += __shfl_xor_sync(0xffffffffu, s, o);
    if (!lane) { gmi[w * 2] = mx; gmi[w * 2 + 1] = 1.f / s; }
}

// weighted partial sums: grid (8, NB), accumulate into out via atomics
__global__ void k_attpool2(const float* __restrict__ hp, const float* __restrict__ gt,
                           const float* __restrict__ gmi, float* __restrict__ out,
                           int npg) {
    int b = blockIdx.y, t = threadIdx.x;
    int chunk = npg >> 3;
    int i0 = blockIdx.x * chunk;
    float mx = gmi[b * 2], inv = gmi[b * 2 + 1];
    const float* g = gt + b * npg + i0;
    const float* hb = hp + ((size_t)b * npg + i0) * FHC;
    float a = 0.f;
    for (int i = 0; i < chunk; i++)
        a = fmaf(expf(g[i] - mx), hb[(size_t)i * FHC + t], a);
    atomicAdd(&out[b * FHC + t], a * inv);
}

// ---------------- host side ----------------

extern "C" void kernel_launch(void* const* d_in, const int* in_sizes, int n_in,
                              void* d_out, int out_size) {
    const float* x        = (const float*)d_in[0];
    const void*  ei       = d_in[1];
    const float* lin0_w   = (const float*)d_in[2];
    const float* lin0_b   = (const float*)d_in[3];
    const float* gat0_W   = (const float*)d_in[4];
    const float* gat0_as  = (const float*)d_in[5];
    const float* gat0_ad  = (const float*)d_in[6];
    const float* gat0_b   = (const float*)d_in[7];
    const float* pool0_w  = (const float*)d_in[8];
    const float* gat1_W   = (const float*)d_in[9];
    const float* gat1_as  = (const float*)d_in[10];
    const float* gat1_ad  = (const float*)d_in[11];
    const float* gat1_b   = (const float*)d_in[12];
    const float* pool1_w  = (const float*)d_in[13];
    const float* gate_w   = (const float*)d_in[14];
    const float* gate_b   = (const float*)d_in[15];
    float* out = (float*)d_out;

    float *xp, *wpad, *h0, *h1, *ho, *hp, *hp2, *as_, *ad_, *sc, *th, *gt, *gmi;
    int *s0, *d0, *s1, *d1, *deg, *off, *cur, *csr, *pm, *nid, *bs;
    unsigned char* v1;
    cudaGetSymbolAddress((void**)&xp, g_xp);
    cudaGetSymbolAddress((void**)&wpad, g_wp);
    cudaGetSymbolAddress((void**)&h0, g_h0);
    cudaGetSymbolAddress((void**)&h1, g_h1);
    cudaGetSymbolAddress((void**)&ho, g_ho);
    cudaGetSymbolAddress((void**)&hp, g_hp);
    cudaGetSymbolAddress((void**)&hp2, g_hp2);
    cudaGetSymbolAddress((void**)&as_, g_as);
    cudaGetSymbolAddress((void**)&ad_, g_ad);
    cudaGetSymbolAddress((void**)&sc, g_sc);
    cudaGetSymbolAddress((void**)&th, g_th);
    cudaGetSymbolAddress((void**)&gt, g_gt);
    cudaGetSymbolAddress((void**)&gmi, g_gmi);
    cudaGetSymbolAddress((void**)&s0, g_s0);
    cudaGetSymbolAddress((void**)&d0, g_d0);
    cudaGetSymbolAddress((void**)&s1, g_s1);
    cudaGetSymbolAddress((void**)&d1, g_d1);
    cudaGetSymbolAddress((void**)&deg, g_deg);
    cudaGetSymbolAddress((void**)&off, g_off);
    cudaGetSymbolAddress((void**)&cur, g_cur);
    cudaGetSymbolAddress((void**)&csr, g_csr);
    cudaGetSymbolAddress((void**)&pm, g_pm);
    cudaGetSymbolAddress((void**)&nid, g_nid);
    cudaGetSymbolAddress((void**)&bs, g_bs);
    cudaGetSymbolAddress((void**)&v1, g_v1);

    cudaFuncSetAttribute(k_gemm_tc, cudaFuncAttributeMaxDynamicSharedMemorySize,
                         SMEM_GEMM);

    // lazy-init side stream + events (host resources, reused every call;
    // identical work each call, so deterministic)
    static cudaStream_t s2 = nullptr;
    static cudaEvent_t evF0, evS0, evT0, evP0, evS1, evA0;
    if (!s2) {
        cudaStreamCreateWithFlags(&s2, cudaStreamNonBlocking);
        cudaEventCreateWithFlags(&evF0, cudaEventDisableTiming);
        cudaEventCreateWithFlags(&evS0, cudaEventDisableTiming);
        cudaEventCreateWithFlags(&evT0, cudaEventDisableTiming);
        cudaEventCreateWithFlags(&evP0, cudaEventDisableTiming);
        cudaEventCreateWithFlags(&evS1, cudaEventDisableTiming);
        cudaEventCreateWithFlags(&evA0, cudaEventDisableTiming);
    }

    const int EB = divup(E0, 256);

    // ---- main: output zero + pads (roots of the capture graph) ----
    k_zerof<<<divup(NB * FHC, 256), 256>>>(out, NB * FHC);
    k_padx<<<divup(N0 * KP, 256), 256>>>(x, xp);
    k_padw<<<divup(KP * FHC, 256), 256>>>(lin0_w, wpad);

    // fork side stream: edge decode + CSR build for GAT0
    cudaEventRecord(evF0, 0);
    cudaStreamWaitEvent(s2, evF0, 0);
    k_detect<<<1, 1, 0, s2>>>((const int*)ei);
    k_fill<<<divup(N0, 256), 256, 0, s2>>>(deg, 0, N0);
    k_edges_deg<<<EB, 256, 0, s2>>>(ei, s0, d0, deg, E0);
    k_scan1<<<N0 / 1024, 1024, 0, s2>>>(deg, off, bs, N0);
    k_scan2<<<1, 1, 0, s2>>>(bs, N0 / 1024, off, N0);
    k_scan3<<<N0 / 1024, 1024, 0, s2>>>(off, bs, cur, N0);
    k_escatter<<<EB, 256, 0, s2>>>(s0, d0, nullptr, cur, csr, E0);
    cudaEventRecord(evS0, s2);

    // ---- main: lin0 + GAT0 GEMM (overlaps CSR build) ----
    k_gemm_tc<<<dim3(1, N0 / 128), 512, SMEM_GEMM>>>(xp, wpad, lin0_b, h0, N0, KP, 256, 1,
                                                     nullptr, nullptr, nullptr, nullptr);
    k_gemm_tc<<<dim3(1, N0 / 128), 512, SMEM_GEMM>>>(h0, gat0_W, nullptr, h1, N0, 256, 256, 0,
                                                     gat0_as, gat0_ad, as_, ad_);

    // join: gather0 needs CSR + h1/as_/ad_
    cudaStreamWaitEvent(0, evS0, 0);
    k_gather<<<divup(N0, 8), 256>>>(h1, off, csr, as_, ad_, gat0_b, pool0_w, ho, sc, N0);

    // TopK pool 0
    k_topk<<<NB, 1024>>>(sc, 2048, 1024, pm, th, nid);
    cudaEventRecord(evT0, 0);
    k_poolfeat<<<divup((N0 / 2) * 32, 256), 256>>>(ho, pm, th, gate_w, gate_b, hp, gt, N0 / 2);
    cudaEventRecord(evP0, 0);

    // side: CSR build for GAT1 (needs nid), then attpool0 (needs hp/gt)
    cudaStreamWaitEvent(s2, evT0, 0);
    k_fill<<<divup(N0 / 2, 256), 256, 0, s2>>>(deg, 0, N0 / 2);
    k_remap_deg<<<EB, 256, 0, s2>>>(s0, d0, nid, s1, d1, v1, deg, E0);
    k_scan1<<<(N0 / 2) / 1024, 1024, 0, s2>>>(deg, off, bs, N0 / 2);
    k_scan2<<<1, 1, 0, s2>>>(bs, (N0 / 2) / 1024, off, N0 / 2);
    k_scan3<<<(N0 / 2) / 1024, 1024, 0, s2>>>(off, bs, cur, N0 / 2);
    k_escatter<<<EB, 256, 0, s2>>>(s1, d1, v1, cur, csr, E0);
    cudaEventRecord(evS1, s2);
    cudaStreamWaitEvent(s2, evP0, 0);
    k_gmax<<<1, 1024, 0, s2>>>(gt, gmi, 1024);
    k_attpool2<<<dim3(8, NB), 256, 0, s2>>>(hp, gt, gmi, out, 1024);
    cudaEventRecord(evA0, s2);

    // ---- main: GAT1 GEMM (overlaps side CSR + attpool0) ----
    k_gemm_tc<<<dim3(1, (N0 / 2) / 128), 512, SMEM_GEMM>>>(hp, gat1_W, nullptr, h1,
                                                           N0 / 2, 256, 256, 0,
                                                           gat1_as, gat1_ad, as_, ad_);
    cudaStreamWaitEvent(0, evS1, 0);
    k_gather<<<divup(N0 / 2, 8), 256>>>(h1, off, csr, as_, ad_, gat1_b, pool1_w, ho, sc, N0 / 2);

    // TopK pool 1
    k_topk<<<NB, 1024>>>(sc, 1024, 512, pm, th, nid);
    k_poolfeat<<<divup((N0 / 4) * 32, 256), 256>>>(ho, pm, th, gate_w, gate_b, hp2, gt, N0 / 4);

    // AttPool 1 -> out (+=); also join attpool0 branch before final adds
    cudaStreamWaitEvent(0, evA0, 0);
    k_gmax<<<1, 1024>>>(gt, gmi, 512);
    k_attpool2<<<dim3(8, NB), 256>>>(hp2, gt, gmi, out, 512);
}

// round 8
// speedup vs baseline: 1.9123x; 1.0608x over previous
#include <cuda_runtime.h>
#include <math.h>
#include <stdint.h>

#define N0  65536     // total nodes
#define E0  524288    // total edges
#define NB  32        // graphs
#define FHC 256       // feature width (H*C)

// ---------------- static device scratch ----------------
__device__ float g_h0[(size_t)N0 * FHC];
__device__ float g_h1[(size_t)N0 * FHC];
__device__ float g_ho[(size_t)N0 * FHC];
__device__ float g_hp[(size_t)(N0 / 2) * FHC];
__device__ float g_hp2[(size_t)(N0 / 4) * FHC];
__device__ float g_as[N0 * 4], g_ad[N0 * 4];
__device__ float g_sc[N0];
__device__ float g_th[N0 / 2];
__device__ float g_gt[N0 / 2];
__device__ float g_gmi[NB * 2];
__device__ int g_s0[E0], g_d0[E0], g_s1[E0], g_d1[E0];
__device__ unsigned char g_v1[E0];
__device__ int g_deg[N0], g_off[N0 + 1], g_cur[N0], g_csr[E0];
__device__ int g_bs[64];
__device__ int g_pm[N0 / 2], g_nid[N0];
__device__ int g_is64;

static inline int divup(int a, int b) { return (a + b - 1) / b; }

__device__ __forceinline__ float lrelu(float z) { return z > 0.f ? z : 0.2f * z; }

// ---------------- tf32 helpers ----------------
__device__ __forceinline__ void tf32split(float x, uint32_t& hi, uint32_t& lo) {
    asm("cvt.rna.tf32.f32 %0, %1;" : "=r"(hi) : "f"(x));
    float r = x - __uint_as_float(hi);
    asm("cvt.rna.tf32.f32 %0, %1;" : "=r"(lo) : "f"(r));
}

#define MMA_TF32(d, a, b0, b1)                                                   \
    asm volatile(                                                                \
        "mma.sync.aligned.m16n8k8.row.col.f32.tf32.tf32.f32 "                    \
        "{%0,%1,%2,%3},{%4,%5,%6,%7},{%8,%9},{%0,%1,%2,%3};"                     \
        : "+f"(d[0]), "+f"(d[1]), "+f"(d[2]), "+f"(d[3])                         \
        : "r"(a[0]), "r"(a[1]), "r"(a[2]), "r"(a[3]), "r"(b0), "r"(b1))

__device__ __forceinline__ void cpa16(uint32_t dst, const void* src) {
    asm volatile("cp.async.cg.shared.global [%0], [%1], 16;" :: "r"(dst), "l"(src));
}
__device__ __forceinline__ void cpa4(uint32_t dst, const void* src) {
    asm volatile("cp.async.ca.shared.global [%0], [%1], 4;" :: "r"(dst), "l"(src));
}

// ---------------- kernels ----------------

__global__ void k_detect(const int* __restrict__ w) {
    int nz = 0;
    for (int i = 1; i < 128; i += 2) nz |= (w[i] != 0);
    g_is64 = nz ? 0 : 1;
}

// decode edges + count in-degrees (fused)
__global__ void k_edges_deg(const void* __restrict__ ei, int* __restrict__ s,
                            int* __restrict__ d, int* __restrict__ deg, int E) {
    int i = blockIdx.x * blockDim.x + threadIdx.x;
    if (i >= E) return;
    int sv, dv;
    if (g_is64) {
        const long long* p = (const long long*)ei;
        sv = (int)p[i];
        dv = (int)p[E + i];
    } else {
        const int* p = (const int*)ei;
        sv = p[i];
        dv = p[E + i];
    }
    s[i] = sv; d[i] = dv;
    atomicAdd(&deg[dv], 1);
}

// Tensor-core GEMM, 3xTF32, double-buffered cp.async.
// Block tile 128x256, BK=32, 512 threads; grid (1, M/128); K % 32 == 0.
// Kld = leading dim of A (may exceed K; if Kld%4 != 0, scalar cp.async).
// Optional rank-1 update (a1col/b1row) folded into the epilogue, and
// optional fused attention epilogue (aS != null).
#define AP 36
#define BP 260
#define ABUF (128 * AP)
#define BBUF (32 * BP)
#define SBUF (ABUF + BBUF)
#define SMEM_GEMM (2 * SBUF * 4)
__global__ void __launch_bounds__(512, 1)
k_gemm_tc(const float* __restrict__ A, const float* __restrict__ Bm,
          const float* __restrict__ bias, float* __restrict__ Cm,
          int M, int K, int N, int act, int Kld,
          const float* __restrict__ a1col, const float* __restrict__ b1row,
          const float* __restrict__ aS, const float* __restrict__ aD,
          float* __restrict__ as_, float* __restrict__ ad_) {
    extern __shared__ float smg[];
    int t = threadIdx.x;
    int lane = t & 31, w = t >> 5;
    int g = lane >> 2, tig = lane & 3;
    int wm = w & 3, wn = w >> 2;
    int row0 = blockIdx.y * 128;
    int nk = K >> 5;
    bool al16 = (Kld & 3) == 0;

    float acc[2][8][4];
#pragma unroll
    for (int i = 0; i < 2; i++)
#pragma unroll
        for (int j = 0; j < 8; j++)
#pragma unroll
            for (int q = 0; q < 4; q++) acc[i][j][q] = 0.f;

    auto copy_tile = [&](int ti, int bf) {
        float* As = smg + bf * SBUF;
        float* Bs = As + ABUF;
#pragma unroll
        for (int it = 0; it < 2; it++) {
            int lin = t + 512 * it;
            int r = lin >> 3, c4 = (lin & 7) * 4;
            const float* src = &A[(size_t)(row0 + r) * Kld + ti * 32 + c4];
            uint32_t dst = (uint32_t)__cvta_generic_to_shared(&As[r * AP + c4]);
            if (al16) {
                cpa16(dst, src);
            } else {
#pragma unroll
                for (int j = 0; j < 4; j++) cpa4(dst + j * 4, src + j);
            }
        }
#pragma unroll
        for (int it = 0; it < 4; it++) {
            int lin = t + 512 * it;
            int kk = lin >> 6, c4 = (lin & 63) * 4;
            cpa16((uint32_t)__cvta_generic_to_shared(&Bs[kk * BP + c4]),
                  &Bm[(size_t)(ti * 32 + kk) * N + c4]);
        }
    };

    copy_tile(0, 0);
    asm volatile("cp.async.commit_group;");

    for (int ti = 0; ti < nk; ti++) {
        if (ti + 1 < nk) {
            copy_tile(ti + 1, (ti + 1) & 1);
            asm volatile("cp.async.commit_group;");
            asm volatile("cp.async.wait_group 1;");
        } else {
            asm volatile("cp.async.wait_group 0;");
        }
        __syncthreads();
        const float* As = smg + (ti & 1) * SBUF;
        const float* Bs = As + ABUF;
#pragma unroll
        for (int ks = 0; ks < 4; ks++) {
            int k8 = ks * 8;
            uint32_t ah[2][4], al[2][4];
#pragma unroll
            for (int mt = 0; mt < 2; mt++) {
                int bm = wm * 32 + mt * 16 + g;
                tf32split(As[bm * AP + k8 + tig],           ah[mt][0], al[mt][0]);
                tf32split(As[(bm + 8) * AP + k8 + tig],     ah[mt][1], al[mt][1]);
                tf32split(As[bm * AP + k8 + tig + 4],       ah[mt][2], al[mt][2]);
                tf32split(As[(bm + 8) * AP + k8 + tig + 4], ah[mt][3], al[mt][3]);
            }
#pragma unroll
            for (int nt = 0; nt < 8; nt++) {
                int bn = wn * 64 + nt * 8 + g;
                uint32_t b0h, b0l, b1h, b1l;
                tf32split(Bs[(k8 + tig) * BP + bn],     b0h, b0l);
                tf32split(Bs[(k8 + tig + 4) * BP + bn], b1h, b1l);
#pragma unroll
                for (int mt = 0; mt < 2; mt++) {
                    MMA_TF32(acc[mt][nt], ah[mt], b0h, b1h);
                    MMA_TF32(acc[mt][nt], ah[mt], b0l, b1l);
                    MMA_TF32(acc[mt][nt], al[mt], b0h, b1h);
                }
            }
        }
        __syncthreads();
    }

#pragma unroll
    for (int mt = 0; mt < 2; mt++) {
        int r = row0 + wm * 32 + mt * 16 + g;
        float ar0 = a1col ? a1col[(size_t)r * Kld] : 0.f;
        float ar8 = a1col ? a1col[(size_t)(r + 8) * Kld] : 0.f;
#pragma unroll
        for (int nt = 0; nt < 8; nt++) {
            int cc = wn * 64 + nt * 8 + tig * 2;
            float bb0 = a1col ? b1row[cc] : 0.f, bb1 = a1col ? b1row[cc + 1] : 0.f;
            float b0 = bias ? bias[cc] : 0.f, b1 = bias ? bias[cc + 1] : 0.f;
            float v0 = acc[mt][nt][0] + ar0 * bb0 + b0;
            float v1 = acc[mt][nt][1] + ar0 * bb1 + b1;
            float v2 = acc[mt][nt][2] + ar8 * bb0 + b0;
            float v3 = acc[mt][nt][3] + ar8 * bb1 + b1;
            if (act) {
                v0 = fmaxf(v0, 0.f); v1 = fmaxf(v1, 0.f);
                v2 = fmaxf(v2, 0.f); v3 = fmaxf(v3, 0.f);
            }
            float2 p0 = {v0, v1}, p1 = {v2, v3};
            *(float2*)&Cm[(size_t)r * N + cc] = p0;
            *(float2*)&Cm[(size_t)(r + 8) * N + cc] = p1;
        }
    }

    if (aS) {
        const float* ws = aS + wn * 64;
        const float* wd = aD + wn * 64;
#pragma unroll
        for (int mt = 0; mt < 2; mt++) {
            float s0 = 0.f, d0 = 0.f, s1 = 0.f, d1 = 0.f;
#pragma unroll
            for (int nt = 0; nt < 8; nt++) {
                int c = nt * 8 + tig * 2;
                float w0 = ws[c], w1 = ws[c + 1];
                float u0 = wd[c], u1 = wd[c + 1];
                s0 = fmaf(acc[mt][nt][0], w0, fmaf(acc[mt][nt][1], w1, s0));
                d0 = fmaf(acc[mt][nt][0], u0, fmaf(acc[mt][nt][1], u1, d0));
                s1 = fmaf(acc[mt][nt][2], w0, fmaf(acc[mt][nt][3], w1, s1));
                d1 = fmaf(acc[mt][nt][2], u0, fmaf(acc[mt][nt][3], u1, d1));
            }
#pragma unroll
            for (int o = 1; o <= 2; o <<= 1) {
                s0 += __shfl_xor_sync(0xffffffffu, s0, o);
                d0 += __shfl_xor_sync(0xffffffffu, d0, o);
                s1 += __shfl_xor_sync(0xffffffffu, s1, o);
                d1 += __shfl_xor_sync(0xffffffffu, d1, o);
            }
            if (tig == 0) {
                int r = row0 + wm * 32 + mt * 16 + g;
                as_[r * 4 + wn] = s0; ad_[r * 4 + wn] = d0;
                as_[(r + 8) * 4 + wn] = s1; ad_[(r + 8) * 4 + wn] = d1;
            }
        }
    }
}

__global__ void k_fill(int* __restrict__ p, int v, int n) {
    int i = blockIdx.x * blockDim.x + threadIdx.x;
    if (i < n) p[i] = v;
}

__global__ void k_zerof(float* __restrict__ p, int n) {
    int i = blockIdx.x * blockDim.x + threadIdx.x;
    if (i < n) p[i] = 0.f;
}

__global__ void __launch_bounds__(1024) k_scan1(const int* __restrict__ in,
                                                int* __restrict__ out,
                                                int* __restrict__ bsum, int n) {
    __shared__ int sm[1024];
    int t = threadIdx.x;
    int i = blockIdx.x * 1024 + t;
    int v = (i < n) ? in[i] : 0;
    sm[t] = v;
    __syncthreads();
    for (int o = 1; o < 1024; o <<= 1) {
        int u = (t >= o) ? sm[t - o] : 0;
        __syncthreads();
        sm[t] += u;
        __syncthreads();
    }
    if (i < n) out[i] = sm[t] - v;
    if (t == 1023) bsum[blockIdx.x] = sm[1023];
}

__global__ void k_scan2(int* __restrict__ bsum, int nb, int* __restrict__ off, int n) {
    int total = 0;
    for (int i = 0; i < nb; i++) { int v = bsum[i]; bsum[i] = total; total += v; }
    off[n] = total;
}

__global__ void __launch_bounds__(1024) k_scan3(int* __restrict__ off,
                                                const int* __restrict__ bsum,
                                                int* __restrict__ cur, int n) {
    int i = blockIdx.x * 1024 + threadIdx.x;
    if (i < n) {
        int v = off[i] + bsum[blockIdx.x];
        off[i] = v;
        cur[i] = v;
    }
}

__global__ void k_escatter(const int* __restrict__ s, const int* __restrict__ d,
                           const unsigned char* __restrict__ val, int* __restrict__ cur,
                           int* __restrict__ csr, int E) {
    int e = blockIdx.x * blockDim.x + threadIdx.x;
    if (e >= E) return;
    if (val && !val[e]) return;
    int p = atomicAdd(&cur[d[e]], 1);
    csr[p] = s[e];
}

// Fused GAT aggregation + topk score: warp per dst node. Softmax without
// max-shift (logits are O(10), exp is safe in fp32; softmax is
// shift-invariant so this matches the reference), 4-way unrolled for MLP.
__global__ void k_gather(const float* __restrict__ h1, const int* __restrict__ off,
                         const int* __restrict__ csr,
                         const float* __restrict__ as_, const float* __restrict__ ad_,
                         const float* __restrict__ bias, const float* __restrict__ pw,
                         float* __restrict__ out, float* __restrict__ sc, int n) {
    int wp = (blockIdx.x * blockDim.x + threadIdx.x) >> 5;
    if (wp >= n) return;
    int lane = threadIdx.x & 31;
    int head = lane >> 3;
    int d = wp;
    float adh = ad_[d * 4 + head];
    float w0s = expf(lrelu(as_[d * 4 + head] + adh));   // self loop
    float den = w0s;
    float acc[8];
    {
        const float4* p = (const float4*)(h1 + (size_t)d * FHC + lane * 8);
        float4 x0 = p[0], x1 = p[1];
        acc[0] = w0s * x0.x; acc[1] = w0s * x0.y; acc[2] = w0s * x0.z; acc[3] = w0s * x0.w;
        acc[4] = w0s * x1.x; acc[5] = w0s * x1.y; acc[6] = w0s * x1.z; acc[7] = w0s * x1.w;
    }
    int e = off[d], e1 = off[d + 1];
    for (; e + 3 < e1; e += 4) {
        int sv[4];
        float wgt[4];
        float4 f0[4], f1[4];
#pragma unroll
        for (int i = 0; i < 4; i++) sv[i] = csr[e + i];
#pragma unroll
        for (int i = 0; i < 4; i++) {
            wgt[i] = expf(lrelu(as_[sv[i] * 4 + head] + adh));
            const float4* p = (const float4*)(h1 + (size_t)sv[i] * FHC + lane * 8);
            f0[i] = p[0]; f1[i] = p[1];
        }
#pragma unroll
        for (int i = 0; i < 4; i++) {
            den += wgt[i];
            acc[0] = fmaf(wgt[i], f0[i].x, acc[0]);
            acc[1] = fmaf(wgt[i], f0[i].y, acc[1]);
            acc[2] = fmaf(wgt[i], f0[i].z, acc[2]);
            acc[3] = fmaf(wgt[i], f0[i].w, acc[3]);
            acc[4] = fmaf(wgt[i], f1[i].x, acc[4]);
            acc[5] = fmaf(wgt[i], f1[i].y, acc[5]);
            acc[6] = fmaf(wgt[i], f1[i].z, acc[6]);
            acc[7] = fmaf(wgt[i], f1[i].w, acc[7]);
        }
    }
    for (; e < e1; e++) {
        int s = csr[e];
        float w = expf(lrelu(as_[s * 4 + head] + adh));
        den += w;
        const float4* p = (const float4*)(h1 + (size_t)s * FHC + lane * 8);
        float4 x0 = p[0], x1 = p[1];
        acc[0] = fmaf(w, x0.x, acc[0]);
        acc[1] = fmaf(w, x0.y, acc[1]);
        acc[2] = fmaf(w, x0.z, acc[2]);
        acc[3] = fmaf(w, x0.w, acc[3]);
        acc[4] = fmaf(w, x1.x, acc[4]);
        acc[5] = fmaf(w, x1.y, acc[5]);
        acc[6] = fmaf(w, x1.z, acc[6]);
        acc[7] = fmaf(w, x1.w, acc[7]);
    }
    float inv = 1.f / (den + 1e-16f);
    int cb = lane * 8;
    float4 o0, o1;
    float v;
    v = acc[0] * inv + bias[cb + 0]; o0.x = v > 0.f ? v : expm1f(v);
    v = acc[1] * inv + bias[cb + 1]; o0.y = v > 0.f ? v : expm1f(v);
    v = acc[2] * inv + bias[cb + 2]; o0.z = v > 0.f ? v : expm1f(v);
    v = acc[3] * inv + bias[cb + 3]; o0.w = v > 0.f ? v : expm1f(v);
    v = acc[4] * inv + bias[cb + 4]; o1.x = v > 0.f ? v : expm1f(v);
    v = acc[5] * inv + bias[cb + 5]; o1.y = v > 0.f ? v : expm1f(v);
    v = acc[6] * inv + bias[cb + 6]; o1.z = v > 0.f ? v : expm1f(v);
    v = acc[7] * inv + bias[cb + 7]; o1.w = v > 0.f ? v : expm1f(v);
    float4* po = (float4*)(out + (size_t)d * FHC + cb);
    __stcs(po, o0);          // streaming store: protect h1's L2 residency
    __stcs(po + 1, o1);
    const float4* pwp = (const float4*)(pw + cb);
    float4 w0 = pwp[0], w1 = pwp[1];
    float sp = o0.x * w0.x + o0.y * w0.y + o0.z * w0.z + o0.w * w0.w +
               o1.x * w1.x + o1.y * w1.y + o1.z * w1.z + o1.w * w1.w;
    float n2 = w0.x * w0.x + w0.y * w0.y + w0.z * w0.z + w0.w * w0.w +
               w1.x * w1.x + w1.y * w1.y + w1.z * w1.z + w1.w * w1.w;
#pragma unroll
    for (int o = 16; o; o >>= 1) {
        sp += __shfl_xor_sync(0xffffffffu, sp, o);
        n2 += __shfl_xor_sync(0xffffffffu, n2, o);
    }
    if (!lane) sc[d] = sp / (sqrtf(n2) + 1e-16f);
}

// exact top-k per graph via tie-broken rank counting (order-invariant compact)
__global__ void __launch_bounds__(1024) k_topk(const float* __restrict__ score, int n_in,
                                               int k, int* __restrict__ perm,
                                               float* __restrict__ tanhv,
                                               int* __restrict__ newid) {
    __shared__ float sv[2048];
    __shared__ int sc[1024];
    int b = blockIdx.x, t = threadIdx.x;
    const float* s = score + b * n_in;
    for (int i = t; i < n_in; i += 1024) sv[i] = s[i];
    __syncthreads();
    int per = n_in >> 10;
    int cnt[2] = {0, 0};
    float mine[2] = {0.f, 0.f};
    int mi[2] = {0, 0};
    for (int q = 0; q < 2; q++)
        if (q < per) { mi[q] = t * per + q; mine[q] = sv[mi[q]]; }
    for (int j = 0; j < n_in; j++) {
        float x = sv[j];
        for (int q = 0; q < 2; q++)
            if (q < per)
                cnt[q] += (x > mine[q]) || (x == mine[q] && j < mi[q]);
    }
    int keep[2] = {0, 0};
    int local = 0;
    for (int q = 0; q < 2; q++)
        if (q < per) { keep[q] = (cnt[q] < k); local += keep[q]; }
    sc[t] = local;
    __syncthreads();
    for (int o = 1; o < 1024; o <<= 1) {
        int u = (t >= o) ? sc[t - o] : 0;
        __syncthreads();
        sc[t] += u;
        __syncthreads();
    }
    int pos = sc[t] - local;
    for (int q = 0; q < 2; q++) {
        if (q >= per) break;
        int oldl = mi[q];
        int old = b * n_in + oldl;
        if (keep[q]) {
            int np = b * k + pos;
            perm[np] = old;
            tanhv[np] = tanhf(mine[q]);
            newid[old] = np;
            pos++;
        } else {
            newid[old] = -1;
        }
    }
}

// warp per pooled node: hp = h[perm]*tanh, fused gate = <hp_row, gate_w> + b
__global__ void k_poolfeat(const float* __restrict__ h, const int* __restrict__ pm,
                           const float* __restrict__ th, const float* __restrict__ gw,
                           const float* __restrict__ gb, float* __restrict__ hp,
                           float* __restrict__ gt, int m) {
    int wp = (blockIdx.x * blockDim.x + threadIdx.x) >> 5;
    if (wp >= m) return;
    int lane = threadIdx.x & 31;
    int srcn = pm[wp];
    float tv = th[wp];
    int cb = lane * 8;
    const float4* p = (const float4*)(h + (size_t)srcn * FHC + cb);
    float4 a = p[0], b = p[1];
    a.x *= tv; a.y *= tv; a.z *= tv; a.w *= tv;
    b.x *= tv; b.y *= tv; b.z *= tv; b.w *= tv;
    float4* po = (float4*)(hp + (size_t)wp * FHC + cb);
    po[0] = a; po[1] = b;
    const float4* g4 = (const float4*)(gw + cb);
    float4 w0 = g4[0], w1 = g4[1];
    float s = a.x * w0.x + a.y * w0.y + a.z * w0.z + a.w * w0.w +
              b.x * w1.x + b.y * w1.y + b.z * w1.z + b.w * w1.w;
#pragma unroll
    for (int o = 16; o; o >>= 1) s += __shfl_xor_sync(0xffffffffu, s, o);
    if (!lane) gt[wp] = s + gb[0];
}

// remap edges to pooled ids + count pooled in-degrees (fused)
__global__ void k_remap_deg(const int* __restrict__ si, const int* __restrict__ di,
                            const int* __restrict__ nid, int* __restrict__ so,
                            int* __restrict__ dq, unsigned char* __restrict__ vo,
                            int* __restrict__ deg, int E) {
    int e = blockIdx.x * blockDim.x + threadIdx.x;
    if (e >= E) return;
    int ns = nid[si[e]], nd = nid[di[e]];
    bool v = (ns >= 0) && (nd >= 0);
    so[e] = v ? ns : 0;
    dq[e] = v ? nd : 0;
    vo[e] = v ? 1 : 0;
    if (v) atomicAdd(&deg[nd], 1);
}

// per-graph gate softmax stats: one warp per graph -> (max, 1/sum)
__global__ void __launch_bounds__(1024) k_gmax(const float* __restrict__ gt,
                                               float* __restrict__ gmi, int npg) {
    int w = threadIdx.x >> 5, lane = threadIdx.x & 31;
    const float* g = gt + w * npg;
    float mx = -1e30f;
    for (int i = lane; i < npg; i += 32) mx = fmaxf(mx, g[i]);
    for (int o = 16; o; o >>= 1) mx = fmaxf(mx, __shfl_xor_sync(0xffffffffu, mx, o));
    float s = 0.f;
    for (int i = lane; i < npg; i += 32) s += expf(g[i] - mx);
    for (int o = 16; o; o >>= 1) s += __shfl_xor_sync(0xffffffffu, s, o);
    if (!lane) { gmi[w * 2] = mx; gmi[w * 2 + 1] = 1.f / s; }
}

// weighted partial sums: grid (8, NB), accumulate into out via atomics
__global__ void k_attpool2(const float* __restrict__ hp, const float* __restrict__ gt,
                           const float* __restrict__ gmi, float* __restrict__ out,
                           int npg) {
    int b = blockIdx.y, t = threadIdx.x;
    int chunk = npg >> 3;
    int i0 = blockIdx.x * chunk;
    float mx = gmi[b * 2], inv = gmi[b * 2 + 1];
    const float* g = gt + b * npg + i0;
    const float* hb = hp + ((size_t)b * npg + i0) * FHC;
    float a = 0.f;
    for (int i = 0; i < chunk; i++)
        a = fmaf(expf(g[i] - mx), hb[(size_t)i * FHC + t], a);
    atomicAdd(&out[b * FHC + t], a * inv);
}

// ---------------- host side ----------------

extern "C" void kernel_launch(void* const* d_in, const int* in_sizes, int n_in,
                              void* d_out, int out_size) {
    const float* x        = (const float*)d_in[0];
    const void*  ei       = d_in[1];
    const float* lin0_w   = (const float*)d_in[2];
    const float* lin0_b   = (const float*)d_in[3];
    const float* gat0_W   = (const float*)d_in[4];
    const float* gat0_as  = (const float*)d_in[5];
    const float* gat0_ad  = (const float*)d_in[6];
    const float* gat0_b   = (const float*)d_in[7];
    const float* pool0_w  = (const float*)d_in[8];
    const float* gat1_W   = (const float*)d_in[9];
    const float* gat1_as  = (const float*)d_in[10];
    const float* gat1_ad  = (const float*)d_in[11];
    const float* gat1_b   = (const float*)d_in[12];
    const float* pool1_w  = (const float*)d_in[13];
    const float* gate_w   = (const float*)d_in[14];
    const float* gate_b   = (const float*)d_in[15];
    float* out = (float*)d_out;

    float *h0, *h1, *ho, *hp, *hp2, *as_, *ad_, *sc, *th, *gt, *gmi;
    int *s0, *d0, *s1, *d1, *deg, *off, *cur, *csr, *pm, *nid, *bs;
    unsigned char* v1;
    cudaGetSymbolAddress((void**)&h0, g_h0);
    cudaGetSymbolAddress((void**)&h1, g_h1);
    cudaGetSymbolAddress((void**)&ho, g_ho);
    cudaGetSymbolAddress((void**)&hp, g_hp);
    cudaGetSymbolAddress((void**)&hp2, g_hp2);
    cudaGetSymbolAddress((void**)&as_, g_as);
    cudaGetSymbolAddress((void**)&ad_, g_ad);
    cudaGetSymbolAddress((void**)&sc, g_sc);
    cudaGetSymbolAddress((void**)&th, g_th);
    cudaGetSymbolAddress((void**)&gt, g_gt);
    cudaGetSymbolAddress((void**)&gmi, g_gmi);
    cudaGetSymbolAddress((void**)&s0, g_s0);
    cudaGetSymbolAddress((void**)&d0, g_d0);
    cudaGetSymbolAddress((void**)&s1, g_s1);
    cudaGetSymbolAddress((void**)&d1, g_d1);
    cudaGetSymbolAddress((void**)&deg, g_deg);
    cudaGetSymbolAddress((void**)&off, g_off);
    cudaGetSymbolAddress((void**)&cur, g_cur);
    cudaGetSymbolAddress((void**)&csr, g_csr);
    cudaGetSymbolAddress((void**)&pm, g_pm);
    cudaGetSymbolAddress((void**)&nid, g_nid);
    cudaGetSymbolAddress((void**)&bs, g_bs);
    cudaGetSymbolAddress((void**)&v1, g_v1);

    cudaFuncSetAttribute(k_gemm_tc, cudaFuncAttributeMaxDynamicSharedMemorySize,
                         SMEM_GEMM);

    static cudaStream_t s2 = nullptr;
    static cudaEvent_t evF0, evS0, evT0, evP0, evS1, evA0;
    if (!s2) {
        cudaStreamCreateWithFlags(&s2, cudaStreamNonBlocking);
        cudaEventCreateWithFlags(&evF0, cudaEventDisableTiming);
        cudaEventCreateWithFlags(&evS0, cudaEventDisableTiming);
        cudaEventCreateWithFlags(&evT0, cudaEventDisableTiming);
        cudaEventCreateWithFlags(&evP0, cudaEventDisableTiming);
        cudaEventCreateWithFlags(&evS1, cudaEventDisableTiming);
        cudaEventCreateWithFlags(&evA0, cudaEventDisableTiming);
    }

    const int EB = divup(E0, 256);

    // ---- main: output zero (root of the capture graph) ----
    k_zerof<<<divup(NB * FHC, 256), 256>>>(out, NB * FHC);

    // fork side stream: edge decode + CSR build for GAT0
    cudaEventRecord(evF0, 0);
    cudaStreamWaitEvent(s2, evF0, 0);
    k_detect<<<1, 1, 0, s2>>>((const int*)ei);
    k_fill<<<divup(N0, 256), 256, 0, s2>>>(deg, 0, N0);
    k_edges_deg<<<EB, 256, 0, s2>>>(ei, s0, d0, deg, E0);
    k_scan1<<<N0 / 1024, 1024, 0, s2>>>(deg, off, bs, N0);
    k_scan2<<<1, 1, 0, s2>>>(bs, N0 / 1024, off, N0);
    k_scan3<<<N0 / 1024, 1024, 0, s2>>>(off, bs, cur, N0);
    k_escatter<<<EB, 256, 0, s2>>>(s0, d0, nullptr, cur, csr, E0);
    cudaEventRecord(evS0, s2);

    // ---- main: lin0 (K=128 + rank-1 for col 128) + GAT0 GEMM ----
    k_gemm_tc<<<dim3(1, N0 / 128), 512, SMEM_GEMM>>>(
        x, lin0_w, lin0_b, h0, N0, 128, 256, 1, 129,
        x + 128, lin0_w + 128 * 256, nullptr, nullptr, nullptr, nullptr);
    k_gemm_tc<<<dim3(1, N0 / 128), 512, SMEM_GEMM>>>(
        h0, gat0_W, nullptr, h1, N0, 256, 256, 0, 256,
        nullptr, nullptr, gat0_as, gat0_ad, as_, ad_);

    // join: gather0 needs CSR + h1/as_/ad_
    cudaStreamWaitEvent(0, evS0, 0);
    k_gather<<<divup(N0, 8), 256>>>(h1, off, csr, as_, ad_, gat0_b, pool0_w, ho, sc, N0);

    // TopK pool 0
    k_topk<<<NB, 1024>>>(sc, 2048, 1024, pm, th, nid);
    cudaEventRecord(evT0, 0);
    k_poolfeat<<<divup((N0 / 2) * 32, 256), 256>>>(ho, pm, th, gate_w, gate_b, hp, gt, N0 / 2);
    cudaEventRecord(evP0, 0);

    // side: CSR build for GAT1 (needs nid), then attpool0 (needs hp/gt)
    cudaStreamWaitEvent(s2, evT0, 0);
    k_fill<<<divup(N0 / 2, 256), 256, 0, s2>>>(deg, 0, N0 / 2);
    k_remap_deg<<<EB, 256, 0, s2>>>(s0, d0, nid, s1, d1, v1, deg, E0);
    k_scan1<<<(N0 / 2) / 1024, 1024, 0, s2>>>(deg, off, bs, N0 / 2);
    k_scan2<<<1, 1, 0, s2>>>(bs, (N0 / 2) / 1024, off, N0 / 2);
    k_scan3<<<(N0 / 2) / 1024, 1024, 0, s2>>>(off, bs, cur, N0 / 2);
    k_escatter<<<EB, 256, 0, s2>>>(s1, d1, v1, cur, csr, E0);
    cudaEventRecord(evS1, s2);
    cudaStreamWaitEvent(s2, evP0, 0);
    k_gmax<<<1, 1024, 0, s2>>>(gt, gmi, 1024);
    k_attpool2<<<dim3(8, NB), 256, 0, s2>>>(hp, gt, gmi, out, 1024);
    cudaEventRecord(evA0, s2);

    // ---- main: GAT1 GEMM (overlaps side CSR + attpool0) ----
    k_gemm_tc<<<dim3(1, (N0 / 2) / 128), 512, SMEM_GEMM>>>(
        hp, gat1_W, nullptr, h1, N0 / 2, 256, 256, 0, 256,
        nullptr, nullptr, gat1_as, gat1_ad, as_, ad_);
    cudaStreamWaitEvent(0, evS1, 0);
    k_gather<<<divup(N0 / 2, 8), 256>>>(h1, off, csr, as_, ad_, gat1_b, pool1_w, ho, sc, N0 / 2);

    // TopK pool 1
    k_topk<<<NB, 1024>>>(sc, 1024, 512, pm, th, nid);
    k_poolfeat<<<divup((N0 / 4) * 32, 256), 256>>>(ho, pm, th, gate_w, gate_b, hp2, gt, N0 / 4);

    // AttPool 1 -> out (+=); join attpool0 branch before final adds
    cudaStreamWaitEvent(0, evA0, 0);
    k_gmax<<<1, 1024>>>(gt, gmi, 512);
    k_attpool2<<<dim3(8, NB), 256>>>(hp2, gt, gmi, out, 512);
}

// round 10
// speedup vs baseline: 1.9340x; 1.0114x over previous
#include <cuda_runtime.h>
#include <math.h>
#include <stdint.h>

#define N0  65536     // total nodes
#define E0  524288    // total edges
#define NB  32        // graphs
#define FHC 256       // feature width (H*C)

// ---------------- static device scratch ----------------
__device__ float g_h0[(size_t)N0 * FHC];
__device__ float g_h1[(size_t)N0 * FHC];
__device__ float g_ho[(size_t)N0 * FHC];
__device__ float g_hp[(size_t)(N0 / 2) * FHC];
__device__ float g_hp2[(size_t)(N0 / 4) * FHC];
__device__ float g_wsp[6 * 65536];   // presplit weights: lin0 hi/lo, gat0 hi/lo, gat1 hi/lo
__device__ float g_as[N0 * 4], g_ad[N0 * 4];
__device__ float g_sc[N0];
__device__ float g_th[N0 / 2];
__device__ float g_gt[N0 / 2];
__device__ float g_gmi[NB * 2];
__device__ int g_s0[E0], g_d0[E0], g_s1[E0], g_d1[E0];
__device__ unsigned char g_v1[E0];
__device__ int g_deg[N0], g_off[N0 + 1], g_cur[N0], g_csr[E0];
__device__ int g_bs[64];
__device__ int g_pm[N0 / 2], g_nid[N0];
__device__ int g_is64;

static inline int divup(int a, int b) { return (a + b - 1) / b; }

__device__ __forceinline__ float lrelu(float z) { return z > 0.f ? z : 0.2f * z; }

// ---------------- tf32 helpers ----------------
__device__ __forceinline__ void tf32split(float x, uint32_t& hi, uint32_t& lo) {
    asm("cvt.rna.tf32.f32 %0, %1;" : "=r"(hi) : "f"(x));
    float r = x - __uint_as_float(hi);
    asm("cvt.rna.tf32.f32 %0, %1;" : "=r"(lo) : "f"(r));
}

#define MMA_TF32(d, a, b0, b1)                                                   \
    asm volatile(                                                                \
        "mma.sync.aligned.m16n8k8.row.col.f32.tf32.tf32.f32 "                    \
        "{%0,%1,%2,%3},{%4,%5,%6,%7},{%8,%9},{%0,%1,%2,%3};"                     \
        : "+f"(d[0]), "+f"(d[1]), "+f"(d[2]), "+f"(d[3])                         \
        : "r"(a[0]), "r"(a[1]), "r"(a[2]), "r"(a[3]), "r"(b0), "r"(b1))

__device__ __forceinline__ void cpa16(uint32_t dst, const void* src) {
    asm volatile("cp.async.cg.shared.global [%0], [%1], 16;" :: "r"(dst), "l"(src));
}
__device__ __forceinline__ void cpa4(uint32_t dst, const void* src) {
    asm volatile("cp.async.ca.shared.global [%0], [%1], 4;" :: "r"(dst), "l"(src));
}

// ---------------- kernels ----------------

__global__ void k_detect(const int* __restrict__ w) {
    int nz = 0;
    for (int i = 1; i < 128; i += 2) nz |= (w[i] != 0);
    g_is64 = nz ? 0 : 1;
}

// split all three weight matrices into tf32 hi/lo (one pass)
// regions: lin0 128x256 -> wsp[0],[1]; gat0 256x256 -> [2],[3]; gat1 -> [4],[5]
__global__ void k_wsplit(const float* __restrict__ w0, const float* __restrict__ w1,
                         const float* __restrict__ w2, float* __restrict__ wsp) {
    int i = blockIdx.x * blockDim.x + threadIdx.x;
    const float* src;
    float *hi, *lo;
    int li;
    if (i < 32768)        { src = w0; li = i;          hi = wsp;            lo = wsp + 65536; }
    else if (i < 98304)   { src = w1; li = i - 32768;  hi = wsp + 131072;   lo = wsp + 196608; }
    else if (i < 163840)  { src = w2; li = i - 98304;  hi = wsp + 262144;   lo = wsp + 327680; }
    else return;
    uint32_t h, l;
    tf32split(src[li], h, l);
    hi[li] = __uint_as_float(h);
    lo[li] = __uint_as_float(l);
}

// decode edges + count in-degrees (fused)
__global__ void k_edges_deg(const void* __restrict__ ei, int* __restrict__ s,
                            int* __restrict__ d, int* __restrict__ deg, int E) {
    int i = blockIdx.x * blockDim.x + threadIdx.x;
    if (i >= E) return;
    int sv, dv;
    if (g_is64) {
        const long long* p = (const long long*)ei;
        sv = (int)p[i];
        dv = (int)p[E + i];
    } else {
        const int* p = (const int*)ei;
        sv = p[i];
        dv = p[E + i];
    }
    s[i] = sv; d[i] = dv;
    atomicAdd(&deg[dv], 1);
}

// Tensor-core GEMM, 3xTF32. B (weights) presplit in global hi/lo; A split
// in registers. Double-buffered cp.async. Block tile 128x256, BK=32,
// 512 threads; grid (1, M/128); K % 32 == 0; N == 256.
// Kld = leading dim of A. Optional rank-1 epilogue + fused attention epilogue.
#define AP 36
#define BP 260
#define ABUF (128 * AP)
#define BBUF (32 * BP)
#define SBUF (ABUF + 2 * BBUF)
#define SMEM_GEMM (2 * SBUF * 4)
__global__ void __launch_bounds__(512, 1)
k_gemm_tc(const float* __restrict__ A, const float* __restrict__ Bh,
          const float* __restrict__ Bl,
          const float* __restrict__ bias, float* __restrict__ Cm,
          int M, int K, int N, int act, int Kld,
          const float* __restrict__ a1col, const float* __restrict__ b1row,
          const float* __restrict__ aS, const float* __restrict__ aD,
          float* __restrict__ as_, float* __restrict__ ad_) {
    extern __shared__ float smg[];
    int t = threadIdx.x;
    int lane = t & 31, w = t >> 5;
    int g = lane >> 2, tig = lane & 3;
    int wm = w & 3, wn = w >> 2;
    int row0 = blockIdx.y * 128;
    int nk = K >> 5;
    bool al16 = (Kld & 3) == 0;

    float acc[2][8][4];
#pragma unroll
    for (int i = 0; i < 2; i++)
#pragma unroll
        for (int j = 0; j < 8; j++)
#pragma unroll
            for (int q = 0; q < 4; q++) acc[i][j][q] = 0.f;

    auto copy_tile = [&](int ti, int bf) {
        float* As  = smg + bf * SBUF;
        float* Bsh = As + ABUF;
        float* Bsl = Bsh + BBUF;
#pragma unroll
        for (int it = 0; it < 2; it++) {
            int lin = t + 512 * it;
            int r = lin >> 3, c4 = (lin & 7) * 4;
            const float* src = &A[(size_t)(row0 + r) * Kld + ti * 32 + c4];
            uint32_t dst = (uint32_t)__cvta_generic_to_shared(&As[r * AP + c4]);
            if (al16) {
                cpa16(dst, src);
            } else {
#pragma unroll
                for (int j = 0; j < 4; j++) cpa4(dst + j * 4, src + j);
            }
        }
#pragma unroll
        for (int it = 0; it < 4; it++) {
            int lin = t + 512 * it;
            int kk = lin >> 6, c4 = (lin & 63) * 4;
            size_t gsrc = (size_t)(ti * 32 + kk) * N + c4;
            cpa16((uint32_t)__cvta_generic_to_shared(&Bsh[kk * BP + c4]), &Bh[gsrc]);
            cpa16((uint32_t)__cvta_generic_to_shared(&Bsl[kk * BP + c4]), &Bl[gsrc]);
        }
    };

    copy_tile(0, 0);
    asm volatile("cp.async.commit_group;");

    for (int ti = 0; ti < nk; ti++) {
        if (ti + 1 < nk) {
            copy_tile(ti + 1, (ti + 1) & 1);
            asm volatile("cp.async.commit_group;");
            asm volatile("cp.async.wait_group 1;");
        } else {
            asm volatile("cp.async.wait_group 0;");
        }
        __syncthreads();
        const float* As  = smg + (ti & 1) * SBUF;
        const float* Bsh = As + ABUF;
        const float* Bsl = Bsh + BBUF;
#pragma unroll
        for (int ks = 0; ks < 4; ks++) {
            int k8 = ks * 8;
            uint32_t ah[2][4], al[2][4];
#pragma unroll
            for (int mt = 0; mt < 2; mt++) {
                int bm = wm * 32 + mt * 16 + g;
                tf32split(As[bm * AP + k8 + tig],           ah[mt][0], al[mt][0]);
                tf32split(As[(bm + 8) * AP + k8 + tig],     ah[mt][1], al[mt][1]);
                tf32split(As[bm * AP + k8 + tig + 4],       ah[mt][2], al[mt][2]);
                tf32split(As[(bm + 8) * AP + k8 + tig + 4], ah[mt][3], al[mt][3]);
            }
#pragma unroll
            for (int nt = 0; nt < 8; nt++) {
                int bn = wn * 64 + nt * 8 + g;
                uint32_t b0h = __float_as_uint(Bsh[(k8 + tig) * BP + bn]);
                uint32_t b1h = __float_as_uint(Bsh[(k8 + tig + 4) * BP + bn]);
                uint32_t b0l = __float_as_uint(Bsl[(k8 + tig) * BP + bn]);
                uint32_t b1l = __float_as_uint(Bsl[(k8 + tig + 4) * BP + bn]);
#pragma unroll
                for (int mt = 0; mt < 2; mt++) {
                    MMA_TF32(acc[mt][nt], ah[mt], b0h, b1h);
                    MMA_TF32(acc[mt][nt], ah[mt], b0l, b1l);
                    MMA_TF32(acc[mt][nt], al[mt], b0h, b1h);
                }
            }
        }
        __syncthreads();
    }

#pragma unroll
    for (int mt = 0; mt < 2; mt++) {
        int r = row0 + wm * 32 + mt * 16 + g;
        float ar0 = a1col ? a1col[(size_t)r * Kld] : 0.f;
        float ar8 = a1col ? a1col[(size_t)(r + 8) * Kld] : 0.f;
#pragma unroll
        for (int nt = 0; nt < 8; nt++) {
            int cc = wn * 64 + nt * 8 + tig * 2;
            float bb0 = a1col ? b1row[cc] : 0.f, bb1 = a1col ? b1row[cc + 1] : 0.f;
            float b0 = bias ? bias[cc] : 0.f, b1 = bias ? bias[cc + 1] : 0.f;
            float v0 = acc[mt][nt][0] + ar0 * bb0 + b0;
            float v1 = acc[mt][nt][1] + ar0 * bb1 + b1;
            float v2 = acc[mt][nt][2] + ar8 * bb0 + b0;
            float v3 = acc[mt][nt][3] + ar8 * bb1 + b1;
            if (act) {
                v0 = fmaxf(v0, 0.f); v1 = fmaxf(v1, 0.f);
                v2 = fmaxf(v2, 0.f); v3 = fmaxf(v3, 0.f);
            }
            float2 p0 = {v0, v1}, p1 = {v2, v3};
            *(float2*)&Cm[(size_t)r * N + cc] = p0;
            *(float2*)&Cm[(size_t)(r + 8) * N + cc] = p1;
        }
    }

    if (aS) {
        const float* ws = aS + wn * 64;
        const float* wd = aD + wn * 64;
#pragma unroll
        for (int mt = 0; mt < 2; mt++) {
            float s0 = 0.f, d0 = 0.f, s1 = 0.f, d1 = 0.f;
#pragma unroll
            for (int nt = 0; nt < 8; nt++) {
                int c = nt * 8 + tig * 2;
                float w0 = ws[c], w1 = ws[c + 1];
                float u0 = wd[c], u1 = wd[c + 1];
                s0 = fmaf(acc[mt][nt][0], w0, fmaf(acc[mt][nt][1], w1, s0));
                d0 = fmaf(acc[mt][nt][0], u0, fmaf(acc[mt][nt][1], u1, d0));
                s1 = fmaf(acc[mt][nt][2], w0, fmaf(acc[mt][nt][3], w1, s1));
                d1 = fmaf(acc[mt][nt][2], u0, fmaf(acc[mt][nt][3], u1, d1));
            }
#pragma unroll
            for (int o = 1; o <= 2; o <<= 1) {
                s0 += __shfl_xor_sync(0xffffffffu, s0, o);
                d0 += __shfl_xor_sync(0xffffffffu, d0, o);
                s1 += __shfl_xor_sync(0xffffffffu, s1, o);
                d1 += __shfl_xor_sync(0xffffffffu, d1, o);
            }
            if (tig == 0) {
                int r = row0 + wm * 32 + mt * 16 + g;
                as_[r * 4 + wn] = s0; ad_[r * 4 + wn] = d0;
                as_[(r + 8) * 4 + wn] = s1; ad_[(r + 8) * 4 + wn] = d1;
            }
        }
    }
}

__global__ void k_fill(int* __restrict__ p, int v, int n) {
    int i = blockIdx.x * blockDim.x + threadIdx.x;
    if (i < n) p[i] = v;
}

__global__ void k_zerof(float* __restrict__ p, int n) {
    int i = blockIdx.x * blockDim.x + threadIdx.x;
    if (i < n) p[i] = 0.f;
}

__global__ void __launch_bounds__(1024) k_scan1(const int* __restrict__ in,
                                                int* __restrict__ out,
                                                int* __restrict__ bsum, int n) {
    __shared__ int sm[1024];
    int t = threadIdx.x;
    int i = blockIdx.x * 1024 + t;
    int v = (i < n) ? in[i] : 0;
    sm[t] = v;
    __syncthreads();
    for (int o = 1; o < 1024; o <<= 1) {
        int u = (t >= o) ? sm[t - o] : 0;
        __syncthreads();
        sm[t] += u;
        __syncthreads();
    }
    if (i < n) out[i] = sm[t] - v;
    if (t == 1023) bsum[blockIdx.x] = sm[1023];
}

__global__ void k_scan2(int* __restrict__ bsum, int nb, int* __restrict__ off, int n) {
    int total = 0;
    for (int i = 0; i < nb; i++) { int v = bsum[i]; bsum[i] = total; total += v; }
    off[n] = total;
}

__global__ void __launch_bounds__(1024) k_scan3(int* __restrict__ off,
                                                const int* __restrict__ bsum,
                                                int* __restrict__ cur, int n) {
    int i = blockIdx.x * 1024 + threadIdx.x;
    if (i < n) {
        int v = off[i] + bsum[blockIdx.x];
        off[i] = v;
        cur[i] = v;
    }
}

__global__ void k_escatter(const int* __restrict__ s, const int* __restrict__ d,
                           const unsigned char* __restrict__ val, int* __restrict__ cur,
                           int* __restrict__ csr, int E) {
    int e = blockIdx.x * blockDim.x + threadIdx.x;
    if (e >= E) return;
    if (val && !val[e]) return;
    int p = atomicAdd(&cur[d[e]], 1);
    csr[p] = s[e];
}

// Fused GAT aggregation + topk score: warp per dst node. Softmax without
// max-shift (shift-invariant; logits O(10), exp safe in fp32), 4-way MLP.
__global__ void k_gather(const float* __restrict__ h1, const int* __restrict__ off,
                         const int* __restrict__ csr,
                         const float* __restrict__ as_, const float* __restrict__ ad_,
                         const float* __restrict__ bias, const float* __restrict__ pw,
                         float* __restrict__ out, float* __restrict__ sc, int n) {
    int wp = (blockIdx.x * blockDim.x + threadIdx.x) >> 5;
    if (wp >= n) return;
    int lane = threadIdx.x & 31;
    int head = lane >> 3;
    int d = wp;
    float adh = ad_[d * 4 + head];
    float w0s = expf(lrelu(as_[d * 4 + head] + adh));   // self loop
    float den = w0s;
    float acc[8];
    {
        const float4* p = (const float4*)(h1 + (size_t)d * FHC + lane * 8);
        float4 x0 = p[0], x1 = p[1];
        acc[0] = w0s * x0.x; acc[1] = w0s * x0.y; acc[2] = w0s * x0.z; acc[3] = w0s * x0.w;
        acc[4] = w0s * x1.x; acc[5] = w0s * x1.y; acc[6] = w0s * x1.z; acc[7] = w0s * x1.w;
    }
    int e = off[d], e1 = off[d + 1];
    for (; e + 3 < e1; e += 4) {
        int sv[4];
        float wgt[4];
        float4 f0[4], f1[4];
#pragma unroll
        for (int i = 0; i < 4; i++) sv[i] = csr[e + i];
#pragma unroll
        for (int i = 0; i < 4; i++) {
            wgt[i] = expf(lrelu(as_[sv[i] * 4 + head] + adh));
            const float4* p = (const float4*)(h1 + (size_t)sv[i] * FHC + lane * 8);
            f0[i] = p[0]; f1[i] = p[1];
        }
#pragma unroll
        for (int i = 0; i < 4; i++) {
            den += wgt[i];
            acc[0] = fmaf(wgt[i], f0[i].x, acc[0]);
            acc[1] = fmaf(wgt[i], f0[i].y, acc[1]);
            acc[2] = fmaf(wgt[i], f0[i].z, acc[2]);
            acc[3] = fmaf(wgt[i], f0[i].w, acc[3]);
            acc[4] = fmaf(wgt[i], f1[i].x, acc[4]);
            acc[5] = fmaf(wgt[i], f1[i].y, acc[5]);
            acc[6] = fmaf(wgt[i], f1[i].z, acc[6]);
            acc[7] = fmaf(wgt[i], f1[i].w, acc[7]);
        }
    }
    for (; e < e1; e++) {
        int s = csr[e];
        float w = expf(lrelu(as_[s * 4 + head] + adh));
        den += w;
        const float4* p = (const float4*)(h1 + (size_t)s * FHC + lane * 8);
        float4 x0 = p[0], x1 = p[1];
        acc[0] = fmaf(w, x0.x, acc[0]);
        acc[1] = fmaf(w, x0.y, acc[1]);
        acc[2] = fmaf(w, x0.z, acc[2]);
        acc[3] = fmaf(w, x0.w, acc[3]);
        acc[4] = fmaf(w, x1.x, acc[4]);
        acc[5] = fmaf(w, x1.y, acc[5]);
        acc[6] = fmaf(w, x1.z, acc[6]);
        acc[7] = fmaf(w, x1.w, acc[7]);
    }
    float inv = 1.f / (den + 1e-16f);
    int cb = lane * 8;
    float4 o0, o1;
    float v;
    v = acc[0] * inv + bias[cb + 0]; o0.x = v > 0.f ? v : expm1f(v);
    v = acc[1] * inv + bias[cb + 1]; o0.y = v > 0.f ? v : expm1f(v);
    v = acc[2] * inv + bias[cb + 2]; o0.z = v > 0.f ? v : expm1f(v);
    v = acc[3] * inv + bias[cb + 3]; o0.w = v > 0.f ? v : expm1f(v);
    v = acc[4] * inv + bias[cb + 4]; o1.x = v > 0.f ? v : expm1f(v);
    v = acc[5] * inv + bias[cb + 5]; o1.y = v > 0.f ? v : expm1f(v);
    v = acc[6] * inv + bias[cb + 6]; o1.z = v > 0.f ? v : expm1f(v);
    v = acc[7] * inv + bias[cb + 7]; o1.w = v > 0.f ? v : expm1f(v);
    float4* po = (float4*)(out + (size_t)d * FHC + cb);
    __stcs(po, o0);
    __stcs(po + 1, o1);
    const float4* pwp = (const float4*)(pw + cb);
    float4 w0 = pwp[0], w1 = pwp[1];
    float sp = o0.x * w0.x + o0.y * w0.y + o0.z * w0.z + o0.w * w0.w +
               o1.x * w1.x + o1.y * w1.y + o1.z * w1.z + o1.w * w1.w;
    float n2 = w0.x * w0.x + w0.y * w0.y + w0.z * w0.z + w0.w * w0.w +
               w1.x * w1.x + w1.y * w1.y + w1.z * w1.z + w1.w * w1.w;
#pragma unroll
    for (int o = 16; o; o >>= 1) {
        sp += __shfl_xor_sync(0xffffffffu, sp, o);
        n2 += __shfl_xor_sync(0xffffffffu, n2, o);
    }
    if (!lane) sc[d] = sp / (sqrtf(n2) + 1e-16f);
}

// exact top-k per graph via tie-broken rank counting (order-invariant compact)
__global__ void __launch_bounds__(1024) k_topk(const float* __restrict__ score, int n_in,
                                               int k, int* __restrict__ perm,
                                               float* __restrict__ tanhv,
                                               int* __restrict__ newid) {
    __shared__ float sv[2048];
    __shared__ int sc[1024];
    int b = blockIdx.x, t = threadIdx.x;
    const float* s = score + b * n_in;
    for (int i = t; i < n_in; i += 1024) sv[i] = s[i];
    __syncthreads();
    int per = n_in >> 10;
    int cnt[2] = {0, 0};
    float mine[2] = {0.f, 0.f};
    int mi[2] = {0, 0};
    for (int q = 0; q < 2; q++)
        if (q < per) { mi[q] = t * per + q; mine[q] = sv[mi[q]]; }
    for (int j = 0; j < n_in; j++) {
        float x = sv[j];
        for (int q = 0; q < 2; q++)
            if (q < per)
                cnt[q] += (x > mine[q]) || (x == mine[q] && j < mi[q]);
    }
    int keep[2] = {0, 0};
    int local = 0;
    for (int q = 0; q < 2; q++)
        if (q < per) { keep[q] = (cnt[q] < k); local += keep[q]; }
    sc[t] = local;
    __syncthreads();
    for (int o = 1; o < 1024; o <<= 1) {
        int u = (t >= o) ? sc[t - o] : 0;
        __syncthreads();
        sc[t] += u;
        __syncthreads();
    }
    int pos = sc[t] - local;
    for (int q = 0; q < 2; q++) {
        if (q >= per) break;
        int oldl = mi[q];
        int old = b * n_in + oldl;
        if (keep[q]) {
            int np = b * k + pos;
            perm[np] = old;
            tanhv[np] = tanhf(mine[q]);
            newid[old] = np;
            pos++;
        } else {
            newid[old] = -1;
        }
    }
}

// warp per pooled node: hp = h[perm]*tanh, fused gate = <hp_row, gate_w> + b
__global__ void k_poolfeat(const float* __restrict__ h, const int* __restrict__ pm,
                           const float* __restrict__ th, const float* __restrict__ gw,
                           const float* __restrict__ gb, float* __restrict__ hp,
                           float* __restrict__ gt, int m) {
    int wp = (blockIdx.x * blockDim.x + threadIdx.x) >> 5;
    if (wp >= m) return;
    int lane = threadIdx.x & 31;
    int srcn = pm[wp];
    float tv = th[wp];
    int cb = lane * 8;
    const float4* p = (const float4*)(h + (size_t)srcn * FHC + cb);
    float4 a = p[0], b = p[1];
    a.x *= tv; a.y *= tv; a.z *= tv; a.w *= tv;
    b.x *= tv; b.y *= tv; b.z *= tv; b.w *= tv;
    float4* po = (float4*)(hp + (size_t)wp * FHC + cb);
    po[0] = a; po[1] = b;
    const float4* g4 = (const float4*)(gw + cb);
    float4 w0 = g4[0], w1 = g4[1];
    float s = a.x * w0.x + a.y * w0.y + a.z * w0.z + a.w * w0.w +
              b.x * w1.x + b.y * w1.y + b.z * w1.z + b.w * w1.w;
#pragma unroll
    for (int o = 16; o; o >>= 1) s += __shfl_xor_sync(0xffffffffu, s, o);
    if (!lane) gt[wp] = s + gb[0];
}

// remap edges to pooled ids + count pooled in-degrees (fused)
__global__ void k_remap_deg(const int* __restrict__ si, const int* __restrict__ di,
                            const int* __restrict__ nid, int* __restrict__ so,
                            int* __restrict__ dq, unsigned char* __restrict__ vo,
                            int* __restrict__ deg, int E) {
    int e = blockIdx.x * blockDim.x + threadIdx.x;
    if (e >= E) return;
    int ns = nid[si[e]], nd = nid[di[e]];
    bool v = (ns >= 0) && (nd >= 0);
    so[e] = v ? ns : 0;
    dq[e] = v ? nd : 0;
    vo[e] = v ? 1 : 0;
    if (v) atomicAdd(&deg[nd], 1);
}

// per-graph gate softmax stats: one warp per graph -> (max, 1/sum)
__global__ void __launch_bounds__(1024) k_gmax(const float* __restrict__ gt,
                                               float* __restrict__ gmi, int npg) {
    int w = threadIdx.x >> 5, lane = threadIdx.x & 31;
    const float* g = gt + w * npg;
    float mx = -1e30f;
    for (int i = lane; i < npg; i += 32) mx = fmaxf(mx, g[i]);
    for (int o = 16; o; o >>= 1) mx = fmaxf(mx, __shfl_xor_sync(0xffffffffu, mx, o));
    float s = 0.f;
    for (int i = lane; i < npg; i += 32) s += expf(g[i] - mx);
    for (int o = 16; o; o >>= 1) s += __shfl_xor_sync(0xffffffffu, s, o);
    if (!lane) { gmi[w * 2] = mx; gmi[w * 2 + 1] = 1.f / s; }
}

// weighted partial sums: grid (8, NB), accumulate into out via atomics
__global__ void k_attpool2(const float* __restrict__ hp, const float* __restrict__ gt,
                           const float* __restrict__ gmi, float* __restrict__ out,
                           int npg) {
    int b = blockIdx.y, t = threadIdx.x;
    int chunk = npg >> 3;
    int i0 = blockIdx.x * chunk;
    float mx = gmi[b * 2], inv = gmi[b * 2 + 1];
    const float* g = gt + b * npg + i0;
    const float* hb = hp + ((size_t)b * npg + i0) * FHC;
    float a = 0.f;
    for (int i = 0; i < chunk; i++)
        a = fmaf(expf(g[i] - mx), hb[(size_t)i * FHC + t], a);
    atomicAdd(&out[b * FHC + t], a * inv);
}

// ---------------- host side ----------------

extern "C" void kernel_launch(void* const* d_in, const int* in_sizes, int n_in,
                              void* d_out, int out_size) {
    const float* x        = (const float*)d_in[0];
    const void*  ei       = d_in[1];
    const float* lin0_w   = (const float*)d_in[2];
    const float* lin0_b   = (const float*)d_in[3];
    const float* gat0_W   = (const float*)d_in[4];
    const float* gat0_as  = (const float*)d_in[5];
    const float* gat0_ad  = (const float*)d_in[6];
    const float* gat0_b   = (const float*)d_in[7];
    const float* pool0_w  = (const float*)d_in[8];
    const float* gat1_W   = (const float*)d_in[9];
    const float* gat1_as  = (const float*)d_in[10];
    const float* gat1_ad  = (const float*)d_in[11];
    const float* gat1_b   = (const float*)d_in[12];
    const float* pool1_w  = (const float*)d_in[13];
    const float* gate_w   = (const float*)d_in[14];
    const float* gate_b   = (const float*)d_in[15];
    float* out = (float*)d_out;

    float *h0, *h1, *ho, *hp, *hp2, *wsp, *as_, *ad_, *sc, *th, *gt, *gmi;
    int *s0, *d0, *s1, *d1, *deg, *off, *cur, *csr, *pm, *nid, *bs;
    unsigned char* v1;
    cudaGetSymbolAddress((void**)&h0, g_h0);
    cudaGetSymbolAddress((void**)&h1, g_h1);
    cudaGetSymbolAddress((void**)&ho, g_ho);
    cudaGetSymbolAddress((void**)&hp, g_hp);
    cudaGetSymbolAddress((void**)&hp2, g_hp2);
    cudaGetSymbolAddress((void**)&wsp, g_wsp);
    cudaGetSymbolAddress((void**)&as_, g_as);
    cudaGetSymbolAddress((void**)&ad_, g_ad);
    cudaGetSymbolAddress((void**)&sc, g_sc);
    cudaGetSymbolAddress((void**)&th, g_th);
    cudaGetSymbolAddress((void**)&gt, g_gt);
    cudaGetSymbolAddress((void**)&gmi, g_gmi);
    cudaGetSymbolAddress((void**)&s0, g_s0);
    cudaGetSymbolAddress((void**)&d0, g_d0);
    cudaGetSymbolAddress((void**)&s1, g_s1);
    cudaGetSymbolAddress((void**)&d1, g_d1);
    cudaGetSymbolAddress((void**)&deg, g_deg);
    cudaGetSymbolAddress((void**)&off, g_off);
    cudaGetSymbolAddress((void**)&cur, g_cur);
    cudaGetSymbolAddress((void**)&csr, g_csr);
    cudaGetSymbolAddress((void**)&pm, g_pm);
    cudaGetSymbolAddress((void**)&nid, g_nid);
    cudaGetSymbolAddress((void**)&bs, g_bs);
    cudaGetSymbolAddress((void**)&v1, g_v1);

    cudaFuncSetAttribute(k_gemm_tc, cudaFuncAttributeMaxDynamicSharedMemorySize,
                         SMEM_GEMM);

    static cudaStream_t s2 = nullptr;
    static cudaEvent_t evF0, evS0, evT0, evP0, evS1, evA0;
    if (!s2) {
        cudaStreamCreateWithFlags(&s2, cudaStreamNonBlocking);
        cudaEventCreateWithFlags(&evF0, cudaEventDisableTiming);
        cudaEventCreateWithFlags(&evS0, cudaEventDisableTiming);
        cudaEventCreateWithFlags(&evT0, cudaEventDisableTiming);
        cudaEventCreateWithFlags(&evP0, cudaEventDisableTiming);
        cudaEventCreateWithFlags(&evS1, cudaEventDisableTiming);
        cudaEventCreateWithFlags(&evA0, cudaEventDisableTiming);
    }

    const int EB = divup(E0, 256);

    // ---- main: output zero + weight presplit (roots of the capture graph) ----
    k_zerof<<<divup(NB * FHC, 256), 256>>>(out, NB * FHC);
    k_wsplit<<<divup(163840, 256), 256>>>(lin0_w, gat0_W, gat1_W, wsp);

    // fork side stream: edge decode + CSR build for GAT0
    cudaEventRecord(evF0, 0);
    cudaStreamWaitEvent(s2, evF0, 0);
    k_detect<<<1, 1, 0, s2>>>((const int*)ei);
    k_fill<<<divup(N0, 256), 256, 0, s2>>>(deg, 0, N0);
    k_edges_deg<<<EB, 256, 0, s2>>>(ei, s0, d0, deg, E0);
    k_scan1<<<N0 / 1024, 1024, 0, s2>>>(deg, off, bs, N0);
    k_scan2<<<1, 1, 0, s2>>>(bs, N0 / 1024, off, N0);
    k_scan3<<<N0 / 1024, 1024, 0, s2>>>(off, bs, cur, N0);
    k_escatter<<<EB, 256, 0, s2>>>(s0, d0, nullptr, cur, csr, E0);
    cudaEventRecord(evS0, s2);

    // ---- main: lin0 (K=128 + rank-1 for col 128) + GAT0 GEMM ----
    k_gemm_tc<<<dim3(1, N0 / 128), 512, SMEM_GEMM>>>(
        x, wsp, wsp + 65536, lin0_b, h0, N0, 128, 256, 1, 129,
        x + 128, lin0_w + 128 * 256, nullptr, nullptr, nullptr, nullptr);
    k_gemm_tc<<<dim3(1, N0 / 128), 512, SMEM_GEMM>>>(
        h0, wsp + 131072, wsp + 196608, nullptr, h1, N0, 256, 256, 0, 256,
        nullptr, nullptr, gat0_as, gat0_ad, as_, ad_);

    // join: gather0 needs CSR + h1/as_/ad_
    cudaStreamWaitEvent(0, evS0, 0);
    k_gather<<<divup(N0, 8), 256>>>(h1, off, csr, as_, ad_, gat0_b, pool0_w, ho, sc, N0);

    // TopK pool 0
    k_topk<<<NB, 1024>>>(sc, 2048, 1024, pm, th, nid);
    cudaEventRecord(evT0, 0);
    k_poolfeat<<<divup((N0 / 2) * 32, 256), 256>>>(ho, pm, th, gate_w, gate_b, hp, gt, N0 / 2);
    cudaEventRecord(evP0, 0);

    // side: CSR build for GAT1 (needs nid), then attpool0 (needs hp/gt)
    cudaStreamWaitEvent(s2, evT0, 0);
    k_fill<<<divup(N0 / 2, 256), 256, 0, s2>>>(deg, 0, N0 / 2);
    k_remap_deg<<<EB, 256, 0, s2>>>(s0, d0, nid, s1, d1, v1, deg, E0);
    k_scan1<<<(N0 / 2) / 1024, 1024, 0, s2>>>(deg, off, bs, N0 / 2);
    k_scan2<<<1, 1, 0, s2>>>(bs, (N0 / 2) / 1024, off, N0 / 2);
    k_scan3<<<(N0 / 2) / 1024, 1024, 0, s2>>>(off, bs, cur, N0 / 2);
    k_escatter<<<EB, 256, 0, s2>>>(s1, d1, v1, cur, csr, E0);
    cudaEventRecord(evS1, s2);
    cudaStreamWaitEvent(s2, evP0, 0);
    k_gmax<<<1, 1024, 0, s2>>>(gt, gmi, 1024);
    k_attpool2<<<dim3(8, NB), 256, 0, s2>>>(hp, gt, gmi, out, 1024);
    cudaEventRecord(evA0, s2);

    // ---- main: GAT1 GEMM (overlaps side CSR + attpool0) ----
    k_gemm_tc<<<dim3(1, (N0 / 2) / 128), 512, SMEM_GEMM>>>(
        hp, wsp + 262144, wsp + 327680, nullptr, h1, N0 / 2, 256, 256, 0, 256,
        nullptr, nullptr, gat1_as, gat1_ad, as_, ad_);
    cudaStreamWaitEvent(0, evS1, 0);
    k_gather<<<divup(N0 / 2, 8), 256>>>(h1, off, csr, as_, ad_, gat1_b, pool1_w, ho, sc, N0 / 2);

    // TopK pool 1
    k_topk<<<NB, 1024>>>(sc, 1024, 512, pm, th, nid);
    k_poolfeat<<<divup((N0 / 4) * 32, 256), 256>>>(ho, pm, th, gate_w, gate_b, hp2, gt, N0 / 4);

    // AttPool 1 -> out (+=); join attpool0 branch before final adds
    cudaStreamWaitEvent(0, evA0, 0);
    k_gmax<<<1, 1024>>>(gt, gmi, 512);
    k_attpool2<<<dim3(8, NB), 256>>>(hp2, gt, gmi, out, 512);
}

// round 11
// speedup vs baseline: 2.9888x; 1.5453x over previous
#include <cuda_runtime.h>
#include <math.h>
#include <stdint.h>

#define N0  65536     // total nodes
#define E0  524288    // total edges
#define NB  32        // graphs
#define FHC 256       // feature width (H*C)

// ---------------- static device scratch ----------------
__device__ float g_h0[(size_t)N0 * FHC];
__device__ float g_h1[(size_t)N0 * FHC];
__device__ float g_ho[(size_t)N0 * FHC];
__device__ float g_hp[(size_t)(N0 / 2) * FHC];
__device__ float g_hp2[(size_t)(N0 / 4) * FHC];
__device__ float g_wsp[6 * 65536];   // presplit weights: lin0 hi/lo, gat0 hi/lo, gat1 hi/lo
__device__ float g_as[N0 * 4], g_ad[N0 * 4];
__device__ float g_sc[N0];
__device__ float g_th[N0 / 2];
__device__ float g_gt[N0 / 2];
__device__ int g_s0[E0], g_d0[E0], g_s1[E0], g_d1[E0];
__device__ unsigned char g_v1[E0];
__device__ int g_deg[N0], g_off[N0 + 1], g_cur[N0], g_csr[E0];
__device__ int g_bs[64];             // lookback flags (value = chunk total + 1)
__device__ int g_pm[N0 / 2], g_nid[N0];
__device__ int g_is64;

static inline int divup(int a, int b) { return (a + b - 1) / b; }

__device__ __forceinline__ float lrelu(float z) { return z > 0.f ? z : 0.2f * z; }

// ---------------- tf32 helpers ----------------
__device__ __forceinline__ void tf32split(float x, uint32_t& hi, uint32_t& lo) {
    asm("cvt.rna.tf32.f32 %0, %1;" : "=r"(hi) : "f"(x));
    float r = x - __uint_as_float(hi);
    asm("cvt.rna.tf32.f32 %0, %1;" : "=r"(lo) : "f"(r));
}

#define MMA_TF32(d, a, b0, b1)                                                   \
    asm volatile(                                                                \
        "mma.sync.aligned.m16n8k8.row.col.f32.tf32.tf32.f32 "                    \
        "{%0,%1,%2,%3},{%4,%5,%6,%7},{%8,%9},{%0,%1,%2,%3};"                     \
        : "+f"(d[0]), "+f"(d[1]), "+f"(d[2]), "+f"(d[3])                         \
        : "r"(a[0]), "r"(a[1]), "r"(a[2]), "r"(a[3]), "r"(b0), "r"(b1))

__device__ __forceinline__ void cpa16(uint32_t dst, const void* src) {
    asm volatile("cp.async.cg.shared.global [%0], [%1], 16;" :: "r"(dst), "l"(src));
}
__device__ __forceinline__ void cpa4(uint32_t dst, const void* src) {
    asm volatile("cp.async.ca.shared.global [%0], [%1], 4;" :: "r"(dst), "l"(src));
}

// ---------------- kernels ----------------

__global__ void k_detect(const int* __restrict__ w) {
    int nz = 0;
    for (int i = 1; i < 128; i += 2) nz |= (w[i] != 0);
    g_is64 = nz ? 0 : 1;
}

// split all three weight matrices into tf32 hi/lo (one pass)
__global__ void k_wsplit(const float* __restrict__ w0, const float* __restrict__ w1,
                         const float* __restrict__ w2, float* __restrict__ wsp) {
    int i = blockIdx.x * blockDim.x + threadIdx.x;
    const float* src;
    float *hi, *lo;
    int li;
    if (i < 32768)        { src = w0; li = i;          hi = wsp;            lo = wsp + 65536; }
    else if (i < 98304)   { src = w1; li = i - 32768;  hi = wsp + 131072;   lo = wsp + 196608; }
    else if (i < 163840)  { src = w2; li = i - 98304;  hi = wsp + 262144;   lo = wsp + 327680; }
    else return;
    uint32_t h, l;
    tf32split(src[li], h, l);
    hi[li] = __uint_as_float(h);
    lo[li] = __uint_as_float(l);
}

// decode edges + count in-degrees (fused)
__global__ void k_edges_deg(const void* __restrict__ ei, int* __restrict__ s,
                            int* __restrict__ d, int* __restrict__ deg, int E) {
    int i = blockIdx.x * blockDim.x + threadIdx.x;
    if (i >= E) return;
    int sv, dv;
    if (g_is64) {
        const long long* p = (const long long*)ei;
        sv = (int)p[i];
        dv = (int)p[E + i];
    } else {
        const int* p = (const int*)ei;
        sv = p[i];
        dv = p[E + i];
    }
    s[i] = sv; d[i] = dv;
    atomicAdd(&deg[dv], 1);
}

// Tensor-core GEMM, 3xTF32. B (weights) presplit in global hi/lo; A split
// in registers. Double-buffered cp.async. Block tile 128x256, BK=32,
// 512 threads; grid (1, M/128); K % 32 == 0; N == 256.
#define AP 36
#define BP 260
#define ABUF (128 * AP)
#define BBUF (32 * BP)
#define SBUF (ABUF + 2 * BBUF)
#define SMEM_GEMM (2 * SBUF * 4)
__global__ void __launch_bounds__(512, 1)
k_gemm_tc(const float* __restrict__ A, const float* __restrict__ Bh,
          const float* __restrict__ Bl,
          const float* __restrict__ bias, float* __restrict__ Cm,
          int M, int K, int N, int act, int Kld,
          const float* __restrict__ a1col, const float* __restrict__ b1row,
          const float* __restrict__ aS, const float* __restrict__ aD,
          float* __restrict__ as_, float* __restrict__ ad_) {
    extern __shared__ float smg[];
    int t = threadIdx.x;
    int lane = t & 31, w = t >> 5;
    int g = lane >> 2, tig = lane & 3;
    int wm = w & 3, wn = w >> 2;
    int row0 = blockIdx.y * 128;
    int nk = K >> 5;
    bool al16 = (Kld & 3) == 0;

    float acc[2][8][4];
#pragma unroll
    for (int i = 0; i < 2; i++)
#pragma unroll
        for (int j = 0; j < 8; j++)
#pragma unroll
            for (int q = 0; q < 4; q++) acc[i][j][q] = 0.f;

    auto copy_tile = [&](int ti, int bf) {
        float* As  = smg + bf * SBUF;
        float* Bsh = As + ABUF;
        float* Bsl = Bsh + BBUF;
#pragma unroll
        for (int it = 0; it < 2; it++) {
            int lin = t + 512 * it;
            int r = lin >> 3, c4 = (lin & 7) * 4;
            const float* src = &A[(size_t)(row0 + r) * Kld + ti * 32 + c4];
            uint32_t dst = (uint32_t)__cvta_generic_to_shared(&As[r * AP + c4]);
            if (al16) {
                cpa16(dst, src);
            } else {
#pragma unroll
                for (int j = 0; j < 4; j++) cpa4(dst + j * 4, src + j);
            }
        }
#pragma unroll
        for (int it = 0; it < 4; it++) {
            int lin = t + 512 * it;
            int kk = lin >> 6, c4 = (lin & 63) * 4;
            size_t gsrc = (size_t)(ti * 32 + kk) * N + c4;
            cpa16((uint32_t)__cvta_generic_to_shared(&Bsh[kk * BP + c4]), &Bh[gsrc]);
            cpa16((uint32_t)__cvta_generic_to_shared(&Bsl[kk * BP + c4]), &Bl[gsrc]);
        }
    };

    copy_tile(0, 0);
    asm volatile("cp.async.commit_group;");

    for (int ti = 0; ti < nk; ti++) {
        if (ti + 1 < nk) {
            copy_tile(ti + 1, (ti + 1) & 1);
            asm volatile("cp.async.commit_group;");
            asm volatile("cp.async.wait_group 1;");
        } else {
            asm volatile("cp.async.wait_group 0;");
        }
        __syncthreads();
        const float* As  = smg + (ti & 1) * SBUF;
        const float* Bsh = As + ABUF;
        const float* Bsl = Bsh + BBUF;
#pragma unroll
        for (int ks = 0; ks < 4; ks++) {
            int k8 = ks * 8;
            uint32_t ah[2][4], al[2][4];
#pragma unroll
            for (int mt = 0; mt < 2; mt++) {
                int bm = wm * 32 + mt * 16 + g;
                tf32split(As[bm * AP + k8 + tig],           ah[mt][0], al[mt][0]);
                tf32split(As[(bm + 8) * AP + k8 + tig],     ah[mt][1], al[mt][1]);
                tf32split(As[bm * AP + k8 + tig + 4],       ah[mt][2], al[mt][2]);
                tf32split(As[(bm + 8) * AP + k8 + tig + 4], ah[mt][3], al[mt][3]);
            }
#pragma unroll
            for (int nt = 0; nt < 8; nt++) {
                int bn = wn * 64 + nt * 8 + g;
                uint32_t b0h = __float_as_uint(Bsh[(k8 + tig) * BP + bn]);
                uint32_t b1h = __float_as_uint(Bsh[(k8 + tig + 4) * BP + bn]);
                uint32_t b0l = __float_as_uint(Bsl[(k8 + tig) * BP + bn]);
                uint32_t b1l = __float_as_uint(Bsl[(k8 + tig + 4) * BP + bn]);
#pragma unroll
                for (int mt = 0; mt < 2; mt++) {
                    MMA_TF32(acc[mt][nt], ah[mt], b0h, b1h);
                    MMA_TF32(acc[mt][nt], ah[mt], b0l, b1l);
                    MMA_TF32(acc[mt][nt], al[mt], b0h, b1h);
                }
            }
        }
        __syncthreads();
    }

#pragma unroll
    for (int mt = 0; mt < 2; mt++) {
        int r = row0 + wm * 32 + mt * 16 + g;
        float ar0 = a1col ? a1col[(size_t)r * Kld] : 0.f;
        float ar8 = a1col ? a1col[(size_t)(r + 8) * Kld] : 0.f;
#pragma unroll
        for (int nt = 0; nt < 8; nt++) {
            int cc = wn * 64 + nt * 8 + tig * 2;
            float bb0 = a1col ? b1row[cc] : 0.f, bb1 = a1col ? b1row[cc + 1] : 0.f;
            float b0 = bias ? bias[cc] : 0.f, b1 = bias ? bias[cc + 1] : 0.f;
            float v0 = acc[mt][nt][0] + ar0 * bb0 + b0;
            float v1 = acc[mt][nt][1] + ar0 * bb1 + b1;
            float v2 = acc[mt][nt][2] + ar8 * bb0 + b0;
            float v3 = acc[mt][nt][3] + ar8 * bb1 + b1;
            if (act) {
                v0 = fmaxf(v0, 0.f); v1 = fmaxf(v1, 0.f);
                v2 = fmaxf(v2, 0.f); v3 = fmaxf(v3, 0.f);
            }
            float2 p0 = {v0, v1}, p1 = {v2, v3};
            *(float2*)&Cm[(size_t)r * N + cc] = p0;
            *(float2*)&Cm[(size_t)(r + 8) * N + cc] = p1;
        }
    }

    if (aS) {
        const float* ws = aS + wn * 64;
        const float* wd = aD + wn * 64;
#pragma unroll
        for (int mt = 0; mt < 2; mt++) {
            float s0 = 0.f, d0 = 0.f, s1 = 0.f, d1 = 0.f;
#pragma unroll
            for (int nt = 0; nt < 8; nt++) {
                int c = nt * 8 + tig * 2;
                float w0 = ws[c], w1 = ws[c + 1];
                float u0 = wd[c], u1 = wd[c + 1];
                s0 = fmaf(acc[mt][nt][0], w0, fmaf(acc[mt][nt][1], w1, s0));
                d0 = fmaf(acc[mt][nt][0], u0, fmaf(acc[mt][nt][1], u1, d0));
                s1 = fmaf(acc[mt][nt][2], w0, fmaf(acc[mt][nt][3], w1, s1));
                d1 = fmaf(acc[mt][nt][2], u0, fmaf(acc[mt][nt][3], u1, d1));
            }
#pragma unroll
            for (int o = 1; o <= 2; o <<= 1) {
                s0 += __shfl_xor_sync(0xffffffffu, s0, o);
                d0 += __shfl_xor_sync(0xffffffffu, d0, o);
                s1 += __shfl_xor_sync(0xffffffffu, s1, o);
                d1 += __shfl_xor_sync(0xffffffffu, d1, o);
            }
            if (tig == 0) {
                int r = row0 + wm * 32 + mt * 16 + g;
                as_[r * 4 + wn] = s0; ad_[r * 4 + wn] = d0;
                as_[(r + 8) * 4 + wn] = s1; ad_[(r + 8) * 4 + wn] = d1;
            }
        }
    }
}

// single-pass exclusive scan with decoupled lookback; nb = gridDim.x <= 64.
// bflag must be zeroed before launch; flag value = chunk total + 1.
// Blocks wait only on lower block-ids -> progress guaranteed.
__global__ void __launch_bounds__(1024) k_scanF(const int* __restrict__ in,
                                                int* __restrict__ off,
                                                int* __restrict__ cur,
                                                int* __restrict__ bflag, int n) {
    __shared__ int sm[1024];
    __shared__ int spre;
    int t = threadIdx.x, b = blockIdx.x;
    int i = b * 1024 + t;
    int v = (i < n) ? in[i] : 0;
    sm[t] = v;
    __syncthreads();
    for (int o = 1; o < 1024; o <<= 1) {
        int u = (t >= o) ? sm[t - o] : 0;
        __syncthreads();
        sm[t] += u;
        __syncthreads();
    }
    if (t == 0) { spre = 0; atomicExch(&bflag[b], sm[1023] + 1); }
    __syncthreads();
    if (t < b) {
        int f;
        do { f = atomicAdd(&bflag[t], 0); } while (f == 0);
        atomicAdd(&spre, f - 1);
    }
    __syncthreads();
    int exc = spre + sm[t] - v;
    if (i < n) { off[i] = exc; cur[i] = exc; }
    if (b == gridDim.x - 1 && t == 1023) off[n] = spre + sm[1023];
}

__global__ void k_escatter(const int* __restrict__ s, const int* __restrict__ d,
                           const unsigned char* __restrict__ val, int* __restrict__ cur,
                           int* __restrict__ csr, int E) {
    int e = blockIdx.x * blockDim.x + threadIdx.x;
    if (e >= E) return;
    if (val && !val[e]) return;
    int p = atomicAdd(&cur[d[e]], 1);
    csr[p] = s[e];
}

// Fused GAT aggregation + topk score: warp per dst node. Softmax without
// max-shift (shift-invariant; logits O(10), exp safe in fp32), 4-way MLP.
__global__ void k_gather(const float* __restrict__ h1, const int* __restrict__ off,
                         const int* __restrict__ csr,
                         const float* __restrict__ as_, const float* __restrict__ ad_,
                         const float* __restrict__ bias, const float* __restrict__ pw,
                         float* __restrict__ out, float* __restrict__ sc, int n) {
    int wp = (blockIdx.x * blockDim.x + threadIdx.x) >> 5;
    if (wp >= n) return;
    int lane = threadIdx.x & 31;
    int head = lane >> 3;
    int d = wp;
    float adh = ad_[d * 4 + head];
    float w0s = expf(lrelu(as_[d * 4 + head] + adh));   // self loop
    float den = w0s;
    float acc[8];
    {
        const float4* p = (const float4*)(h1 + (size_t)d * FHC + lane * 8);
        float4 x0 = p[0], x1 = p[1];
        acc[0] = w0s * x0.x; acc[1] = w0s * x0.y; acc[2] = w0s * x0.z; acc[3] = w0s * x0.w;
        acc[4] = w0s * x1.x; acc[5] = w0s * x1.y; acc[6] = w0s * x1.z; acc[7] = w0s * x1.w;
    }
    int e = off[d], e1 = off[d + 1];
    for (; e + 3 < e1; e += 4) {
        int sv[4];
        float wgt[4];
        float4 f0[4], f1[4];
#pragma unroll
        for (int i = 0; i < 4; i++) sv[i] = csr[e + i];
#pragma unroll
        for (int i = 0; i < 4; i++) {
            wgt[i] = expf(lrelu(as_[sv[i] * 4 + head] + adh));
            const float4* p = (const float4*)(h1 + (size_t)sv[i] * FHC + lane * 8);
            f0[i] = p[0]; f1[i] = p[1];
        }
#pragma unroll
        for (int i = 0; i < 4; i++) {
            den += wgt[i];
            acc[0] = fmaf(wgt[i], f0[i].x, acc[0]);
            acc[1] = fmaf(wgt[i], f0[i].y, acc[1]);
            acc[2] = fmaf(wgt[i], f0[i].z, acc[2]);
            acc[3] = fmaf(wgt[i], f0[i].w, acc[3]);
            acc[4] = fmaf(wgt[i], f1[i].x, acc[4]);
            acc[5] = fmaf(wgt[i], f1[i].y, acc[5]);
            acc[6] = fmaf(wgt[i], f1[i].z, acc[6]);
            acc[7] = fmaf(wgt[i], f1[i].w, acc[7]);
        }
    }
    for (; e < e1; e++) {
        int s = csr[e];
        float w = expf(lrelu(as_[s * 4 + head] + adh));
        den += w;
        const float4* p = (const float4*)(h1 + (size_t)s * FHC + lane * 8);
        float4 x0 = p[0], x1 = p[1];
        acc[0] = fmaf(w, x0.x, acc[0]);
        acc[1] = fmaf(w, x0.y, acc[1]);
        acc[2] = fmaf(w, x0.z, acc[2]);
        acc[3] = fmaf(w, x0.w, acc[3]);
        acc[4] = fmaf(w, x1.x, acc[4]);
        acc[5] = fmaf(w, x1.y, acc[5]);
        acc[6] = fmaf(w, x1.z, acc[6]);
        acc[7] = fmaf(w, x1.w, acc[7]);
    }
    float inv = 1.f / (den + 1e-16f);
    int cb = lane * 8;
    float4 o0, o1;
    float v;
    v = acc[0] * inv + bias[cb + 0]; o0.x = v > 0.f ? v : expm1f(v);
    v = acc[1] * inv + bias[cb + 1]; o0.y = v > 0.f ? v : expm1f(v);
    v = acc[2] * inv + bias[cb + 2]; o0.z = v > 0.f ? v : expm1f(v);
    v = acc[3] * inv + bias[cb + 3]; o0.w = v > 0.f ? v : expm1f(v);
    v = acc[4] * inv + bias[cb + 4]; o1.x = v > 0.f ? v : expm1f(v);
    v = acc[5] * inv + bias[cb + 5]; o1.y = v > 0.f ? v : expm1f(v);
    v = acc[6] * inv + bias[cb + 6]; o1.z = v > 0.f ? v : expm1f(v);
    v = acc[7] * inv + bias[cb + 7]; o1.w = v > 0.f ? v : expm1f(v);
    float4* po = (float4*)(out + (size_t)d * FHC + cb);
    __stcs(po, o0);
    __stcs(po + 1, o1);
    const float4* pwp = (const float4*)(pw + cb);
    float4 w0 = pwp[0], w1 = pwp[1];
    float sp = o0.x * w0.x + o0.y * w0.y + o0.z * w0.z + o0.w * w0.w +
               o1.x * w1.x + o1.y * w1.y + o1.z * w1.z + o1.w * w1.w;
    float n2 = w0.x * w0.x + w0.y * w0.y + w0.z * w0.z + w0.w * w0.w +
               w1.x * w1.x + w1.y * w1.y + w1.z * w1.z + w1.w * w1.w;
#pragma unroll
    for (int o = 16; o; o >>= 1) {
        sp += __shfl_xor_sync(0xffffffffu, sp, o);
        n2 += __shfl_xor_sync(0xffffffffu, n2, o);
    }
    if (!lane) sc[d] = sp / (sqrtf(n2) + 1e-16f);
}

// exact top-k per graph via 4-pass radix select on sortable uint keys.
// Selection set identical to reference (threshold + earliest-index among ties);
// compaction order (greater-first, then ties by index) is irrelevant downstream.
__global__ void __launch_bounds__(1024) k_topk(const float* __restrict__ score, int n_in,
                                               int k, int* __restrict__ perm,
                                               float* __restrict__ tanhv,
                                               int* __restrict__ newid) {
    __shared__ unsigned su[2048];
    __shared__ int hist[256];
    __shared__ int sscan[1024];
    __shared__ unsigned s_thr;
    __shared__ int s_kk;
    __shared__ int s_totgt;
    int b = blockIdx.x, t = threadIdx.x;
    const float* s = score + b * n_in;
    int per = n_in >> 10;  // 1 or 2
    for (int i = t; i < n_in; i += 1024) {
        unsigned u = __float_as_uint(s[i]);
        su[i] = (u & 0x80000000u) ? ~u : (u | 0x80000000u);
    }
    __syncthreads();
    unsigned prefix = 0u;
    int kk = k;
    for (int pass = 0; pass < 4; pass++) {
        int shift = 24 - 8 * pass;
        unsigned pmask = pass ? (0xFFFFFFFFu << (shift + 8)) : 0u;
        if (t < 256) hist[t] = 0;
        __syncthreads();
        for (int i = t; i < n_in; i += 1024) {
            unsigned u = su[i];
            if ((u & pmask) == (prefix & pmask))
                atomicAdd(&hist[(u >> shift) & 0xFFu], 1);
        }
        __syncthreads();
        if (t == 0) {
            int acc = 0, d = 255;
            for (; d > 0; d--) {
                int c = hist[d];
                if (acc + c >= kk) break;
                acc += c;
            }
            s_thr = (prefix & pmask) | ((unsigned)d << shift);
            s_kk = kk - acc;
        }
        __syncthreads();
        prefix = s_thr;
        kk = s_kk;
        __syncthreads();
    }
    unsigned T = prefix;   // exact k-th key; kk = count of ==T to keep (earliest)
    // per-thread flags (index order: idx = t*per+q)
    int isgt[2] = {0, 0}, iseq[2] = {0, 0};
    int keepc = 0, eqc = 0;
    for (int q = 0; q < 2; q++) {
        if (q < per) {
            unsigned u = su[t * per + q];
            isgt[q] = (u > T);
            iseq[q] = (u == T);
            keepc += isgt[q];
            eqc += iseq[q];
        }
    }
    sscan[t] = (eqc << 16) | keepc;
    __syncthreads();
    for (int o = 1; o < 1024; o <<= 1) {
        int u = (t >= o) ? sscan[t - o] : 0;
        __syncthreads();
        sscan[t] += u;
        __syncthreads();
    }
    int packed_exc = sscan[t] - ((eqc << 16) | keepc);
    int gtpos = packed_exc & 0xFFFF;
    int eqrank = packed_exc >> 16;
    if (t == 1023) s_totgt = sscan[1023] & 0xFFFF;
    __syncthreads();
    int totgt = s_totgt;
    for (int q = 0; q < per; q++) {
        int idx = t * per + q;
        int old = b * n_in + idx;
        bool kept = false;
        int pos = 0;
        if (isgt[q]) {
            kept = true; pos = gtpos; gtpos++;
        } else if (iseq[q]) {
            kept = (eqrank < kk); pos = totgt + eqrank; eqrank++;
        }
        if (kept) {
            int np = b * k + pos;
            perm[np] = old;
            tanhv[np] = tanhf(s[idx]);
            newid[old] = np;
        } else {
            newid[old] = -1;
        }
    }
}

// warp per pooled node: hp = h[perm]*tanh, fused gate = <hp_row, gate_w> + b
__global__ void k_poolfeat(const float* __restrict__ h, const int* __restrict__ pm,
                           const float* __restrict__ th, const float* __restrict__ gw,
                           const float* __restrict__ gb, float* __restrict__ hp,
                           float* __restrict__ gt, int m) {
    int wp = (blockIdx.x * blockDim.x + threadIdx.x) >> 5;
    if (wp >= m) return;
    int lane = threadIdx.x & 31;
    int srcn = pm[wp];
    float tv = th[wp];
    int cb = lane * 8;
    const float4* p = (const float4*)(h + (size_t)srcn * FHC + cb);
    float4 a = p[0], b = p[1];
    a.x *= tv; a.y *= tv; a.z *= tv; a.w *= tv;
    b.x *= tv; b.y *= tv; b.z *= tv; b.w *= tv;
    float4* po = (float4*)(hp + (size_t)wp * FHC + cb);
    po[0] = a; po[1] = b;
    const float4* g4 = (const float4*)(gw + cb);
    float4 w0 = g4[0], w1 = g4[1];
    float s = a.x * w0.x + a.y * w0.y + a.z * w0.z + a.w * w0.w +
              b.x * w1.x + b.y * w1.y + b.z * w1.z + b.w * w1.w;
#pragma unroll
    for (int o = 16; o; o >>= 1) s += __shfl_xor_sync(0xffffffffu, s, o);
    if (!lane) gt[wp] = s + gb[0];
}

// remap edges to pooled ids + count pooled in-degrees (fused)
__global__ void k_remap_deg(const int* __restrict__ si, const int* __restrict__ di,
                            const int* __restrict__ nid, int* __restrict__ so,
                            int* __restrict__ dq, unsigned char* __restrict__ vo,
                            int* __restrict__ deg, int E) {
    int e = blockIdx.x * blockDim.x + threadIdx.x;
    if (e >= E) return;
    int ns = nid[si[e]], nd = nid[di[e]];
    bool v = (ns >= 0) && (nd >= 0);
    so[e] = v ? ns : 0;
    dq[e] = v ? nd : 0;
    vo[e] = v ? 1 : 0;
    if (v) atomicAdd(&deg[nd], 1);
}

// attentional pooling with in-kernel softmax stats: grid (8, NB); each block
// recomputes the per-graph (max, sum) over the gate vector (cheap) then
// accumulates its 1/8 chunk of the weighted feature sum into out via atomics.
__global__ void k_attpool2(const float* __restrict__ hp, const float* __restrict__ gt,
                           float* __restrict__ out, int npg) {
    __shared__ float red[256];
    int b = blockIdx.y, t = threadIdx.x;
    const float* g = gt + b * npg;
    float mxv = -1e30f;
    for (int i = t; i < npg; i += 256) mxv = fmaxf(mxv, g[i]);
    red[t] = mxv;
    __syncthreads();
    for (int o = 128; o; o >>= 1) { if (t < o) red[t] = fmaxf(red[t], red[t + o]); __syncthreads(); }
    float m = red[0];
    __syncthreads();
    float sum = 0.f;
    for (int i = t; i < npg; i += 256) sum += expf(g[i] - m);
    red[t] = sum;
    __syncthreads();
    for (int o = 128; o; o >>= 1) { if (t < o) red[t] += red[t + o]; __syncthreads(); }
    float inv = 1.f / red[0];
    int chunk = npg >> 3;
    int i0 = blockIdx.x * chunk;
    const float* hb = hp + ((size_t)b * npg + i0) * FHC;
    float a = 0.f;
    for (int i = 0; i < chunk; i++)
        a = fmaf(expf(g[i0 + i] - m), hb[(size_t)i * FHC + t], a);
    atomicAdd(&out[b * FHC + t], a * inv);
}

// ---------------- host side ----------------

extern "C" void kernel_launch(void* const* d_in, const int* in_sizes, int n_in,
                              void* d_out, int out_size) {
    const float* x        = (const float*)d_in[0];
    const void*  ei       = d_in[1];
    const float* lin0_w   = (const float*)d_in[2];
    const float* lin0_b   = (const float*)d_in[3];
    const float* gat0_W   = (const float*)d_in[4];
    const float* gat0_as  = (const float*)d_in[5];
    const float* gat0_ad  = (const float*)d_in[6];
    const float* gat0_b   = (const float*)d_in[7];
    const float* pool0_w  = (const float*)d_in[8];
    const float* gat1_W   = (const float*)d_in[9];
    const float* gat1_as  = (const float*)d_in[10];
    const float* gat1_ad  = (const float*)d_in[11];
    const float* gat1_b   = (const float*)d_in[12];
    const float* pool1_w  = (const float*)d_in[13];
    const float* gate_w   = (const float*)d_in[14];
    const float* gate_b   = (const float*)d_in[15];
    float* out = (float*)d_out;

    float *h0, *h1, *ho, *hp, *hp2, *wsp, *as_, *ad_, *sc, *th, *gt;
    int *s0, *d0, *s1, *d1, *deg, *off, *cur, *csr, *pm, *nid, *bs;
    unsigned char* v1;
    cudaGetSymbolAddress((void**)&h0, g_h0);
    cudaGetSymbolAddress((void**)&h1, g_h1);
    cudaGetSymbolAddress((void**)&ho, g_ho);
    cudaGetSymbolAddress((void**)&hp, g_hp);
    cudaGetSymbolAddress((void**)&hp2, g_hp2);
    cudaGetSymbolAddress((void**)&wsp, g_wsp);
    cudaGetSymbolAddress((void**)&as_, g_as);
    cudaGetSymbolAddress((void**)&ad_, g_ad);
    cudaGetSymbolAddress((void**)&sc, g_sc);
    cudaGetSymbolAddress((void**)&th, g_th);
    cudaGetSymbolAddress((void**)&gt, g_gt);
    cudaGetSymbolAddress((void**)&s0, g_s0);
    cudaGetSymbolAddress((void**)&d0, g_d0);
    cudaGetSymbolAddress((void**)&s1, g_s1);
    cudaGetSymbolAddress((void**)&d1, g_d1);
    cudaGetSymbolAddress((void**)&deg, g_deg);
    cudaGetSymbolAddress((void**)&off, g_off);
    cudaGetSymbolAddress((void**)&cur, g_cur);
    cudaGetSymbolAddress((void**)&csr, g_csr);
    cudaGetSymbolAddress((void**)&pm, g_pm);
    cudaGetSymbolAddress((void**)&nid, g_nid);
    cudaGetSymbolAddress((void**)&bs, g_bs);
    cudaGetSymbolAddress((void**)&v1, g_v1);

    cudaFuncSetAttribute(k_gemm_tc, cudaFuncAttributeMaxDynamicSharedMemorySize,
                         SMEM_GEMM);

    static cudaStream_t s2 = nullptr;
    static cudaEvent_t evF0, evS0, evT0, evP0, evS1, evA0;
    if (!s2) {
        cudaStreamCreateWithFlags(&s2, cudaStreamNonBlocking);
        cudaEventCreateWithFlags(&evF0, cudaEventDisableTiming);
        cudaEventCreateWithFlags(&evS0, cudaEventDisableTiming);
        cudaEventCreateWithFlags(&evT0, cudaEventDisableTiming);
        cudaEventCreateWithFlags(&evP0, cudaEventDisableTiming);
        cudaEventCreateWithFlags(&evS1, cudaEventDisableTiming);
        cudaEventCreateWithFlags(&evA0, cudaEventDisableTiming);
    }

    const int EB = divup(E0, 256);

    // ---- main: output zero (memset node) + weight presplit ----
    cudaMemsetAsync(out, 0, (size_t)NB * FHC * sizeof(float), 0);
    k_wsplit<<<divup(163840, 256), 256>>>(lin0_w, gat0_W, gat1_W, wsp);
    cudaEventRecord(evF0, 0);

    // ---- main: lin0 (K=128 + rank-1 for col 128) + GAT0 GEMM (launches 2-3) ----
    k_gemm_tc<<<dim3(1, N0 / 128), 512, SMEM_GEMM>>>(
        x, wsp, wsp + 65536, lin0_b, h0, N0, 128, 256, 1, 129,
        x + 128, lin0_w + 128 * 256, nullptr, nullptr, nullptr, nullptr);
    k_gemm_tc<<<dim3(1, N0 / 128), 512, SMEM_GEMM>>>(
        h0, wsp + 131072, wsp + 196608, nullptr, h1, N0, 256, 256, 0, 256,
        nullptr, nullptr, gat0_as, gat0_ad, as_, ad_);

    // side stream (executes concurrently with GEMMs): edge decode + CSR0
    cudaStreamWaitEvent(s2, evF0, 0);
    k_detect<<<1, 1, 0, s2>>>((const int*)ei);
    cudaMemsetAsync(deg, 0, (size_t)N0 * sizeof(int), s2);
    cudaMemsetAsync(bs, 0, 64 * sizeof(int), s2);
    k_edges_deg<<<EB, 256, 0, s2>>>(ei, s0, d0, deg, E0);
    k_scanF<<<N0 / 1024, 1024, 0, s2>>>(deg, off, cur, bs, N0);
    k_escatter<<<EB, 256, 0, s2>>>(s0, d0, nullptr, cur, csr, E0);
    cudaEventRecord(evS0, s2);

    // join: gather0 needs CSR + h1/as_/ad_
    cudaStreamWaitEvent(0, evS0, 0);
    k_gather<<<divup(N0, 8), 256>>>(h1, off, csr, as_, ad_, gat0_b, pool0_w, ho, sc, N0);

    // TopK pool 0 (radix select)
    k_topk<<<NB, 1024>>>(sc, 2048, 1024, pm, th, nid);
    cudaEventRecord(evT0, 0);
    k_poolfeat<<<divup((N0 / 2) * 32, 256), 256>>>(ho, pm, th, gate_w, gate_b, hp, gt, N0 / 2);
    cudaEventRecord(evP0, 0);

    // side: CSR build for GAT1 (needs nid), then attpool0 (needs hp/gt)
    cudaStreamWaitEvent(s2, evT0, 0);
    cudaMemsetAsync(deg, 0, (size_t)(N0 / 2) * sizeof(int), s2);
    cudaMemsetAsync(bs, 0, 64 * sizeof(int), s2);
    k_remap_deg<<<EB, 256, 0, s2>>>(s0, d0, nid, s1, d1, v1, deg, E0);
    k_scanF<<<(N0 / 2) / 1024, 1024, 0, s2>>>(deg, off, cur, bs, N0 / 2);
    k_escatter<<<EB, 256, 0, s2>>>(s1, d1, v1, cur, csr, E0);
    cudaEventRecord(evS1, s2);
    cudaStreamWaitEvent(s2, evP0, 0);
    k_attpool2<<<dim3(8, NB), 256, 0, s2>>>(hp, gt, out, 1024);
    cudaEventRecord(evA0, s2);

    // ---- main: GAT1 GEMM (overlaps side CSR + attpool0) ----
    k_gemm_tc<<<dim3(1, (N0 / 2) / 128), 512, SMEM_GEMM>>>(
        hp, wsp + 262144, wsp + 327680, nullptr, h1, N0 / 2, 256, 256, 0, 256,
        nullptr, nullptr, gat1_as, gat1_ad, as_, ad_);
    cudaStreamWaitEvent(0, evS1, 0);
    k_gather<<<divup(N0 / 2, 8), 256>>>(h1, off, csr, as_, ad_, gat1_b, pool1_w, ho, sc, N0 / 2);

    // TopK pool 1
    k_topk<<<NB, 1024>>>(sc, 1024, 512, pm, th, nid);
    k_poolfeat<<<divup((N0 / 4) * 32, 256), 256>>>(ho, pm, th, gate_w, gate_b, hp2, gt, N0 / 4);

    // AttPool 1 -> out (+=); join attpool0 branch before final adds
    cudaStreamWaitEvent(0, evA0, 0);
    k_attpool2<<<dim3(8, NB), 256>>>(hp2, gt, out, 512);
}

// round 12
// speedup vs baseline: 3.0522x; 1.0212x over previous
#include <cuda_runtime.h>
#include <math.h>
#include <stdint.h>

#define N0  65536     // total nodes
#define E0  524288    // total edges
#define NB  32        // graphs
#define FHC 256       // feature width (H*C)

// ---------------- static device scratch ----------------
__device__ float g_h0[(size_t)N0 * FHC];
__device__ float g_h1[(size_t)N0 * FHC];
__device__ float g_ho[(size_t)N0 * FHC];
__device__ float g_hp[(size_t)(N0 / 2) * FHC];
__device__ float g_hp2[(size_t)(N0 / 4) * FHC];
__device__ float g_wsp[6 * 65536];   // presplit weights: lin0 hi/lo, gat0 hi/lo, gat1 hi/lo
__device__ float g_as[N0 * 4], g_ad[N0 * 4];
__device__ float g_sc[N0];
__device__ float g_th[N0 / 2];
__device__ float g_gt[N0 / 2];
__device__ int g_s0[E0], g_d0[E0], g_s1[E0], g_d1[E0];
__device__ unsigned char g_v1[E0];
__device__ int g_deg[N0], g_off[N0 + 1], g_cur[N0], g_csr[E0];
__device__ int g_bs[64];             // lookback flags (value = chunk total + 1)
__device__ int g_pm[N0 / 2], g_nid[N0];
__device__ int g_is64;

static inline int divup(int a, int b) { return (a + b - 1) / b; }

__device__ __forceinline__ float lrelu(float z) { return z > 0.f ? z : 0.2f * z; }

// ---------------- tf32 helpers ----------------
__device__ __forceinline__ void tf32split(float x, uint32_t& hi, uint32_t& lo) {
    asm("cvt.rna.tf32.f32 %0, %1;" : "=r"(hi) : "f"(x));
    float r = x - __uint_as_float(hi);
    asm("cvt.rna.tf32.f32 %0, %1;" : "=r"(lo) : "f"(r));
}

#define MMA_TF32(d, a, b0, b1)                                                   \
    asm volatile(                                                                \
        "mma.sync.aligned.m16n8k8.row.col.f32.tf32.tf32.f32 "                    \
        "{%0,%1,%2,%3},{%4,%5,%6,%7},{%8,%9},{%0,%1,%2,%3};"                     \
        : "+f"(d[0]), "+f"(d[1]), "+f"(d[2]), "+f"(d[3])                         \
        : "r"(a[0]), "r"(a[1]), "r"(a[2]), "r"(a[3]), "r"(b0), "r"(b1))

__device__ __forceinline__ void cpa16(uint32_t dst, const void* src) {
    asm volatile("cp.async.cg.shared.global [%0], [%1], 16;" :: "r"(dst), "l"(src));
}
__device__ __forceinline__ void cpa4(uint32_t dst, const void* src) {
    asm volatile("cp.async.ca.shared.global [%0], [%1], 4;" :: "r"(dst), "l"(src));
}

// ---------------- kernels ----------------

__global__ void k_detect(const int* __restrict__ w) {
    int nz = 0;
    for (int i = 1; i < 128; i += 2) nz |= (w[i] != 0);
    g_is64 = nz ? 0 : 1;
}

// split all three weight matrices into tf32 hi/lo (one pass)
__global__ void k_wsplit(const float* __restrict__ w0, const float* __restrict__ w1,
                         const float* __restrict__ w2, float* __restrict__ wsp) {
    int i = blockIdx.x * blockDim.x + threadIdx.x;
    const float* src;
    float *hi, *lo;
    int li;
    if (i < 32768)        { src = w0; li = i;          hi = wsp;            lo = wsp + 65536; }
    else if (i < 98304)   { src = w1; li = i - 32768;  hi = wsp + 131072;   lo = wsp + 196608; }
    else if (i < 163840)  { src = w2; li = i - 98304;  hi = wsp + 262144;   lo = wsp + 327680; }
    else return;
    uint32_t h, l;
    tf32split(src[li], h, l);
    hi[li] = __uint_as_float(h);
    lo[li] = __uint_as_float(l);
}

// decode edges + count in-degrees (fused)
__global__ void k_edges_deg(const void* __restrict__ ei, int* __restrict__ s,
                            int* __restrict__ d, int* __restrict__ deg, int E) {
    int i = blockIdx.x * blockDim.x + threadIdx.x;
    if (i >= E) return;
    int sv, dv;
    if (g_is64) {
        const long long* p = (const long long*)ei;
        sv = (int)p[i];
        dv = (int)p[E + i];
    } else {
        const int* p = (const int*)ei;
        sv = p[i];
        dv = p[E + i];
    }
    s[i] = sv; d[i] = dv;
    atomicAdd(&deg[dv], 1);
}

// Tensor-core GEMM, 3xTF32. B (weights) presplit in global hi/lo; A split
// in registers. Double-buffered cp.async. Block tile 128x256, BK=32,
// 512 threads; grid (1, M/128); K % 32 == 0; N == 256.
// BP = 264 (== 8 mod 32) -> B fragment LDS is bank-conflict-free.
#define AP 36
#define BP 264
#define ABUF (128 * AP)
#define BBUF (32 * BP)
#define SBUF (ABUF + 2 * BBUF)
#define SMEM_GEMM (2 * SBUF * 4)
__global__ void __launch_bounds__(512, 1)
k_gemm_tc(const float* __restrict__ A, const float* __restrict__ Bh,
          const float* __restrict__ Bl,
          const float* __restrict__ bias, float* __restrict__ Cm,
          int M, int K, int N, int act, int Kld,
          const float* __restrict__ a1col, const float* __restrict__ b1row,
          const float* __restrict__ aS, const float* __restrict__ aD,
          float* __restrict__ as_, float* __restrict__ ad_) {
    extern __shared__ float smg[];
    int t = threadIdx.x;
    int lane = t & 31, w = t >> 5;
    int g = lane >> 2, tig = lane & 3;
    int wm = w & 3, wn = w >> 2;
    int row0 = blockIdx.y * 128;
    int nk = K >> 5;
    bool al16 = (Kld & 3) == 0;

    float acc[2][8][4];
#pragma unroll
    for (int i = 0; i < 2; i++)
#pragma unroll
        for (int j = 0; j < 8; j++)
#pragma unroll
            for (int q = 0; q < 4; q++) acc[i][j][q] = 0.f;

    auto copy_tile = [&](int ti, int bf) {
        float* As  = smg + bf * SBUF;
        float* Bsh = As + ABUF;
        float* Bsl = Bsh + BBUF;
#pragma unroll
        for (int it = 0; it < 2; it++) {
            int lin = t + 512 * it;
            int r = lin >> 3, c4 = (lin & 7) * 4;
            const float* src = &A[(size_t)(row0 + r) * Kld + ti * 32 + c4];
            uint32_t dst = (uint32_t)__cvta_generic_to_shared(&As[r * AP + c4]);
            if (al16) {
                cpa16(dst, src);
            } else {
#pragma unroll
                for (int j = 0; j < 4; j++) cpa4(dst + j * 4, src + j);
            }
        }
#pragma unroll
        for (int it = 0; it < 4; it++) {
            int lin = t + 512 * it;
            int kk = lin >> 6, c4 = (lin & 63) * 4;
            size_t gsrc = (size_t)(ti * 32 + kk) * N + c4;
            cpa16((uint32_t)__cvta_generic_to_shared(&Bsh[kk * BP + c4]), &Bh[gsrc]);
            cpa16((uint32_t)__cvta_generic_to_shared(&Bsl[kk * BP + c4]), &Bl[gsrc]);
        }
    };

    copy_tile(0, 0);
    asm volatile("cp.async.commit_group;");

    for (int ti = 0; ti < nk; ti++) {
        if (ti + 1 < nk) {
            copy_tile(ti + 1, (ti + 1) & 1);
            asm volatile("cp.async.commit_group;");
            asm volatile("cp.async.wait_group 1;");
        } else {
            asm volatile("cp.async.wait_group 0;");
        }
        __syncthreads();
        const float* As  = smg + (ti & 1) * SBUF;
        const float* Bsh = As + ABUF;
        const float* Bsl = Bsh + BBUF;
#pragma unroll
        for (int ks = 0; ks < 4; ks++) {
            int k8 = ks * 8;
            uint32_t ah[2][4], al[2][4];
#pragma unroll
            for (int mt = 0; mt < 2; mt++) {
                int bm = wm * 32 + mt * 16 + g;
                tf32split(As[bm * AP + k8 + tig],           ah[mt][0], al[mt][0]);
                tf32split(As[(bm + 8) * AP + k8 + tig],     ah[mt][1], al[mt][1]);
                tf32split(As[bm * AP + k8 + tig + 4],       ah[mt][2], al[mt][2]);
                tf32split(As[(bm + 8) * AP + k8 + tig + 4], ah[mt][3], al[mt][3]);
            }
#pragma unroll
            for (int nt = 0; nt < 8; nt++) {
                int bn = wn * 64 + nt * 8 + g;
                uint32_t b0h = __float_as_uint(Bsh[(k8 + tig) * BP + bn]);
                uint32_t b1h = __float_as_uint(Bsh[(k8 + tig + 4) * BP + bn]);
                uint32_t b0l = __float_as_uint(Bsl[(k8 + tig) * BP + bn]);
                uint32_t b1l = __float_as_uint(Bsl[(k8 + tig + 4) * BP + bn]);
#pragma unroll
                for (int mt = 0; mt < 2; mt++) {
                    MMA_TF32(acc[mt][nt], ah[mt], b0h, b1h);
                    MMA_TF32(acc[mt][nt], ah[mt], b0l, b1l);
                    MMA_TF32(acc[mt][nt], al[mt], b0h, b1h);
                }
            }
        }
        __syncthreads();
    }

#pragma unroll
    for (int mt = 0; mt < 2; mt++) {
        int r = row0 + wm * 32 + mt * 16 + g;
        float ar0 = a1col ? a1col[(size_t)r * Kld] : 0.f;
        float ar8 = a1col ? a1col[(size_t)(r + 8) * Kld] : 0.f;
#pragma unroll
        for (int nt = 0; nt < 8; nt++) {
            int cc = wn * 64 + nt * 8 + tig * 2;
            float bb0 = a1col ? b1row[cc] : 0.f, bb1 = a1col ? b1row[cc + 1] : 0.f;
            float b0 = bias ? bias[cc] : 0.f, b1 = bias ? bias[cc + 1] : 0.f;
            float v0 = acc[mt][nt][0] + ar0 * bb0 + b0;
            float v1 = acc[mt][nt][1] + ar0 * bb1 + b1;
            float v2 = acc[mt][nt][2] + ar8 * bb0 + b0;
            float v3 = acc[mt][nt][3] + ar8 * bb1 + b1;
            if (act) {
                v0 = fmaxf(v0, 0.f); v1 = fmaxf(v1, 0.f);
                v2 = fmaxf(v2, 0.f); v3 = fmaxf(v3, 0.f);
            }
            float2 p0 = {v0, v1}, p1 = {v2, v3};
            *(float2*)&Cm[(size_t)r * N + cc] = p0;
            *(float2*)&Cm[(size_t)(r + 8) * N + cc] = p1;
        }
    }

    if (aS) {
        const float* ws = aS + wn * 64;
        const float* wd = aD + wn * 64;
#pragma unroll
        for (int mt = 0; mt < 2; mt++) {
            float s0 = 0.f, d0 = 0.f, s1 = 0.f, d1 = 0.f;
#pragma unroll
            for (int nt = 0; nt < 8; nt++) {
                int c = nt * 8 + tig * 2;
                float w0 = ws[c], w1 = ws[c + 1];
                float u0 = wd[c], u1 = wd[c + 1];
                s0 = fmaf(acc[mt][nt][0], w0, fmaf(acc[mt][nt][1], w1, s0));
                d0 = fmaf(acc[mt][nt][0], u0, fmaf(acc[mt][nt][1], u1, d0));
                s1 = fmaf(acc[mt][nt][2], w0, fmaf(acc[mt][nt][3], w1, s1));
                d1 = fmaf(acc[mt][nt][2], u0, fmaf(acc[mt][nt][3], u1, d1));
            }
#pragma unroll
            for (int o = 1; o <= 2; o <<= 1) {
                s0 += __shfl_xor_sync(0xffffffffu, s0, o);
                d0 += __shfl_xor_sync(0xffffffffu, d0, o);
                s1 += __shfl_xor_sync(0xffffffffu, s1, o);
                d1 += __shfl_xor_sync(0xffffffffu, d1, o);
            }
            if (tig == 0) {
                int r = row0 + wm * 32 + mt * 16 + g;
                as_[r * 4 + wn] = s0; ad_[r * 4 + wn] = d0;
                as_[(r + 8) * 4 + wn] = s1; ad_[(r + 8) * 4 + wn] = d1;
            }
        }
    }
}

// single-pass exclusive scan with decoupled lookback; nb = gridDim.x <= 64.
__global__ void __launch_bounds__(1024) k_scanF(const int* __restrict__ in,
                                                int* __restrict__ off,
                                                int* __restrict__ cur,
                                                int* __restrict__ bflag, int n) {
    __shared__ int sm[1024];
    __shared__ int spre;
    int t = threadIdx.x, b = blockIdx.x;
    int i = b * 1024 + t;
    int v = (i < n) ? in[i] : 0;
    sm[t] = v;
    __syncthreads();
    for (int o = 1; o < 1024; o <<= 1) {
        int u = (t >= o) ? sm[t - o] : 0;
        __syncthreads();
        sm[t] += u;
        __syncthreads();
    }
    if (t == 0) { spre = 0; atomicExch(&bflag[b], sm[1023] + 1); }
    __syncthreads();
    if (t < b) {
        int f;
        do { f = atomicAdd(&bflag[t], 0); } while (f == 0);
        atomicAdd(&spre, f - 1);
    }
    __syncthreads();
    int exc = spre + sm[t] - v;
    if (i < n) { off[i] = exc; cur[i] = exc; }
    if (b == gridDim.x - 1 && t == 1023) off[n] = spre + sm[1023];
}

__global__ void k_escatter(const int* __restrict__ s, const int* __restrict__ d,
                           const unsigned char* __restrict__ val, int* __restrict__ cur,
                           int* __restrict__ csr, int E) {
    int e = blockIdx.x * blockDim.x + threadIdx.x;
    if (e >= E) return;
    if (val && !val[e]) return;
    int p = atomicAdd(&cur[d[e]], 1);
    csr[p] = s[e];
}

// Fused GAT aggregation + topk score: warp per dst node. Softmax without
// max-shift. Edge loop processes predicated batches of 4 (invalid lanes use
// the self index with weight 0) so MLP=4 holds through the tail.
__global__ void k_gather(const float* __restrict__ h1, const int* __restrict__ off,
                         const int* __restrict__ csr,
                         const float* __restrict__ as_, const float* __restrict__ ad_,
                         const float* __restrict__ bias, const float* __restrict__ pw,
                         float* __restrict__ out, float* __restrict__ sc, int n) {
    int wp = (blockIdx.x * blockDim.x + threadIdx.x) >> 5;
    if (wp >= n) return;
    int lane = threadIdx.x & 31;
    int head = lane >> 3;
    int d = wp;
    float adh = ad_[d * 4 + head];
    float w0s = expf(lrelu(as_[d * 4 + head] + adh));   // self loop
    float den = w0s;
    float acc[8];
    {
        const float4* p = (const float4*)(h1 + (size_t)d * FHC + lane * 8);
        float4 x0 = p[0], x1 = p[1];
        acc[0] = w0s * x0.x; acc[1] = w0s * x0.y; acc[2] = w0s * x0.z; acc[3] = w0s * x0.w;
        acc[4] = w0s * x1.x; acc[5] = w0s * x1.y; acc[6] = w0s * x1.z; acc[7] = w0s * x1.w;
    }
    int e0 = off[d], e1 = off[d + 1];
    for (int e = e0; e < e1; e += 4) {
        int sv[4];
        float wgt[4];
        float4 f0[4], f1[4];
#pragma unroll
        for (int i = 0; i < 4; i++) {
            bool ok = (e + i < e1);
            sv[i] = ok ? csr[e + i] : d;
            wgt[i] = ok ? 1.f : 0.f;
        }
#pragma unroll
        for (int i = 0; i < 4; i++) {
            wgt[i] *= expf(lrelu(as_[sv[i] * 4 + head] + adh));
            const float4* p = (const float4*)(h1 + (size_t)sv[i] * FHC + lane * 8);
            f0[i] = p[0]; f1[i] = p[1];
        }
#pragma unroll
        for (int i = 0; i < 4; i++) {
            den += wgt[i];
            acc[0] = fmaf(wgt[i], f0[i].x, acc[0]);
            acc[1] = fmaf(wgt[i], f0[i].y, acc[1]);
            acc[2] = fmaf(wgt[i], f0[i].z, acc[2]);
            acc[3] = fmaf(wgt[i], f0[i].w, acc[3]);
            acc[4] = fmaf(wgt[i], f1[i].x, acc[4]);
            acc[5] = fmaf(wgt[i], f1[i].y, acc[5]);
            acc[6] = fmaf(wgt[i], f1[i].z, acc[6]);
            acc[7] = fmaf(wgt[i], f1[i].w, acc[7]);
        }
    }
    float inv = 1.f / (den + 1e-16f);
    int cb = lane * 8;
    float4 o0, o1;
    float v;
    v = acc[0] * inv + bias[cb + 0]; o0.x = v > 0.f ? v : expm1f(v);
    v = acc[1] * inv + bias[cb + 1]; o0.y = v > 0.f ? v : expm1f(v);
    v = acc[2] * inv + bias[cb + 2]; o0.z = v > 0.f ? v : expm1f(v);
    v = acc[3] * inv + bias[cb + 3]; o0.w = v > 0.f ? v : expm1f(v);
    v = acc[4] * inv + bias[cb + 4]; o1.x = v > 0.f ? v : expm1f(v);
    v = acc[5] * inv + bias[cb + 5]; o1.y = v > 0.f ? v : expm1f(v);
    v = acc[6] * inv + bias[cb + 6]; o1.z = v > 0.f ? v : expm1f(v);
    v = acc[7] * inv + bias[cb + 7]; o1.w = v > 0.f ? v : expm1f(v);
    float4* po = (float4*)(out + (size_t)d * FHC + cb);
    __stcs(po, o0);
    __stcs(po + 1, o1);
    const float4* pwp = (const float4*)(pw + cb);
    float4 w0 = pwp[0], w1 = pwp[1];
    float sp = o0.x * w0.x + o0.y * w0.y + o0.z * w0.z + o0.w * w0.w +
               o1.x * w1.x + o1.y * w1.y + o1.z * w1.z + o1.w * w1.w;
    float n2 = w0.x * w0.x + w0.y * w0.y + w0.z * w0.z + w0.w * w0.w +
               w1.x * w1.x + w1.y * w1.y + w1.z * w1.z + w1.w * w1.w;
#pragma unroll
    for (int o = 16; o; o >>= 1) {
        sp += __shfl_xor_sync(0xffffffffu, sp, o);
        n2 += __shfl_xor_sync(0xffffffffu, n2, o);
    }
    if (!lane) sc[d] = sp / (sqrtf(n2) + 1e-16f);
}

// exact top-k per graph via 4-pass radix select on sortable uint keys.
__global__ void __launch_bounds__(1024) k_topk(const float* __restrict__ score, int n_in,
                                               int k, int* __restrict__ perm,
                                               float* __restrict__ tanhv,
                                               int* __restrict__ newid) {
    __shared__ unsigned su[2048];
    __shared__ int hist[256];
    __shared__ int sscan[1024];
    __shared__ unsigned s_thr;
    __shared__ int s_kk;
    __shared__ int s_totgt;
    int b = blockIdx.x, t = threadIdx.x;
    const float* s = score + b * n_in;
    int per = n_in >> 10;  // 1 or 2
    for (int i = t; i < n_in; i += 1024) {
        unsigned u = __float_as_uint(s[i]);
        su[i] = (u & 0x80000000u) ? ~u : (u | 0x80000000u);
    }
    __syncthreads();
    unsigned prefix = 0u;
    int kk = k;
    for (int pass = 0; pass < 4; pass++) {
        int shift = 24 - 8 * pass;
        unsigned pmask = pass ? (0xFFFFFFFFu << (shift + 8)) : 0u;
        if (t < 256) hist[t] = 0;
        __syncthreads();
        for (int i = t; i < n_in; i += 1024) {
            unsigned u = su[i];
            if ((u & pmask) == (prefix & pmask))
                atomicAdd(&hist[(u >> shift) & 0xFFu], 1);
        }
        __syncthreads();
        if (t == 0) {
            int acc = 0, d = 255;
            for (; d > 0; d--) {
                int c = hist[d];
                if (acc + c >= kk) break;
                acc += c;
            }
            s_thr = (prefix & pmask) | ((unsigned)d << shift);
            s_kk = kk - acc;
        }
        __syncthreads();
        prefix = s_thr;
        kk = s_kk;
        __syncthreads();
    }
    unsigned T = prefix;
    int isgt[2] = {0, 0}, iseq[2] = {0, 0};
    int keepc = 0, eqc = 0;
    for (int q = 0; q < 2; q++) {
        if (q < per) {
            unsigned u = su[t * per + q];
            isgt[q] = (u > T);
            iseq[q] = (u == T);
            keepc += isgt[q];
            eqc += iseq[q];
        }
    }
    sscan[t] = (eqc << 16) | keepc;
    __syncthreads();
    for (int o = 1; o < 1024; o <<= 1) {
        int u = (t >= o) ? sscan[t - o] : 0;
        __syncthreads();
        sscan[t] += u;
        __syncthreads();
    }
    int packed_exc = sscan[t] - ((eqc << 16) | keepc);
    int gtpos = packed_exc & 0xFFFF;
    int eqrank = packed_exc >> 16;
    if (t == 1023) s_totgt = sscan[1023] & 0xFFFF;
    __syncthreads();
    int totgt = s_totgt;
    for (int q = 0; q < per; q++) {
        int idx = t * per + q;
        int old = b * n_in + idx;
        bool kept = false;
        int pos = 0;
        if (isgt[q]) {
            kept = true; pos = gtpos; gtpos++;
        } else if (iseq[q]) {
            kept = (eqrank < kk); pos = totgt + eqrank; eqrank++;
        }
        if (kept) {
            int np = b * k + pos;
            perm[np] = old;
            tanhv[np] = tanhf(s[idx]);
            newid[old] = np;
        } else {
            newid[old] = -1;
        }
    }
}

// warp per pooled node: hp = h[perm]*tanh, fused gate = <hp_row, gate_w> + b
__global__ void k_poolfeat(const float* __restrict__ h, const int* __restrict__ pm,
                           const float* __restrict__ th, const float* __restrict__ gw,
                           const float* __restrict__ gb, float* __restrict__ hp,
                           float* __restrict__ gt, int m) {
    int wp = (blockIdx.x * blockDim.x + threadIdx.x) >> 5;
    if (wp >= m) return;
    int lane = threadIdx.x & 31;
    int srcn = pm[wp];
    float tv = th[wp];
    int cb = lane * 8;
    const float4* p = (const float4*)(h + (size_t)srcn * FHC + cb);
    float4 a = p[0], b = p[1];
    a.x *= tv; a.y *= tv; a.z *= tv; a.w *= tv;
    b.x *= tv; b.y *= tv; b.z *= tv; b.w *= tv;
    float4* po = (float4*)(hp + (size_t)wp * FHC + cb);
    po[0] = a; po[1] = b;
    const float4* g4 = (const float4*)(gw + cb);
    float4 w0 = g4[0], w1 = g4[1];
    float s = a.x * w0.x + a.y * w0.y + a.z * w0.z + a.w * w0.w +
              b.x * w1.x + b.y * w1.y + b.z * w1.z + b.w * w1.w;
#pragma unroll
    for (int o = 16; o; o >>= 1) s += __shfl_xor_sync(0xffffffffu, s, o);
    if (!lane) gt[wp] = s + gb[0];
}

// remap edges to pooled ids + count pooled in-degrees (fused)
__global__ void k_remap_deg(const int* __restrict__ si, const int* __restrict__ di,
                            const int* __restrict__ nid, int* __restrict__ so,
                            int* __restrict__ dq, unsigned char* __restrict__ vo,
                            int* __restrict__ deg, int E) {
    int e = blockIdx.x * blockDim.x + threadIdx.x;
    if (e >= E) return;
    int ns = nid[si[e]], nd = nid[di[e]];
    bool v = (ns >= 0) && (nd >= 0);
    so[e] = v ? ns : 0;
    dq[e] = v ? nd : 0;
    vo[e] = v ? 1 : 0;
    if (v) atomicAdd(&deg[nd], 1);
}

// attentional pooling with in-kernel softmax stats: grid (8, NB)
__global__ void k_attpool2(const float* __restrict__ hp, const float* __restrict__ gt,
                           float* __restrict__ out, int npg) {
    __shared__ float red[256];
    int b = blockIdx.y, t = threadIdx.x;
    const float* g = gt + b * npg;
    float mxv = -1e30f;
    for (int i = t; i < npg; i += 256) mxv = fmaxf(mxv, g[i]);
    red[t] = mxv;
    __syncthreads();
    for (int o = 128; o; o >>= 1) { if (t < o) red[t] = fmaxf(red[t], red[t + o]); __syncthreads(); }
    float m = red[0];
    __syncthreads();
    float sum = 0.f;
    for (int i = t; i < npg; i += 256) sum += expf(g[i] - m);
    red[t] = sum;
    __syncthreads();
    for (int o = 128; o; o >>= 1) { if (t < o) red[t] += red[t + o]; __syncthreads(); }
    float inv = 1.f / red[0];
    int chunk = npg >> 3;
    int i0 = blockIdx.x * chunk;
    const float* hb = hp + ((size_t)b * npg + i0) * FHC;
    float a = 0.f;
    for (int i = 0; i < chunk; i++)
        a = fmaf(expf(g[i0 + i] - m), hb[(size_t)i * FHC + t], a);
    atomicAdd(&out[b * FHC + t], a * inv);
}

// ---------------- host side ----------------

extern "C" void kernel_launch(void* const* d_in, const int* in_sizes, int n_in,
                              void* d_out, int out_size) {
    const float* x        = (const float*)d_in[0];
    const void*  ei       = d_in[1];
    const float* lin0_w   = (const float*)d_in[2];
    const float* lin0_b   = (const float*)d_in[3];
    const float* gat0_W   = (const float*)d_in[4];
    const float* gat0_as  = (const float*)d_in[5];
    const float* gat0_ad  = (const float*)d_in[6];
    const float* gat0_b   = (const float*)d_in[7];
    const float* pool0_w  = (const float*)d_in[8];
    const float* gat1_W   = (const float*)d_in[9];
    const float* gat1_as  = (const float*)d_in[10];
    const float* gat1_ad  = (const float*)d_in[11];
    const float* gat1_b   = (const float*)d_in[12];
    const float* pool1_w  = (const float*)d_in[13];
    const float* gate_w   = (const float*)d_in[14];
    const float* gate_b   = (const float*)d_in[15];
    float* out = (float*)d_out;

    float *h0, *h1, *ho, *hp, *hp2, *wsp, *as_, *ad_, *sc, *th, *gt;
    int *s0, *d0, *s1, *d1, *deg, *off, *cur, *csr, *pm, *nid, *bs;
    unsigned char* v1;
    cudaGetSymbolAddress((void**)&h0, g_h0);
    cudaGetSymbolAddress((void**)&h1, g_h1);
    cudaGetSymbolAddress((void**)&ho, g_ho);
    cudaGetSymbolAddress((void**)&hp, g_hp);
    cudaGetSymbolAddress((void**)&hp2, g_hp2);
    cudaGetSymbolAddress((void**)&wsp, g_wsp);
    cudaGetSymbolAddress((void**)&as_, g_as);
    cudaGetSymbolAddress((void**)&ad_, g_ad);
    cudaGetSymbolAddress((void**)&sc, g_sc);
    cudaGetSymbolAddress((void**)&th, g_th);
    cudaGetSymbolAddress((void**)&gt, g_gt);
    cudaGetSymbolAddress((void**)&s0, g_s0);
    cudaGetSymbolAddress((void**)&d0, g_d0);
    cudaGetSymbolAddress((void**)&s1, g_s1);
    cudaGetSymbolAddress((void**)&d1, g_d1);
    cudaGetSymbolAddress((void**)&deg, g_deg);
    cudaGetSymbolAddress((void**)&off, g_off);
    cudaGetSymbolAddress((void**)&cur, g_cur);
    cudaGetSymbolAddress((void**)&csr, g_csr);
    cudaGetSymbolAddress((void**)&pm, g_pm);
    cudaGetSymbolAddress((void**)&nid, g_nid);
    cudaGetSymbolAddress((void**)&bs, g_bs);
    cudaGetSymbolAddress((void**)&v1, g_v1);

    cudaFuncSetAttribute(k_gemm_tc, cudaFuncAttributeMaxDynamicSharedMemorySize,
                         SMEM_GEMM);

    static cudaStream_t s2 = nullptr;
    static cudaEvent_t evF0, evS0, evT0, evP0, evS1, evA0;
    if (!s2) {
        cudaStreamCreateWithFlags(&s2, cudaStreamNonBlocking);
        cudaEventCreateWithFlags(&evF0, cudaEventDisableTiming);
        cudaEventCreateWithFlags(&evS0, cudaEventDisableTiming);
        cudaEventCreateWithFlags(&evT0, cudaEventDisableTiming);
        cudaEventCreateWithFlags(&evP0, cudaEventDisableTiming);
        cudaEventCreateWithFlags(&evS1, cudaEventDisableTiming);
        cudaEventCreateWithFlags(&evA0, cudaEventDisableTiming);
    }

    const int EB = divup(E0, 256);

    // ---- main: output zero (memset node) + weight presplit ----
    cudaMemsetAsync(out, 0, (size_t)NB * FHC * sizeof(float), 0);
    k_wsplit<<<divup(163840, 256), 256>>>(lin0_w, gat0_W, gat1_W, wsp);
    cudaEventRecord(evF0, 0);

    // ---- main: lin0 (K=128 + rank-1 for col 128) + GAT0 GEMM ----
    k_gemm_tc<<<dim3(1, N0 / 128), 512, SMEM_GEMM>>>(
        x, wsp, wsp + 65536, lin0_b, h0, N0, 128, 256, 1, 129,
        x + 128, lin0_w + 128 * 256, nullptr, nullptr, nullptr, nullptr);
    k_gemm_tc<<<dim3(1, N0 / 128), 512, SMEM_GEMM>>>(
        h0, wsp + 131072, wsp + 196608, nullptr, h1, N0, 256, 256, 0, 256,
        nullptr, nullptr, gat0_as, gat0_ad, as_, ad_);

    // side stream (executes concurrently with GEMMs): edge decode + CSR0
    cudaStreamWaitEvent(s2, evF0, 0);
    k_detect<<<1, 1, 0, s2>>>((const int*)ei);
    cudaMemsetAsync(deg, 0, (size_t)N0 * sizeof(int), s2);
    cudaMemsetAsync(bs, 0, 64 * sizeof(int), s2);
    k_edges_deg<<<EB, 256, 0, s2>>>(ei, s0, d0, deg, E0);
    k_scanF<<<N0 / 1024, 1024, 0, s2>>>(deg, off, cur, bs, N0);
    k_escatter<<<EB, 256, 0, s2>>>(s0, d0, nullptr, cur, csr, E0);
    cudaEventRecord(evS0, s2);

    // join: gather0 needs CSR + h1/as_/ad_
    cudaStreamWaitEvent(0, evS0, 0);
    k_gather<<<divup(N0, 8), 256>>>(h1, off, csr, as_, ad_, gat0_b, pool0_w, ho, sc, N0);

    // TopK pool 0 (radix select)
    k_topk<<<NB, 1024>>>(sc, 2048, 1024, pm, th, nid);
    cudaEventRecord(evT0, 0);
    k_poolfeat<<<divup((N0 / 2) * 32, 256), 256>>>(ho, pm, th, gate_w, gate_b, hp, gt, N0 / 2);
    cudaEventRecord(evP0, 0);

    // side: CSR build for GAT1 (needs nid), then attpool0 (needs hp/gt)
    cudaStreamWaitEvent(s2, evT0, 0);
    cudaMemsetAsync(deg, 0, (size_t)(N0 / 2) * sizeof(int), s2);
    cudaMemsetAsync(bs, 0, 64 * sizeof(int), s2);
    k_remap_deg<<<EB, 256, 0, s2>>>(s0, d0, nid, s1, d1, v1, deg, E0);
    k_scanF<<<(N0 / 2) / 1024, 1024, 0, s2>>>(deg, off, cur, bs, N0 / 2);
    k_escatter<<<EB, 256, 0, s2>>>(s1, d1, v1, cur, csr, E0);
    cudaEventRecord(evS1, s2);
    cudaStreamWaitEvent(s2, evP0, 0);
    k_attpool2<<<dim3(8, NB), 256, 0, s2>>>(hp, gt, out, 1024);
    cudaEventRecord(evA0, s2);

    // ---- main: GAT1 GEMM (overlaps side CSR + attpool0) ----
    k_gemm_tc<<<dim3(1, (N0 / 2) / 128), 512, SMEM_GEMM>>>(
        hp, wsp + 262144, wsp + 327680, nullptr, h1, N0 / 2, 256, 256, 0, 256,
        nullptr, nullptr, gat1_as, gat1_ad, as_, ad_);
    cudaStreamWaitEvent(0, evS1, 0);
    k_gather<<<divup(N0 / 2, 8), 256>>>(h1, off, csr, as_, ad_, gat1_b, pool1_w, ho, sc, N0 / 2);

    // TopK pool 1
    k_topk<<<NB, 1024>>>(sc, 1024, 512, pm, th, nid);
    k_poolfeat<<<divup((N0 / 4) * 32, 256), 256>>>(ho, pm, th, gate_w, gate_b, hp2, gt, N0 / 4);

    // AttPool 1 -> out (+=); join attpool0 branch before final adds
    cudaStreamWaitEvent(0, evA0, 0);
    k_attpool2<<<dim3(8, NB), 256>>>(hp2, gt, out, 512);
}

// round 14
// speedup vs baseline: 3.1101x; 1.0189x over previous
#include <cuda_runtime.h>
#include <math.h>
#include <stdint.h>

#define N0  65536     // total nodes
#define E0  524288    // total edges
#define NB  32        // graphs
#define FHC 256       // feature width (H*C)

// ---------------- static device scratch ----------------
__device__ float g_h0[(size_t)N0 * FHC];
__device__ float g_h1[(size_t)N0 * FHC];
__device__ float g_ho[(size_t)N0 * FHC];
__device__ float g_hp[(size_t)(N0 / 2) * FHC];
__device__ float g_hp2[(size_t)(N0 / 4) * FHC];
__device__ float g_wsp[6 * 65536];   // presplit weights: lin0 hi/lo, gat0 hi/lo, gat1 hi/lo
__device__ float g_as[N0 * 4], g_ad[N0 * 4];
__device__ float g_sc[N0];
__device__ float g_th[N0 / 2];
__device__ float g_gt[N0 / 2];
__device__ int g_s0[E0], g_d0[E0], g_s1[E0], g_d1[E0];
__device__ unsigned char g_v1[E0];
__device__ int g_deg[N0], g_off[N0 + 1], g_cur[N0], g_csr[E0];
__device__ int g_bs[64];             // lookback flags (value = chunk total + 1)
__device__ int g_pm[N0 / 2], g_nid[N0];

static inline int divup(int a, int b) { return (a + b - 1) / b; }

__device__ __forceinline__ float lrelu(float z) { return z > 0.f ? z : 0.2f * z; }

// ---------------- tf32 helpers ----------------
__device__ __forceinline__ void tf32split(float x, uint32_t& hi, uint32_t& lo) {
    asm("cvt.rna.tf32.f32 %0, %1;" : "=r"(hi) : "f"(x));
    float r = x - __uint_as_float(hi);
    asm("cvt.rna.tf32.f32 %0, %1;" : "=r"(lo) : "f"(r));
}

#define MMA_TF32(d, a, b0, b1)                                                   \
    asm volatile(                                                                \
        "mma.sync.aligned.m16n8k8.row.col.f32.tf32.tf32.f32 "                    \
        "{%0,%1,%2,%3},{%4,%5,%6,%7},{%8,%9},{%0,%1,%2,%3};"                     \
        : "+f"(d[0]), "+f"(d[1]), "+f"(d[2]), "+f"(d[3])                         \
        : "r"(a[0]), "r"(a[1]), "r"(a[2]), "r"(a[3]), "r"(b0), "r"(b1))

__device__ __forceinline__ void cpa16(uint32_t dst, const void* src) {
    asm volatile("cp.async.cg.shared.global [%0], [%1], 16;" :: "r"(dst), "l"(src));
}
__device__ __forceinline__ void cpa4(uint32_t dst, const void* src) {
    asm volatile("cp.async.ca.shared.global [%0], [%1], 4;" :: "r"(dst), "l"(src));
}

// ---------------- kernels ----------------

// split all three weight matrices into tf32 hi/lo (one pass)
__global__ void k_wsplit(const float* __restrict__ w0, const float* __restrict__ w1,
                         const float* __restrict__ w2, float* __restrict__ wsp) {
    int i = blockIdx.x * blockDim.x + threadIdx.x;
    const float* src;
    float *hi, *lo;
    int li;
    if (i < 32768)        { src = w0; li = i;          hi = wsp;            lo = wsp + 65536; }
    else if (i < 98304)   { src = w1; li = i - 32768;  hi = wsp + 131072;   lo = wsp + 196608; }
    else if (i < 163840)  { src = w2; li = i - 98304;  hi = wsp + 262144;   lo = wsp + 327680; }
    else return;
    uint32_t h, l;
    tf32split(src[li], h, l);
    hi[li] = __uint_as_float(h);
    lo[li] = __uint_as_float(l);
}

// decode edges + count in-degrees; int64-vs-int32 detection fused per block
// (for little-endian int64 ids < 2^31 every odd 32-bit word is 0; for int32
// random ids the probability all 64 sampled odd words are 0 is ~0).
__global__ void k_edges_deg(const void* __restrict__ ei, int* __restrict__ s,
                            int* __restrict__ d, int* __restrict__ deg, int E) {
    __shared__ int s64;
    if (threadIdx.x == 0) {
        const int* w = (const int*)ei;
        int nz = 0;
        for (int i = 1; i < 128; i += 2) nz |= (w[i] != 0);
        s64 = nz ? 0 : 1;
    }
    __syncthreads();
    int i = blockIdx.x * blockDim.x + threadIdx.x;
    if (i >= E) return;
    int sv, dv;
    if (s64) {
        const long long* p = (const long long*)ei;
        sv = (int)p[i];
        dv = (int)p[E + i];
    } else {
        const int* p = (const int*)ei;
        sv = p[i];
        dv = p[E + i];
    }
    s[i] = sv; d[i] = dv;
    atomicAdd(&deg[dv], 1);
}

// Tensor-core GEMM, 3xTF32. B (weights) presplit in global hi/lo; A split
// in registers. Double-buffered cp.async. Block tile 128x256, BK=32,
// 256 threads (8 warps, warp tile 64x64); grid (1, M/128); K % 32 == 0; N == 256.
#define AP 36
#define BP 264
#define ABUF (128 * AP)
#define BBUF (32 * BP)
#define SBUF (ABUF + 2 * BBUF)
#define SMEM_GEMM (2 * SBUF * 4)
__global__ void __launch_bounds__(256, 1)
k_gemm_tc(const float* __restrict__ A, const float* __restrict__ Bh,
          const float* __restrict__ Bl,
          const float* __restrict__ bias, float* __restrict__ Cm,
          int M, int K, int N, int act, int Kld,
          const float* __restrict__ a1col, const float* __restrict__ b1row,
          const float* __restrict__ aS, const float* __restrict__ aD,
          float* __restrict__ as_, float* __restrict__ ad_) {
    extern __shared__ float smg[];
    int t = threadIdx.x;
    int lane = t & 31, w = t >> 5;
    int g = lane >> 2, tig = lane & 3;
    int wm = w & 1, wn = w >> 1;         // 2 warps M x 4 warps N, warp tile 64x64
    int row0 = blockIdx.y * 128;
    int nk = K >> 5;
    bool al16 = (Kld & 3) == 0;

    float acc[4][8][4];
#pragma unroll
    for (int i = 0; i < 4; i++)
#pragma unroll
        for (int j = 0; j < 8; j++)
#pragma unroll
            for (int q = 0; q < 4; q++) acc[i][j][q] = 0.f;

    auto copy_tile = [&](int ti, int bf) {
        float* As  = smg + bf * SBUF;
        float* Bsh = As + ABUF;
        float* Bsl = Bsh + BBUF;
#pragma unroll
        for (int it = 0; it < 4; it++) {
            int lin = t + 256 * it;
            int r = lin >> 3, c4 = (lin & 7) * 4;
            const float* src = &A[(size_t)(row0 + r) * Kld + ti * 32 + c4];
            uint32_t dst = (uint32_t)__cvta_generic_to_shared(&As[r * AP + c4]);
            if (al16) {
                cpa16(dst, src);
            } else {
#pragma unroll
                for (int j = 0; j < 4; j++) cpa4(dst + j * 4, src + j);
            }
        }
#pragma unroll
        for (int it = 0; it < 8; it++) {
            int lin = t + 256 * it;
            int kk = lin >> 6, c4 = (lin & 63) * 4;
            size_t gsrc = (size_t)(ti * 32 + kk) * N + c4;
            cpa16((uint32_t)__cvta_generic_to_shared(&Bsh[kk * BP + c4]), &Bh[gsrc]);
            cpa16((uint32_t)__cvta_generic_to_shared(&Bsl[kk * BP + c4]), &Bl[gsrc]);
        }
    };

    copy_tile(0, 0);
    asm volatile("cp.async.commit_group;");

    for (int ti = 0; ti < nk; ti++) {
        if (ti + 1 < nk) {
            copy_tile(ti + 1, (ti + 1) & 1);
            asm volatile("cp.async.commit_group;");
            asm volatile("cp.async.wait_group 1;");
        } else {
            asm volatile("cp.async.wait_group 0;");
        }
        __syncthreads();
        const float* As  = smg + (ti & 1) * SBUF;
        const float* Bsh = As + ABUF;
        const float* Bsl = Bsh + BBUF;
#pragma unroll
        for (int ks = 0; ks < 4; ks++) {
            int k8 = ks * 8;
            uint32_t ah[4][4], al[4][4];
#pragma unroll
            for (int mt = 0; mt < 4; mt++) {
                int bm = wm * 64 + mt * 16 + g;
                tf32split(As[bm * AP + k8 + tig],           ah[mt][0], al[mt][0]);
                tf32split(As[(bm + 8) * AP + k8 + tig],     ah[mt][1], al[mt][1]);
                tf32split(As[bm * AP + k8 + tig + 4],       ah[mt][2], al[mt][2]);
                tf32split(As[(bm + 8) * AP + k8 + tig + 4], ah[mt][3], al[mt][3]);
            }
#pragma unroll
            for (int nt = 0; nt < 8; nt++) {
                int bn = wn * 64 + nt * 8 + g;
                uint32_t b0h = __float_as_uint(Bsh[(k8 + tig) * BP + bn]);
                uint32_t b1h = __float_as_uint(Bsh[(k8 + tig + 4) * BP + bn]);
                uint32_t b0l = __float_as_uint(Bsl[(k8 + tig) * BP + bn]);
                uint32_t b1l = __float_as_uint(Bsl[(k8 + tig + 4) * BP + bn]);
#pragma unroll
                for (int mt = 0; mt < 4; mt++) {
                    MMA_TF32(acc[mt][nt], ah[mt], b0h, b1h);
                    MMA_TF32(acc[mt][nt], ah[mt], b0l, b1l);
                    MMA_TF32(acc[mt][nt], al[mt], b0h, b1h);
                }
            }
        }
        __syncthreads();
    }

#pragma unroll
    for (int mt = 0; mt < 4; mt++) {
        int r = row0 + wm * 64 + mt * 16 + g;
        float ar0 = a1col ? a1col[(size_t)r * Kld] : 0.f;
        float ar8 = a1col ? a1col[(size_t)(r + 8) * Kld] : 0.f;
#pragma unroll
        for (int nt = 0; nt < 8; nt++) {
            int cc = wn * 64 + nt * 8 + tig * 2;
            float bb0 = a1col ? b1row[cc] : 0.f, bb1 = a1col ? b1row[cc + 1] : 0.f;
            float b0 = bias ? bias[cc] : 0.f, b1 = bias ? bias[cc + 1] : 0.f;
            float v0 = acc[mt][nt][0] + ar0 * bb0 + b0;
            float v1 = acc[mt][nt][1] + ar0 * bb1 + b1;
            float v2 = acc[mt][nt][2] + ar8 * bb0 + b0;
            float v3 = acc[mt][nt][3] + ar8 * bb1 + b1;
            if (act) {
                v0 = fmaxf(v0, 0.f); v1 = fmaxf(v1, 0.f);
                v2 = fmaxf(v2, 0.f); v3 = fmaxf(v3, 0.f);
            }
            float2 p0 = {v0, v1}, p1 = {v2, v3};
            *(float2*)&Cm[(size_t)r * N + cc] = p0;
            *(float2*)&Cm[(size_t)(r + 8) * N + cc] = p1;
        }
    }

    if (aS) {
        const float* ws = aS + wn * 64;
        const float* wd = aD + wn * 64;
#pragma unroll
        for (int mt = 0; mt < 4; mt++) {
            float s0 = 0.f, d0 = 0.f, s1 = 0.f, d1 = 0.f;
#pragma unroll
            for (int nt = 0; nt < 8; nt++) {
                int c = nt * 8 + tig * 2;
                float w0 = ws[c], w1 = ws[c + 1];
                float u0 = wd[c], u1 = wd[c + 1];
                s0 = fmaf(acc[mt][nt][0], w0, fmaf(acc[mt][nt][1], w1, s0));
                d0 = fmaf(acc[mt][nt][0], u0, fmaf(acc[mt][nt][1], u1, d0));
                s1 = fmaf(acc[mt][nt][2], w0, fmaf(acc[mt][nt][3], w1, s1));
                d1 = fmaf(acc[mt][nt][2], u0, fmaf(acc[mt][nt][3], u1, d1));
            }
#pragma unroll
            for (int o = 1; o <= 2; o <<= 1) {
                s0 += __shfl_xor_sync(0xffffffffu, s0, o);
                d0 += __shfl_xor_sync(0xffffffffu, d0, o);
                s1 += __shfl_xor_sync(0xffffffffu, s1, o);
                d1 += __shfl_xor_sync(0xffffffffu, d1, o);
            }
            if (tig == 0) {
                int r = row0 + wm * 64 + mt * 16 + g;
                as_[r * 4 + wn] = s0; ad_[r * 4 + wn] = d0;
                as_[(r + 8) * 4 + wn] = s1; ad_[(r + 8) * 4 + wn] = d1;
            }
        }
    }
}

// single-pass exclusive scan with decoupled lookback; nb = gridDim.x <= 64.
__global__ void __launch_bounds__(1024) k_scanF(const int* __restrict__ in,
                                                int* __restrict__ off,
                                                int* __restrict__ cur,
                                                int* __restrict__ bflag, int n) {
    __shared__ int sm[1024];
    __shared__ int spre;
    int t = threadIdx.x, b = blockIdx.x;
    int i = b * 1024 + t;
    int v = (i < n) ? in[i] : 0;
    sm[t] = v;
    __syncthreads();
    for (int o = 1; o < 1024; o <<= 1) {
        int u = (t >= o) ? sm[t - o] : 0;
        __syncthreads();
        sm[t] += u;
        __syncthreads();
    }
    if (t == 0) { spre = 0; atomicExch(&bflag[b], sm[1023] + 1); }
    __syncthreads();
    if (t < b) {
        int f;
        do { f = atomicAdd(&bflag[t], 0); } while (f == 0);
        atomicAdd(&spre, f - 1);
    }
    __syncthreads();
    int exc = spre + sm[t] - v;
    if (i < n) { off[i] = exc; cur[i] = exc; }
    if (b == gridDim.x - 1 && t == 1023) off[n] = spre + sm[1023];
}

__global__ void k_escatter(const int* __restrict__ s, const int* __restrict__ d,
                           const unsigned char* __restrict__ val, int* __restrict__ cur,
                           int* __restrict__ csr, int E) {
    int e = blockIdx.x * blockDim.x + threadIdx.x;
    if (e >= E) return;
    if (val && !val[e]) return;
    int p = atomicAdd(&cur[d[e]], 1);
    csr[p] = s[e];
}

// Fused GAT aggregation + topk score: warp per dst node, no-shift softmax,
// predicated 4-batches for MLP=4 through the tail.
__global__ void k_gather(const float* __restrict__ h1, const int* __restrict__ off,
                         const int* __restrict__ csr,
                         const float* __restrict__ as_, const float* __restrict__ ad_,
                         const float* __restrict__ bias, const float* __restrict__ pw,
                         float* __restrict__ out, float* __restrict__ sc, int n) {
    int wp = (blockIdx.x * blockDim.x + threadIdx.x) >> 5;
    if (wp >= n) return;
    int lane = threadIdx.x & 31;
    int head = lane >> 3;
    int d = wp;
    float adh = ad_[d * 4 + head];
    float w0s = expf(lrelu(as_[d * 4 + head] + adh));   // self loop
    float den = w0s;
    float acc[8];
    {
        const float4* p = (const float4*)(h1 + (size_t)d * FHC + lane * 8);
        float4 x0 = p[0], x1 = p[1];
        acc[0] = w0s * x0.x; acc[1] = w0s * x0.y; acc[2] = w0s * x0.z; acc[3] = w0s * x0.w;
        acc[4] = w0s * x1.x; acc[5] = w0s * x1.y; acc[6] = w0s * x1.z; acc[7] = w0s * x1.w;
    }
    int e0 = off[d], e1 = off[d + 1];
    for (int e = e0; e < e1; e += 4) {
        int sv[4];
        float wgt[4];
        float4 f0[4], f1[4];
#pragma unroll
        for (int i = 0; i < 4; i++) {
            bool ok = (e + i < e1);
            sv[i] = ok ? csr[e + i] : d;
            wgt[i] = ok ? 1.f : 0.f;
        }
#pragma unroll
        for (int i = 0; i < 4; i++) {
            wgt[i] *= expf(lrelu(as_[sv[i] * 4 + head] + adh));
            const float4* p = (const float4*)(h1 + (size_t)sv[i] * FHC + lane * 8);
            f0[i] = p[0]; f1[i] = p[1];
        }
#pragma unroll
        for (int i = 0; i < 4; i++) {
            den += wgt[i];
            acc[0] = fmaf(wgt[i], f0[i].x, acc[0]);
            acc[1] = fmaf(wgt[i], f0[i].y, acc[1]);
            acc[2] = fmaf(wgt[i], f0[i].z, acc[2]);
            acc[3] = fmaf(wgt[i], f0[i].w, acc[3]);
            acc[4] = fmaf(wgt[i], f1[i].x, acc[4]);
            acc[5] = fmaf(wgt[i], f1[i].y, acc[5]);
            acc[6] = fmaf(wgt[i], f1[i].z, acc[6]);
            acc[7] = fmaf(wgt[i], f1[i].w, acc[7]);
        }
    }
    float inv = 1.f / (den + 1e-16f);
    int cb = lane * 8;
    float4 o0, o1;
    float v;
    v = acc[0] * inv + bias[cb + 0]; o0.x = v > 0.f ? v : expm1f(v);
    v = acc[1] * inv + bias[cb + 1]; o0.y = v > 0.f ? v : expm1f(v);
    v = acc[2] * inv + bias[cb + 2]; o0.z = v > 0.f ? v : expm1f(v);
    v = acc[3] * inv + bias[cb + 3]; o0.w = v > 0.f ? v : expm1f(v);
    v = acc[4] * inv + bias[cb + 4]; o1.x = v > 0.f ? v : expm1f(v);
    v = acc[5] * inv + bias[cb + 5]; o1.y = v > 0.f ? v : expm1f(v);
    v = acc[6] * inv + bias[cb + 6]; o1.z = v > 0.f ? v : expm1f(v);
    v = acc[7] * inv + bias[cb + 7]; o1.w = v > 0.f ? v : expm1f(v);
    float4* po = (float4*)(out + (size_t)d * FHC + cb);
    __stcs(po, o0);
    __stcs(po + 1, o1);
    const float4* pwp = (const float4*)(pw + cb);
    float4 w0 = pwp[0], w1 = pwp[1];
    float sp = o0.x * w0.x + o0.y * w0.y + o0.z * w0.z + o0.w * w0.w +
               o1.x * w1.x + o1.y * w1.y + o1.z * w1.z + o1.w * w1.w;
    float n2 = w0.x * w0.x + w0.y * w0.y + w0.z * w0.z + w0.w * w0.w +
               w1.x * w1.x + w1.y * w1.y + w1.z * w1.z + w1.w * w1.w;
#pragma unroll
    for (int o = 16; o; o >>= 1) {
        sp += __shfl_xor_sync(0xffffffffu, sp, o);
        n2 += __shfl_xor_sync(0xffffffffu, n2, o);
    }
    if (!lane) sc[d] = sp / (sqrtf(n2) + 1e-16f);
}

// exact top-k per graph via 4-pass radix select on sortable uint keys.
__global__ void __launch_bounds__(1024) k_topk(const float* __restrict__ score, int n_in,
                                               int k, int* __restrict__ perm,
                                               float* __restrict__ tanhv,
                                               int* __restrict__ newid) {
    __shared__ unsigned su[2048];
    __shared__ int hist[256];
    __shared__ int sscan[1024];
    __shared__ unsigned s_thr;
    __shared__ int s_kk;
    __shared__ int s_totgt;
    int b = blockIdx.x, t = threadIdx.x;
    const float* s = score + b * n_in;
    int per = n_in >> 10;  // 1 or 2
    for (int i = t; i < n_in; i += 1024) {
        unsigned u = __float_as_uint(s[i]);
        su[i] = (u & 0x80000000u) ? ~u : (u | 0x80000000u);
    }
    __syncthreads();
    unsigned prefix = 0u;
    int kk = k;
    for (int pass = 0; pass < 4; pass++) {
        int shift = 24 - 8 * pass;
        unsigned pmask = pass ? (0xFFFFFFFFu << (shift + 8)) : 0u;
        if (t < 256) hist[t] = 0;
        __syncthreads();
        for (int i = t; i < n_in; i += 1024) {
            unsigned u = su[i];
            if ((u & pmask) == (prefix & pmask))
                atomicAdd(&hist[(u >> shift) & 0xFFu], 1);
        }
        __syncthreads();
        if (t == 0) {
            int acc = 0, d = 255;
            for (; d > 0; d--) {
                int c = hist[d];
                if (acc + c >= kk) break;
                acc += c;
            }
            s_thr = (prefix & pmask) | ((unsigned)d << shift);
            s_kk = kk - acc;
        }
        __syncthreads();
        prefix = s_thr;
        kk = s_kk;
        __syncthreads();
    }
    unsigned T = prefix;
    int isgt[2] = {0, 0}, iseq[2] = {0, 0};
    int keepc = 0, eqc = 0;
    for (int q = 0; q < 2; q++) {
        if (q < per) {
            unsigned u = su[t * per + q];
            isgt[q] = (u > T);
            iseq[q] = (u == T);
            keepc += isgt[q];
            eqc += iseq[q];
        }
    }
    sscan[t] = (eqc << 16) | keepc;
    __syncthreads();
    for (int o = 1; o < 1024; o <<= 1) {
        int u = (t >= o) ? sscan[t - o] : 0;
        __syncthreads();
        sscan[t] += u;
        __syncthreads();
    }
    int packed_exc = sscan[t] - ((eqc << 16) | keepc);
    int gtpos = packed_exc & 0xFFFF;
    int eqrank = packed_exc >> 16;
    if (t == 1023) s_totgt = sscan[1023] & 0xFFFF;
    __syncthreads();
    int totgt = s_totgt;
    for (int q = 0; q < per; q++) {
        int idx = t * per + q;
        int old = b * n_in + idx;
        bool kept = false;
        int pos = 0;
        if (isgt[q]) {
            kept = true; pos = gtpos; gtpos++;
        } else if (iseq[q]) {
            kept = (eqrank < kk); pos = totgt + eqrank; eqrank++;
        }
        if (kept) {
            int np = b * k + pos;
            perm[np] = old;
            tanhv[np] = tanhf(s[idx]);
            newid[old] = np;
        } else {
            newid[old] = -1;
        }
    }
}

// warp per pooled node: hp = h[perm]*tanh, fused gate = <hp_row, gate_w> + b
__global__ void k_poolfeat(const float* __restrict__ h, const int* __restrict__ pm,
                           const float* __restrict__ th, const float* __restrict__ gw,
                           const float* __restrict__ gb, float* __restrict__ hp,
                           float* __restrict__ gt, int m) {
    int wp = (blockIdx.x * blockDim.x + threadIdx.x) >> 5;
    if (wp >= m) return;
    int lane = threadIdx.x & 31;
    int srcn = pm[wp];
    float tv = th[wp];
    int cb = lane * 8;
    const float4* p = (const float4*)(h + (size_t)srcn * FHC + cb);
    float4 a = p[0], b = p[1];
    a.x *= tv; a.y *= tv; a.z *= tv; a.w *= tv;
    b.x *= tv; b.y *= tv; b.z *= tv; b.w *= tv;
    float4* po = (float4*)(hp + (size_t)wp * FHC + cb);
    po[0] = a; po[1] = b;
    const float4* g4 = (const float4*)(gw + cb);
    float4 w0 = g4[0], w1 = g4[1];
    float s = a.x * w0.x + a.y * w0.y + a.z * w0.z + a.w * w0.w +
              b.x * w1.x + b.y * w1.y + b.z * w1.z + b.w * w1.w;
#pragma unroll
    for (int o = 16; o; o >>= 1) s += __shfl_xor_sync(0xffffffffu, s, o);
    if (!lane) gt[wp] = s + gb[0];
}

// remap edges to pooled ids + count pooled in-degrees (fused)
__global__ void k_remap_deg(const int* __restrict__ si, const int* __restrict__ di,
                            const int* __restrict__ nid, int* __restrict__ so,
                            int* __restrict__ dq, unsigned char* __restrict__ vo,
                            int* __restrict__ deg, int E) {
    int e = blockIdx.x * blockDim.x + threadIdx.x;
    if (e >= E) return;
    int ns = nid[si[e]], nd = nid[di[e]];
    bool v = (ns >= 0) && (nd >= 0);
    so[e] = v ? ns : 0;
    dq[e] = v ? nd : 0;
    vo[e] = v ? 1 : 0;
    if (v) atomicAdd(&deg[nd], 1);
}

// attentional pooling with in-kernel softmax stats: grid (8, NB)
__global__ void k_attpool2(const float* __restrict__ hp, const float* __restrict__ gt,
                           float* __restrict__ out, int npg) {
    __shared__ float red[256];
    int b = blockIdx.y, t = threadIdx.x;
    const float* g = gt + b * npg;
    float mxv = -1e30f;
    for (int i = t; i < npg; i += 256) mxv = fmaxf(mxv, g[i]);
    red[t] = mxv;
    __syncthreads();
    for (int o = 128; o; o >>= 1) { if (t < o) red[t] = fmaxf(red[t], red[t + o]); __syncthreads(); }
    float m = red[0];
    __syncthreads();
    float sum = 0.f;
    for (int i = t; i < npg; i += 256) sum += expf(g[i] - m);
    red[t] = sum;
    __syncthreads();
    for (int o = 128; o; o >>= 1) { if (t < o) red[t] += red[t + o]; __syncthreads(); }
    float inv = 1.f / red[0];
    int chunk = npg >> 3;
    int i0 = blockIdx.x * chunk;
    const float* hb = hp + ((size_t)b * npg + i0) * FHC;
    float a = 0.f;
    for (int i = 0; i < chunk; i++)
        a = fmaf(expf(g[i0 + i] - m), hb[(size_t)i * FHC + t], a);
    atomicAdd(&out[b * FHC + t], a * inv);
}

// ---------------- host side ----------------

extern "C" void kernel_launch(void* const* d_in, const int* in_sizes, int n_in,
                              void* d_out, int out_size) {
    const float* x        = (const float*)d_in[0];
    const void*  ei       = d_in[1];
    const float* lin0_w   = (const float*)d_in[2];
    const float* lin0_b   = (const float*)d_in[3];
    const float* gat0_W   = (const float*)d_in[4];
    const float* gat0_as  = (const float*)d_in[5];
    const float* gat0_ad  = (const float*)d_in[6];
    const float* gat0_b   = (const float*)d_in[7];
    const float* pool0_w  = (const float*)d_in[8];
    const float* gat1_W   = (const float*)d_in[9];
    const float* gat1_as  = (const float*)d_in[10];
    const float* gat1_ad  = (const float*)d_in[11];
    const float* gat1_b   = (const float*)d_in[12];
    const float* pool1_w  = (const float*)d_in[13];
    const float* gate_w   = (const float*)d_in[14];
    const float* gate_b   = (const float*)d_in[15];
    float* out = (float*)d_out;

    float *h0, *h1, *ho, *hp, *hp2, *wsp, *as_, *ad_, *sc, *th, *gt;
    int *s0, *d0, *s1, *d1, *deg, *off, *cur, *csr, *pm, *nid, *bs;
    unsigned char* v1;
    cudaGetSymbolAddress((void**)&h0, g_h0);
    cudaGetSymbolAddress((void**)&h1, g_h1);
    cudaGetSymbolAddress((void**)&ho, g_ho);
    cudaGetSymbolAddress((void**)&hp, g_hp);
    cudaGetSymbolAddress((void**)&hp2, g_hp2);
    cudaGetSymbolAddress((void**)&wsp, g_wsp);
    cudaGetSymbolAddress((void**)&as_, g_as);
    cudaGetSymbolAddress((void**)&ad_, g_ad);
    cudaGetSymbolAddress((void**)&sc, g_sc);
    cudaGetSymbolAddress((void**)&th, g_th);
    cudaGetSymbolAddress((void**)&gt, g_gt);
    cudaGetSymbolAddress((void**)&s0, g_s0);
    cudaGetSymbolAddress((void**)&d0, g_d0);
    cudaGetSymbolAddress((void**)&s1, g_s1);
    cudaGetSymbolAddress((void**)&d1, g_d1);
    cudaGetSymbolAddress((void**)&deg, g_deg);
    cudaGetSymbolAddress((void**)&off, g_off);
    cudaGetSymbolAddress((void**)&cur, g_cur);
    cudaGetSymbolAddress((void**)&csr, g_csr);
    cudaGetSymbolAddress((void**)&pm, g_pm);
    cudaGetSymbolAddress((void**)&nid, g_nid);
    cudaGetSymbolAddress((void**)&bs, g_bs);
    cudaGetSymbolAddress((void**)&v1, g_v1);

    cudaFuncSetAttribute(k_gemm_tc, cudaFuncAttributeMaxDynamicSharedMemorySize,
                         SMEM_GEMM);

    static cudaStream_t s2 = nullptr;
    static cudaEvent_t evF0, evS0, evT0, evP0, evS1, evA0;
    if (!s2) {
        cudaStreamCreateWithFlags(&s2, cudaStreamNonBlocking);
        cudaEventCreateWithFlags(&evF0, cudaEventDisableTiming);
        cudaEventCreateWithFlags(&evS0, cudaEventDisableTiming);
        cudaEventCreateWithFlags(&evT0, cudaEventDisableTiming);
        cudaEventCreateWithFlags(&evP0, cudaEventDisableTiming);
        cudaEventCreateWithFlags(&evS1, cudaEventDisableTiming);
        cudaEventCreateWithFlags(&evA0, cudaEventDisableTiming);
    }

    const int EB = divup(E0, 256);

    // fork side stream immediately (CSR0 build depends only on inputs)
    cudaEventRecord(evF0, 0);
    cudaStreamWaitEvent(s2, evF0, 0);
    cudaMemsetAsync(deg, 0, (size_t)N0 * sizeof(int), s2);
    cudaMemsetAsync(bs, 0, 64 * sizeof(int), s2);
    k_edges_deg<<<EB, 256, 0, s2>>>(ei, s0, d0, deg, E0);
    k_scanF<<<N0 / 1024, 1024, 0, s2>>>(deg, off, cur, bs, N0);
    k_escatter<<<EB, 256, 0, s2>>>(s0, d0, nullptr, cur, csr, E0);
    cudaEventRecord(evS0, s2);

    // ---- main: zero out, presplit weights, then the two big GEMMs ----
    cudaMemsetAsync(out, 0, (size_t)NB * FHC * sizeof(float), 0);
    k_wsplit<<<divup(163840, 256), 256>>>(lin0_w, gat0_W, gat1_W, wsp);
    k_gemm_tc<<<dim3(1, N0 / 128), 256, SMEM_GEMM>>>(
        x, wsp, wsp + 65536, lin0_b, h0, N0, 128, 256, 1, 129,
        x + 128, lin0_w + 128 * 256, nullptr, nullptr, nullptr, nullptr);
    k_gemm_tc<<<dim3(1, N0 / 128), 256, SMEM_GEMM>>>(
        h0, wsp + 131072, wsp + 196608, nullptr, h1, N0, 256, 256, 0, 256,
        nullptr, nullptr, gat0_as, gat0_ad, as_, ad_);

    // join: gather0 needs CSR + h1/as_/ad_
    cudaStreamWaitEvent(0, evS0, 0);
    k_gather<<<divup(N0, 8), 256>>>(h1, off, csr, as_, ad_, gat0_b, pool0_w, ho, sc, N0);

    // TopK pool 0 (radix select)
    k_topk<<<NB, 1024>>>(sc, 2048, 1024, pm, th, nid);
    cudaEventRecord(evT0, 0);
    k_poolfeat<<<divup((N0 / 2) * 32, 256), 256>>>(ho, pm, th, gate_w, gate_b, hp, gt, N0 / 2);
    cudaEventRecord(evP0, 0);

    // side: CSR build for GAT1 (needs nid), then attpool0 (needs hp/gt)
    cudaStreamWaitEvent(s2, evT0, 0);
    cudaMemsetAsync(deg, 0, (size_t)(N0 / 2) * sizeof(int), s2);
    cudaMemsetAsync(bs, 0, 64 * sizeof(int), s2);
    k_remap_deg<<<EB, 256, 0, s2>>>(s0, d0, nid, s1, d1, v1, deg, E0);
    k_scanF<<<(N0 / 2) / 1024, 1024, 0, s2>>>(deg, off, cur, bs, N0 / 2);
    k_escatter<<<EB, 256, 0, s2>>>(s1, d1, v1, cur, csr, E0);
    cudaEventRecord(evS1, s2);
    cudaStreamWaitEvent(s2, evP0, 0);
    k_attpool2<<<dim3(8, NB), 256, 0, s2>>>(hp, gt, out, 1024);
    cudaEventRecord(evA0, s2);

    // ---- main: GAT1 GEMM (overlaps side CSR + attpool0) ----
    k_gemm_tc<<<dim3(1, (N0 / 2) / 128), 256, SMEM_GEMM>>>(
        hp, wsp + 262144, wsp + 327680, nullptr, h1, N0 / 2, 256, 256, 0, 256,
        nullptr, nullptr, gat1_as, gat1_ad, as_, ad_);
    cudaStreamWaitEvent(0, evS1, 0);
    k_gather<<<divup(N0 / 2, 8), 256>>>(h1, off, csr, as_, ad_, gat1_b, pool1_w, ho, sc, N0 / 2);

    // TopK pool 1
    k_topk<<<NB, 1024>>>(sc, 1024, 512, pm, th, nid);
    k_poolfeat<<<divup((N0 / 4) * 32, 256), 256>>>(ho, pm, th, gate_w, gate_b, hp2, gt, N0 / 4);

    // AttPool 1 -> out (+=); join attpool0 branch before final adds
    cudaStreamWaitEvent(0, evA0, 0);
    k_attpool2<<<dim3(8, NB), 256>>>(hp2, gt, out, 512);
}

// round 15
// speedup vs baseline: 3.3039x; 1.0623x over previous
#include <cuda_runtime.h>
#include <math.h>
#include <stdint.h>

#define N0  65536     // total nodes
#define E0  524288    // total edges
#define NB  32        // graphs
#define FHC 256       // feature width (H*C)

// ---------------- static device scratch ----------------
__device__ float g_h0[(size_t)N0 * FHC];
__device__ float g_h1[(size_t)N0 * FHC];
__device__ float g_ho[(size_t)N0 * FHC];
__device__ float g_hp[(size_t)(N0 / 2) * FHC];
__device__ float g_hp2[(size_t)(N0 / 4) * FHC];
__device__ float g_wsp[6 * 65536];   // presplit weights: lin0 hi/lo, gat0 hi/lo, gat1 hi/lo
__device__ float g_as[N0 * 4], g_ad[N0 * 4];
__device__ float g_sc[N0];
__device__ float g_th[N0 / 2];
__device__ float g_gt[N0 / 2];
__device__ int g_s0[E0], g_d0[E0], g_s1[E0], g_d1[E0];
__device__ unsigned char g_v1[E0];
__device__ int g_deg[N0], g_off[N0 + 1], g_cur[N0], g_csr[E0];
__device__ int g_bs[64];             // lookback flags (value = chunk total + 1)
__device__ int g_pm[N0 / 2], g_nid[N0];

static inline int divup(int a, int b) { return (a + b - 1) / b; }

__device__ __forceinline__ float lrelu(float z) { return z > 0.f ? z : 0.2f * z; }

// ---------------- tf32 helpers ----------------
__device__ __forceinline__ void tf32split(float x, uint32_t& hi, uint32_t& lo) {
    asm("cvt.rna.tf32.f32 %0, %1;" : "=r"(hi) : "f"(x));
    float r = x - __uint_as_float(hi);
    asm("cvt.rna.tf32.f32 %0, %1;" : "=r"(lo) : "f"(r));
}

#define MMA_TF32(d, a, b0, b1)                                                   \
    asm volatile(                                                                \
        "mma.sync.aligned.m16n8k8.row.col.f32.tf32.tf32.f32 "                    \
        "{%0,%1,%2,%3},{%4,%5,%6,%7},{%8,%9},{%0,%1,%2,%3};"                     \
        : "+f"(d[0]), "+f"(d[1]), "+f"(d[2]), "+f"(d[3])                         \
        : "r"(a[0]), "r"(a[1]), "r"(a[2]), "r"(a[3]), "r"(b0), "r"(b1))

__device__ __forceinline__ void cpa16(uint32_t dst, const void* src) {
    asm volatile("cp.async.cg.shared.global [%0], [%1], 16;" :: "r"(dst), "l"(src));
}
__device__ __forceinline__ void cpa4(uint32_t dst, const void* src) {
    asm volatile("cp.async.ca.shared.global [%0], [%1], 4;" :: "r"(dst), "l"(src));
}

// ---------------- kernels ----------------

// split all three weight matrices into tf32 hi/lo (one pass)
__global__ void k_wsplit(const float* __restrict__ w0, const float* __restrict__ w1,
                         const float* __restrict__ w2, float* __restrict__ wsp) {
    int i = blockIdx.x * blockDim.x + threadIdx.x;
    const float* src;
    float *hi, *lo;
    int li;
    if (i < 32768)        { src = w0; li = i;          hi = wsp;            lo = wsp + 65536; }
    else if (i < 98304)   { src = w1; li = i - 32768;  hi = wsp + 131072;   lo = wsp + 196608; }
    else if (i < 163840)  { src = w2; li = i - 98304;  hi = wsp + 262144;   lo = wsp + 327680; }
    else return;
    uint32_t h, l;
    tf32split(src[li], h, l);
    hi[li] = __uint_as_float(h);
    lo[li] = __uint_as_float(l);
}

// decode edges + count in-degrees; int64-vs-int32 detection fused per block
__global__ void k_edges_deg(const void* __restrict__ ei, int* __restrict__ s,
                            int* __restrict__ d, int* __restrict__ deg, int E) {
    __shared__ int s64;
    if (threadIdx.x == 0) {
        const int* w = (const int*)ei;
        int nz = 0;
        for (int i = 1; i < 128; i += 2) nz |= (w[i] != 0);
        s64 = nz ? 0 : 1;
    }
    __syncthreads();
    int i = blockIdx.x * blockDim.x + threadIdx.x;
    if (i >= E) return;
    int sv, dv;
    if (s64) {
        const long long* p = (const long long*)ei;
        sv = (int)p[i];
        dv = (int)p[E + i];
    } else {
        const int* p = (const int*)ei;
        sv = p[i];
        dv = p[E + i];
    }
    s[i] = sv; d[i] = dv;
    atomicAdd(&deg[dv], 1);
}

// Tensor-core GEMM, 3xTF32. B (weights) presplit in global hi/lo; A split
// in registers. Double-buffered cp.async. Block tile 128x128, BK=32,
// 256 threads (8 warps, warp tile 32x64), 2 CTAs/SM; grid (N/128, M/128);
// K % 32 == 0; N == 256.
#define AP 36
#define BP 136
#define ABUF (128 * AP)
#define BBUF (32 * BP)
#define SBUF (ABUF + 2 * BBUF)
#define SMEM_GEMM (2 * SBUF * 4)
__global__ void __launch_bounds__(256, 2)
k_gemm_tc(const float* __restrict__ A, const float* __restrict__ Bh,
          const float* __restrict__ Bl,
          const float* __restrict__ bias, float* __restrict__ Cm,
          int M, int K, int N, int act, int Kld,
          const float* __restrict__ a1col, const float* __restrict__ b1row,
          const float* __restrict__ aS, const float* __restrict__ aD,
          float* __restrict__ as_, float* __restrict__ ad_) {
    extern __shared__ float smg[];
    int t = threadIdx.x;
    int lane = t & 31, w = t >> 5;
    int g = lane >> 2, tig = lane & 3;
    int wm = w & 3, wn = w >> 2;         // 4 warps M (32 rows) x 2 warps N (64 cols)
    int row0 = blockIdx.y * 128;
    int col0 = blockIdx.x * 128;
    int nk = K >> 5;
    bool al16 = (Kld & 3) == 0;

    float acc[2][8][4];
#pragma unroll
    for (int i = 0; i < 2; i++)
#pragma unroll
        for (int j = 0; j < 8; j++)
#pragma unroll
            for (int q = 0; q < 4; q++) acc[i][j][q] = 0.f;

    auto copy_tile = [&](int ti, int bf) {
        float* As  = smg + bf * SBUF;
        float* Bsh = As + ABUF;
        float* Bsl = Bsh + BBUF;
#pragma unroll
        for (int it = 0; it < 4; it++) {
            int lin = t + 256 * it;
            int r = lin >> 3, c4 = (lin & 7) * 4;
            const float* src = &A[(size_t)(row0 + r) * Kld + ti * 32 + c4];
            uint32_t dst = (uint32_t)__cvta_generic_to_shared(&As[r * AP + c4]);
            if (al16) {
                cpa16(dst, src);
            } else {
#pragma unroll
                for (int j = 0; j < 4; j++) cpa4(dst + j * 4, src + j);
            }
        }
#pragma unroll
        for (int it = 0; it < 4; it++) {
            int lin = t + 256 * it;
            int kk = lin >> 5, c4 = (lin & 31) * 4;
            size_t gsrc = (size_t)(ti * 32 + kk) * N + col0 + c4;
            cpa16((uint32_t)__cvta_generic_to_shared(&Bsh[kk * BP + c4]), &Bh[gsrc]);
            cpa16((uint32_t)__cvta_generic_to_shared(&Bsl[kk * BP + c4]), &Bl[gsrc]);
        }
    };

    copy_tile(0, 0);
    asm volatile("cp.async.commit_group;");

    for (int ti = 0; ti < nk; ti++) {
        if (ti + 1 < nk) {
            copy_tile(ti + 1, (ti + 1) & 1);
            asm volatile("cp.async.commit_group;");
            asm volatile("cp.async.wait_group 1;");
        } else {
            asm volatile("cp.async.wait_group 0;");
        }
        __syncthreads();
        const float* As  = smg + (ti & 1) * SBUF;
        const float* Bsh = As + ABUF;
        const float* Bsl = Bsh + BBUF;
#pragma unroll
        for (int ks = 0; ks < 4; ks++) {
            int k8 = ks * 8;
            uint32_t ah[2][4], al[2][4];
#pragma unroll
            for (int mt = 0; mt < 2; mt++) {
                int bm = wm * 32 + mt * 16 + g;
                tf32split(As[bm * AP + k8 + tig],           ah[mt][0], al[mt][0]);
                tf32split(As[(bm + 8) * AP + k8 + tig],     ah[mt][1], al[mt][1]);
                tf32split(As[bm * AP + k8 + tig + 4],       ah[mt][2], al[mt][2]);
                tf32split(As[(bm + 8) * AP + k8 + tig + 4], ah[mt][3], al[mt][3]);
            }
#pragma unroll
            for (int nt = 0; nt < 8; nt++) {
                int bn = wn * 64 + nt * 8 + g;
                uint32_t b0h = __float_as_uint(Bsh[(k8 + tig) * BP + bn]);
                uint32_t b1h = __float_as_uint(Bsh[(k8 + tig + 4) * BP + bn]);
                uint32_t b0l = __float_as_uint(Bsl[(k8 + tig) * BP + bn]);
                uint32_t b1l = __float_as_uint(Bsl[(k8 + tig + 4) * BP + bn]);
#pragma unroll
                for (int mt = 0; mt < 2; mt++) {
                    MMA_TF32(acc[mt][nt], ah[mt], b0h, b1h);
                    MMA_TF32(acc[mt][nt], ah[mt], b0l, b1l);
                    MMA_TF32(acc[mt][nt], al[mt], b0h, b1h);
                }
            }
        }
        __syncthreads();
    }

#pragma unroll
    for (int mt = 0; mt < 2; mt++) {
        int r = row0 + wm * 32 + mt * 16 + g;
        float ar0 = a1col ? a1col[(size_t)r * Kld] : 0.f;
        float ar8 = a1col ? a1col[(size_t)(r + 8) * Kld] : 0.f;
#pragma unroll
        for (int nt = 0; nt < 8; nt++) {
            int cc = col0 + wn * 64 + nt * 8 + tig * 2;
            float bb0 = a1col ? b1row[cc] : 0.f, bb1 = a1col ? b1row[cc + 1] : 0.f;
            float b0 = bias ? bias[cc] : 0.f, b1 = bias ? bias[cc + 1] : 0.f;
            float v0 = acc[mt][nt][0] + ar0 * bb0 + b0;
            float v1 = acc[mt][nt][1] + ar0 * bb1 + b1;
            float v2 = acc[mt][nt][2] + ar8 * bb0 + b0;
            float v3 = acc[mt][nt][3] + ar8 * bb1 + b1;
            if (act) {
                v0 = fmaxf(v0, 0.f); v1 = fmaxf(v1, 0.f);
                v2 = fmaxf(v2, 0.f); v3 = fmaxf(v3, 0.f);
            }
            float2 p0 = {v0, v1}, p1 = {v2, v3};
            *(float2*)&Cm[(size_t)r * N + cc] = p0;
            *(float2*)&Cm[(size_t)(r + 8) * N + cc] = p1;
        }
    }

    // fused attention epilogue: warp wn's 64 cols = head (blockIdx.x*2 + wn)
    if (aS) {
        int head = blockIdx.x * 2 + wn;
        const float* ws = aS + head * 64;
        const float* wd = aD + head * 64;
#pragma unroll
        for (int mt = 0; mt < 2; mt++) {
            float s0 = 0.f, d0 = 0.f, s1 = 0.f, d1 = 0.f;
#pragma unroll
            for (int nt = 0; nt < 8; nt++) {
                int c = nt * 8 + tig * 2;
                float w0 = ws[c], w1 = ws[c + 1];
                float u0 = wd[c], u1 = wd[c + 1];
                s0 = fmaf(acc[mt][nt][0], w0, fmaf(acc[mt][nt][1], w1, s0));
                d0 = fmaf(acc[mt][nt][0], u0, fmaf(acc[mt][nt][1], u1, d0));
                s1 = fmaf(acc[mt][nt][2], w0, fmaf(acc[mt][nt][3], w1, s1));
                d1 = fmaf(acc[mt][nt][2], u0, fmaf(acc[mt][nt][3], u1, d1));
            }
#pragma unroll
            for (int o = 1; o <= 2; o <<= 1) {
                s0 += __shfl_xor_sync(0xffffffffu, s0, o);
                d0 += __shfl_xor_sync(0xffffffffu, d0, o);
                s1 += __shfl_xor_sync(0xffffffffu, s1, o);
                d1 += __shfl_xor_sync(0xffffffffu, d1, o);
            }
            if (tig == 0) {
                int r = row0 + wm * 32 + mt * 16 + g;
                as_[r * 4 + head] = s0; ad_[r * 4 + head] = d0;
                as_[(r + 8) * 4 + head] = s1; ad_[(r + 8) * 4 + head] = d1;
            }
        }
    }
}

// single-pass exclusive scan with decoupled lookback; nb = gridDim.x <= 64.
__global__ void __launch_bounds__(1024) k_scanF(const int* __restrict__ in,
                                                int* __restrict__ off,
                                                int* __restrict__ cur,
                                                int* __restrict__ bflag, int n) {
    __shared__ int sm[1024];
    __shared__ int spre;
    int t = threadIdx.x, b = blockIdx.x;
    int i = b * 1024 + t;
    int v = (i < n) ? in[i] : 0;
    sm[t] = v;
    __syncthreads();
    for (int o = 1; o < 1024; o <<= 1) {
        int u = (t >= o) ? sm[t - o] : 0;
        __syncthreads();
        sm[t] += u;
        __syncthreads();
    }
    if (t == 0) { spre = 0; atomicExch(&bflag[b], sm[1023] + 1); }
    __syncthreads();
    if (t < b) {
        int f;
        do { f = atomicAdd(&bflag[t], 0); } while (f == 0);
        atomicAdd(&spre, f - 1);
    }
    __syncthreads();
    int exc = spre + sm[t] - v;
    if (i < n) { off[i] = exc; cur[i] = exc; }
    if (b == gridDim.x - 1 && t == 1023) off[n] = spre + sm[1023];
}

__global__ void k_escatter(const int* __restrict__ s, const int* __restrict__ d,
                           const unsigned char* __restrict__ val, int* __restrict__ cur,
                           int* __restrict__ csr, int E) {
    int e = blockIdx.x * blockDim.x + threadIdx.x;
    if (e >= E) return;
    if (val && !val[e]) return;
    int p = atomicAdd(&cur[d[e]], 1);
    csr[p] = s[e];
}

// Fused GAT aggregation + topk score: warp per dst node, no-shift softmax,
// predicated 4-batches for MLP=4 through the tail.
__global__ void k_gather(const float* __restrict__ h1, const int* __restrict__ off,
                         const int* __restrict__ csr,
                         const float* __restrict__ as_, const float* __restrict__ ad_,
                         const float* __restrict__ bias, const float* __restrict__ pw,
                         float* __restrict__ out, float* __restrict__ sc, int n) {
    int wp = (blockIdx.x * blockDim.x + threadIdx.x) >> 5;
    if (wp >= n) return;
    int lane = threadIdx.x & 31;
    int head = lane >> 3;
    int d = wp;
    float adh = ad_[d * 4 + head];
    float w0s = expf(lrelu(as_[d * 4 + head] + adh));   // self loop
    float den = w0s;
    float acc[8];
    {
        const float4* p = (const float4*)(h1 + (size_t)d * FHC + lane * 8);
        float4 x0 = p[0], x1 = p[1];
        acc[0] = w0s * x0.x; acc[1] = w0s * x0.y; acc[2] = w0s * x0.z; acc[3] = w0s * x0.w;
        acc[4] = w0s * x1.x; acc[5] = w0s * x1.y; acc[6] = w0s * x1.z; acc[7] = w0s * x1.w;
    }
    int e0 = off[d], e1 = off[d + 1];
    for (int e = e0; e < e1; e += 4) {
        int sv[4];
        float wgt[4];
        float4 f0[4], f1[4];
#pragma unroll
        for (int i = 0; i < 4; i++) {
            bool ok = (e + i < e1);
            sv[i] = ok ? csr[e + i] : d;
            wgt[i] = ok ? 1.f : 0.f;
        }
#pragma unroll
        for (int i = 0; i < 4; i++) {
            wgt[i] *= expf(lrelu(as_[sv[i] * 4 + head] + adh));
            const float4* p = (const float4*)(h1 + (size_t)sv[i] * FHC + lane * 8);
            f0[i] = p[0]; f1[i] = p[1];
        }
#pragma unroll
        for (int i = 0; i < 4; i++) {
            den += wgt[i];
            acc[0] = fmaf(wgt[i], f0[i].x, acc[0]);
            acc[1] = fmaf(wgt[i], f0[i].y, acc[1]);
            acc[2] = fmaf(wgt[i], f0[i].z, acc[2]);
            acc[3] = fmaf(wgt[i], f0[i].w, acc[3]);
            acc[4] = fmaf(wgt[i], f1[i].x, acc[4]);
            acc[5] = fmaf(wgt[i], f1[i].y, acc[5]);
            acc[6] = fmaf(wgt[i], f1[i].z, acc[6]);
            acc[7] = fmaf(wgt[i], f1[i].w, acc[7]);
        }
    }
    float inv = 1.f / (den + 1e-16f);
    int cb = lane * 8;
    float4 o0, o1;
    float v;
    v = acc[0] * inv + bias[cb + 0]; o0.x = v > 0.f ? v : expm1f(v);
    v = acc[1] * inv + bias[cb + 1]; o0.y = v > 0.f ? v : expm1f(v);
    v = acc[2] * inv + bias[cb + 2]; o0.z = v > 0.f ? v : expm1f(v);
    v = acc[3] * inv + bias[cb + 3]; o0.w = v > 0.f ? v : expm1f(v);
    v = acc[4] * inv + bias[cb + 4]; o1.x = v > 0.f ? v : expm1f(v);
    v = acc[5] * inv + bias[cb + 5]; o1.y = v > 0.f ? v : expm1f(v);
    v = acc[6] * inv + bias[cb + 6]; o1.z = v > 0.f ? v : expm1f(v);
    v = acc[7] * inv + bias[cb + 7]; o1.w = v > 0.f ? v : expm1f(v);
    float4* po = (float4*)(out + (size_t)d * FHC + cb);
    __stcs(po, o0);
    __stcs(po + 1, o1);
    const float4* pwp = (const float4*)(pw + cb);
    float4 w0 = pwp[0], w1 = pwp[1];
    float sp = o0.x * w0.x + o0.y * w0.y + o0.z * w0.z + o0.w * w0.w +
               o1.x * w1.x + o1.y * w1.y + o1.z * w1.z + o1.w * w1.w;
    float n2 = w0.x * w0.x + w0.y * w0.y + w0.z * w0.z + w0.w * w0.w +
               w1.x * w1.x + w1.y * w1.y + w1.z * w1.z + w1.w * w1.w;
#pragma unroll
    for (int o = 16; o; o >>= 1) {
        sp += __shfl_xor_sync(0xffffffffu, sp, o);
        n2 += __shfl_xor_sync(0xffffffffu, n2, o);
    }
    if (!lane) sc[d] = sp / (sqrtf(n2) + 1e-16f);
}

// exact top-k per graph via 4-pass radix select on sortable uint keys.
__global__ void __launch_bounds__(1024) k_topk(const float* __restrict__ score, int n_in,
                                               int k, int* __restrict__ perm,
                                               float* __restrict__ tanhv,
                                               int* __restrict__ newid) {
    __shared__ unsigned su[2048];
    __shared__ int hist[256];
    __shared__ int sscan[1024];
    __shared__ unsigned s_thr;
    __shared__ int s_kk;
    __shared__ int s_totgt;
    int b = blockIdx.x, t = threadIdx.x;
    const float* s = score + b * n_in;
    int per = n_in >> 10;  // 1 or 2
    for (int i = t; i < n_in; i += 1024) {
        unsigned u = __float_as_uint(s[i]);
        su[i] = (u & 0x80000000u) ? ~u : (u | 0x80000000u);
    }
    __syncthreads();
    unsigned prefix = 0u;
    int kk = k;
    for (int pass = 0; pass < 4; pass++) {
        int shift = 24 - 8 * pass;
        unsigned pmask = pass ? (0xFFFFFFFFu << (shift + 8)) : 0u;
        if (t < 256) hist[t] = 0;
        __syncthreads();
        for (int i = t; i < n_in; i += 1024) {
            unsigned u = su[i];
            if ((u & pmask) == (prefix & pmask))
                atomicAdd(&hist[(u >> shift) & 0xFFu], 1);
        }
        __syncthreads();
        if (t == 0) {
            int acc = 0, d = 255;
            for (; d > 0; d--) {
                int c = hist[d];
                if (acc + c >= kk) break;
                acc += c;
            }
            s_thr = (prefix & pmask) | ((unsigned)d << shift);
            s_kk = kk - acc;
        }
        __syncthreads();
        prefix = s_thr;
        kk = s_kk;
        __syncthreads();
    }
    unsigned T = prefix;
    int isgt[2] = {0, 0}, iseq[2] = {0, 0};
    int keepc = 0, eqc = 0;
    for (int q = 0; q < 2; q++) {
        if (q < per) {
            unsigned u = su[t * per + q];
            isgt[q] = (u > T);
            iseq[q] = (u == T);
            keepc += isgt[q];
            eqc += iseq[q];
        }
    }
    sscan[t] = (eqc << 16) | keepc;
    __syncthreads();
    for (int o = 1; o < 1024; o <<= 1) {
        int u = (t >= o) ? sscan[t - o] : 0;
        __syncthreads();
        sscan[t] += u;
        __syncthreads();
    }
    int packed_exc = sscan[t] - ((eqc << 16) | keepc);
    int gtpos = packed_exc & 0xFFFF;
    int eqrank = packed_exc >> 16;
    if (t == 1023) s_totgt = sscan[1023] & 0xFFFF;
    __syncthreads();
    int totgt = s_totgt;
    for (int q = 0; q < per; q++) {
        int idx = t * per + q;
        int old = b * n_in + idx;
        bool kept = false;
        int pos = 0;
        if (isgt[q]) {
            kept = true; pos = gtpos; gtpos++;
        } else if (iseq[q]) {
            kept = (eqrank < kk); pos = totgt + eqrank; eqrank++;
        }
        if (kept) {
            int np = b * k + pos;
            perm[np] = old;
            tanhv[np] = tanhf(s[idx]);
            newid[old] = np;
        } else {
            newid[old] = -1;
        }
    }
}

// warp per pooled node: hp = h[perm]*tanh, fused gate = <hp_row, gate_w> + b
__global__ void k_poolfeat(const float* __restrict__ h, const int* __restrict__ pm,
                           const float* __restrict__ th, const float* __restrict__ gw,
                           const float* __restrict__ gb, float* __restrict__ hp,
                           float* __restrict__ gt, int m) {
    int wp = (blockIdx.x * blockDim.x + threadIdx.x) >> 5;
    if (wp >= m) return;
    int lane = threadIdx.x & 31;
    int srcn = pm[wp];
    float tv = th[wp];
    int cb = lane * 8;
    const float4* p = (const float4*)(h + (size_t)srcn * FHC + cb);
    float4 a = p[0], b = p[1];
    a.x *= tv; a.y *= tv; a.z *= tv; a.w *= tv;
    b.x *= tv; b.y *= tv; b.z *= tv; b.w *= tv;
    float4* po = (float4*)(hp + (size_t)wp * FHC + cb);
    po[0] = a; po[1] = b;
    const float4* g4 = (const float4*)(gw + cb);
    float4 w0 = g4[0], w1 = g4[1];
    float s = a.x * w0.x + a.y * w0.y + a.z * w0.z + a.w * w0.w +
              b.x * w1.x + b.y * w1.y + b.z * w1.z + b.w * w1.w;
#pragma unroll
    for (int o = 16; o; o >>= 1) s += __shfl_xor_sync(0xffffffffu, s, o);
    if (!lane) gt[wp] = s + gb[0];
}

// remap edges to pooled ids + count pooled in-degrees (fused)
__global__ void k_remap_deg(const int* __restrict__ si, const int* __restrict__ di,
                            const int* __restrict__ nid, int* __restrict__ so,
                            int* __restrict__ dq, unsigned char* __restrict__ vo,
                            int* __restrict__ deg, int E) {
    int e = blockIdx.x * blockDim.x + threadIdx.x;
    if (e >= E) return;
    int ns = nid[si[e]], nd = nid[di[e]];
    bool v = (ns >= 0) && (nd >= 0);
    so[e] = v ? ns : 0;
    dq[e] = v ? nd : 0;
    vo[e] = v ? 1 : 0;
    if (v) atomicAdd(&deg[nd], 1);
}

// attentional pooling with in-kernel softmax stats: grid (8, NB)
__global__ void k_attpool2(const float* __restrict__ hp, const float* __restrict__ gt,
                           float* __restrict__ out, int npg) {
    __shared__ float red[256];
    int b = blockIdx.y, t = threadIdx.x;
    const float* g = gt + b * npg;
    float mxv = -1e30f;
    for (int i = t; i < npg; i += 256) mxv = fmaxf(mxv, g[i]);
    red[t] = mxv;
    __syncthreads();
    for (int o = 128; o; o >>= 1) { if (t < o) red[t] = fmaxf(red[t], red[t + o]); __syncthreads(); }
    float m = red[0];
    __syncthreads();
    float sum = 0.f;
    for (int i = t; i < npg; i += 256) sum += expf(g[i] - m);
    red[t] = sum;
    __syncthreads();
    for (int o = 128; o; o >>= 1) { if (t < o) red[t] += red[t + o]; __syncthreads(); }
    float inv = 1.f / red[0];
    int chunk = npg >> 3;
    int i0 = blockIdx.x * chunk;
    const float* hb = hp + ((size_t)b * npg + i0) * FHC;
    float a = 0.f;
    for (int i = 0; i < chunk; i++)
        a = fmaf(expf(g[i0 + i] - m), hb[(size_t)i * FHC + t], a);
    atomicAdd(&out[b * FHC + t], a * inv);
}

// ---------------- host side ----------------

extern "C" void kernel_launch(void* const* d_in, const int* in_sizes, int n_in,
                              void* d_out, int out_size) {
    const float* x        = (const float*)d_in[0];
    const void*  ei       = d_in[1];
    const float* lin0_w   = (const float*)d_in[2];
    const float* lin0_b   = (const float*)d_in[3];
    const float* gat0_W   = (const float*)d_in[4];
    const float* gat0_as  = (const float*)d_in[5];
    const float* gat0_ad  = (const float*)d_in[6];
    const float* gat0_b   = (const float*)d_in[7];
    const float* pool0_w  = (const float*)d_in[8];
    const float* gat1_W   = (const float*)d_in[9];
    const float* gat1_as  = (const float*)d_in[10];
    const float* gat1_ad  = (const float*)d_in[11];
    const float* gat1_b   = (const float*)d_in[12];
    const float* pool1_w  = (const float*)d_in[13];
    const float* gate_w   = (const float*)d_in[14];
    const float* gate_b   = (const float*)d_in[15];
    float* out = (float*)d_out;

    float *h0, *h1, *ho, *hp, *hp2, *wsp, *as_, *ad_, *sc, *th, *gt;
    int *s0, *d0, *s1, *d1, *deg, *off, *cur, *csr, *pm, *nid, *bs;
    unsigned char* v1;
    cudaGetSymbolAddress((void**)&h0, g_h0);
    cudaGetSymbolAddress((void**)&h1, g_h1);
    cudaGetSymbolAddress((void**)&ho, g_ho);
    cudaGetSymbolAddress((void**)&hp, g_hp);
    cudaGetSymbolAddress((void**)&hp2, g_hp2);
    cudaGetSymbolAddress((void**)&wsp, g_wsp);
    cudaGetSymbolAddress((void**)&as_, g_as);
    cudaGetSymbolAddress((void**)&ad_, g_ad);
    cudaGetSymbolAddress((void**)&sc, g_sc);
    cudaGetSymbolAddress((void**)&th, g_th);
    cudaGetSymbolAddress((void**)&gt, g_gt);
    cudaGetSymbolAddress((void**)&s0, g_s0);
    cudaGetSymbolAddress((void**)&d0, g_d0);
    cudaGetSymbolAddress((void**)&s1, g_s1);
    cudaGetSymbolAddress((void**)&d1, g_d1);
    cudaGetSymbolAddress((void**)&deg, g_deg);
    cudaGetSymbolAddress((void**)&off, g_off);
    cudaGetSymbolAddress((void**)&cur, g_cur);
    cudaGetSymbolAddress((void**)&csr, g_csr);
    cudaGetSymbolAddress((void**)&pm, g_pm);
    cudaGetSymbolAddress((void**)&nid, g_nid);
    cudaGetSymbolAddress((void**)&bs, g_bs);
    cudaGetSymbolAddress((void**)&v1, g_v1);

    cudaFuncSetAttribute(k_gemm_tc, cudaFuncAttributeMaxDynamicSharedMemorySize,
                         SMEM_GEMM);

    static cudaStream_t s2 = nullptr;
    static cudaEvent_t evF0, evS0, evT0, evP0, evS1, evA0;
    if (!s2) {
        cudaStreamCreateWithFlags(&s2, cudaStreamNonBlocking);
        cudaEventCreateWithFlags(&evF0, cudaEventDisableTiming);
        cudaEventCreateWithFlags(&evS0, cudaEventDisableTiming);
        cudaEventCreateWithFlags(&evT0, cudaEventDisableTiming);
        cudaEventCreateWithFlags(&evP0, cudaEventDisableTiming);
        cudaEventCreateWithFlags(&evS1, cudaEventDisableTiming);
        cudaEventCreateWithFlags(&evA0, cudaEventDisableTiming);
    }

    const int EB = divup(E0, 256);

    // fork side stream immediately (CSR0 build depends only on inputs)
    cudaEventRecord(evF0, 0);
    cudaStreamWaitEvent(s2, evF0, 0);
    cudaMemsetAsync(deg, 0, (size_t)N0 * sizeof(int), s2);
    cudaMemsetAsync(bs, 0, 64 * sizeof(int), s2);
    k_edges_deg<<<EB, 256, 0, s2>>>(ei, s0, d0, deg, E0);
    k_scanF<<<N0 / 1024, 1024, 0, s2>>>(deg, off, cur, bs, N0);
    k_escatter<<<EB, 256, 0, s2>>>(s0, d0, nullptr, cur, csr, E0);
    cudaEventRecord(evS0, s2);

    // ---- main: zero out, presplit weights, then the two big GEMMs ----
    cudaMemsetAsync(out, 0, (size_t)NB * FHC * sizeof(float), 0);
    k_wsplit<<<divup(163840, 256), 256>>>(lin0_w, gat0_W, gat1_W, wsp);
    k_gemm_tc<<<dim3(2, N0 / 128), 256, SMEM_GEMM>>>(
        x, wsp, wsp + 65536, lin0_b, h0, N0, 128, 256, 1, 129,
        x + 128, lin0_w + 128 * 256, nullptr, nullptr, nullptr, nullptr);
    k_gemm_tc<<<dim3(2, N0 / 128), 256, SMEM_GEMM>>>(
        h0, wsp + 131072, wsp + 196608, nullptr, h1, N0, 256, 256, 0, 256,
        nullptr, nullptr, gat0_as, gat0_ad, as_, ad_);

    // join: gather0 needs CSR + h1/as_/ad_
    cudaStreamWaitEvent(0, evS0, 0);
    k_gather<<<divup(N0, 8), 256>>>(h1, off, csr, as_, ad_, gat0_b, pool0_w, ho, sc, N0);

    // TopK pool 0 (radix select)
    k_topk<<<NB, 1024>>>(sc, 2048, 1024, pm, th, nid);
    cudaEventRecord(evT0, 0);
    k_poolfeat<<<divup((N0 / 2) * 32, 256), 256>>>(ho, pm, th, gate_w, gate_b, hp, gt, N0 / 2);
    cudaEventRecord(evP0, 0);

    // side: CSR build for GAT1 (needs nid), then attpool0 (needs hp/gt)
    cudaStreamWaitEvent(s2, evT0, 0);
    cudaMemsetAsync(deg, 0, (size_t)(N0 / 2) * sizeof(int), s2);
    cudaMemsetAsync(bs, 0, 64 * sizeof(int), s2);
    k_remap_deg<<<EB, 256, 0, s2>>>(s0, d0, nid, s1, d1, v1, deg, E0);
    k_scanF<<<(N0 / 2) / 1024, 1024, 0, s2>>>(deg, off, cur, bs, N0 / 2);
    k_escatter<<<EB, 256, 0, s2>>>(s1, d1, v1, cur, csr, E0);
    cudaEventRecord(evS1, s2);
    cudaStreamWaitEvent(s2, evP0, 0);
    k_attpool2<<<dim3(8, NB), 256, 0, s2>>>(hp, gt, out, 1024);
    cudaEventRecord(evA0, s2);

    // ---- main: GAT1 GEMM (overlaps side CSR + attpool0) ----
    k_gemm_tc<<<dim3(2, (N0 / 2) / 128), 256, SMEM_GEMM>>>(
        hp, wsp + 262144, wsp + 327680, nullptr, h1, N0 / 2, 256, 256, 0, 256,
        nullptr, nullptr, gat1_as, gat1_ad, as_, ad_);
    cudaStreamWaitEvent(0, evS1, 0);
    k_gather<<<divup(N0 / 2, 8), 256>>>(h1, off, csr, as_, ad_, gat1_b, pool1_w, ho, sc, N0 / 2);

    // TopK pool 1
    k_topk<<<NB, 1024>>>(sc, 1024, 512, pm, th, nid);
    k_poolfeat<<<divup((N0 / 4) * 32, 256), 256>>>(ho, pm, th, gate_w, gate_b, hp2, gt, N0 / 4);

    // AttPool 1 -> out (+=); join attpool0 branch before final adds
    cudaStreamWaitEvent(0, evA0, 0);
    k_attpool2<<<dim3(8, NB), 256>>>(hp2, gt, out, 512);
}